// round 2
// baseline (speedup 1.0000x reference)
#include <cuda_runtime.h>
#include <math.h>

#define NN_N   512
#define FB     256
#define DD     64
#define HH     4
#define HD     128
#define HHD    512
#define LAYERS 4
#define KDIM   100
#define NPAIR  (NN_N*NN_N)
#define EPSV   1e-5f

typedef unsigned long long ull;

// ---------------- device scratch (static globals: allocation-free) ----------------
__device__ float g_bias0[NPAIR*DD];   // 64 MB  ping
__device__ float g_bias1[NPAIR*DD];   // 64 MB  pong
__device__ float g_diffs[HH*NPAIR];   // 4 MB   [h][n][m]
__device__ float g_x[NN_N*DD];
__device__ float g_b0[NN_N*DD];
__device__ float g_qkv[NN_N*3*HHD];   // [n][h*384 + {q:0,k:128,v:256} + d]
__device__ float g_vals[NN_N*HHD];

// ---------------- helpers ----------------
__device__ __forceinline__ ull pk2(float lo, float hi){
    ull r; asm("mov.b64 %0, {%1,%2};" : "=l"(r) : "f"(lo), "f"(hi)); return r;
}
__device__ __forceinline__ float2 upk2(ull v){
    float2 r; asm("mov.b64 {%0,%1}, %2;" : "=f"(r.x), "=f"(r.y) : "l"(v)); return r;
}
__device__ __forceinline__ void fma2(ull &d, ull a, ull b){
    asm("fma.rn.f32x2 %0, %1, %2, %3;" : "=l"(d) : "l"(a), "l"(b), "l"(d));
}
__device__ __forceinline__ float mishf(float x){
    // softplus = max(x,0) + log1p(exp(-|x|));  tanh(sp) = 1 - 2/(exp(2sp)+1)
    float sp = fmaxf(x, 0.f) + __logf(1.f + __expf(-fabsf(x)));
    float e  = __expf(2.f * sp);          // inf -> tanh = 1 (correct)
    float t  = 1.f - 2.f / (e + 1.f);
    return x * t;
}

// ---------------- K1: embeddings + LN1 ----------------
__global__ void k_embed(const float* __restrict__ nf, const float* __restrict__ am,
                        const float* __restrict__ eW, const float* __restrict__ eb,
                        const float* __restrict__ bW, const float* __restrict__ bbv,
                        const float* __restrict__ g1, const float* __restrict__ b1){
    int n = blockIdx.x, d = threadIdx.x;  // 64 threads
    float acc = eb[d];
    for (int f = 0; f < FB; f++) acc += nf[n*FB + f] * eW[f*DD + d];
    float b0 = bbv[d];
    for (int k = 0; k < KDIM; k++) b0 += am[n*KDIM + k] * bW[k*DD + d];
    g_b0[n*DD + d] = b0;
    __shared__ float s[DD];
    s[d] = acc; __syncthreads();
    float mu = 0.f;
    #pragma unroll
    for (int k = 0; k < DD; k++) mu += s[k];
    mu *= (1.f/DD);
    float var = 0.f;
    #pragma unroll
    for (int k = 0; k < DD; k++){ float dd = s[k]-mu; var += dd*dd; }
    var *= (1.f/DD);
    g_x[n*DD + d] = (acc - mu) * rsqrtf(var + EPSV) * g1[d] + b1[d];
}

// ---------------- K2: bias[n,m,:] = b0[m] - b0[n] ----------------
__global__ void k_biasinit(){
    long idx = (long)blockIdx.x * blockDim.x + threadIdx.x;   // NPAIR*DD threads
    int d = (int)(idx & 63);
    long pair = idx >> 6;
    int m = (int)(pair & 511);
    int n = (int)(pair >> 9);
    g_bias0[idx] = g_b0[m*DD + d] - g_b0[n*DD + d];
}

// ---------------- K3: qkv = x @ qkv_W + b (8 rows per block) ----------------
__global__ void __launch_bounds__(512,1)
k_qkv(const float* __restrict__ W, const float* __restrict__ b){
    int n0 = blockIdx.x * 8;
    __shared__ float xs[8*DD];
    int t = threadIdx.x;
    xs[t] = g_x[n0*DD + t];
    __syncthreads();
    for (int j = t; j < 3*HHD; j += 512){
        float acc[8];
        float bv = b[j];
        #pragma unroll
        for (int r = 0; r < 8; r++) acc[r] = bv;
        #pragma unroll 8
        for (int d = 0; d < DD; d++){
            float w = W[d*(3*HHD) + j];
            #pragma unroll
            for (int r = 0; r < 8; r++) acc[r] += xs[r*DD + d] * w;
        }
        #pragma unroll
        for (int r = 0; r < 8; r++) g_qkv[(long)(n0+r)*(3*HHD) + j] = acc[r];
    }
}

// ---------------- K4: THE big fused kernel -------------------------------------
// per block: 64 pair-rows.  GEMM1 [64x64]@[64x512] -> mish -> beS(smem) + diffs,
// GEMM2 [64x512]@[512x64] -> mish -> new bias.   f32x2 packed FMA throughout.
#define BE_SMEM (16384 + 131072 + 16384 + 1024)
__global__ void __launch_bounds__(512,1)
k_be(const float* __restrict__ dW, const float* __restrict__ db,
     const float* __restrict__ bW, const float* __restrict__ bb,
     int flip, int writeBias){
    extern __shared__ float sm[];
    float* biasS = sm;                    // [64][64]
    float* beS   = sm + 4096;             // [64][512]
    float* bWs   = sm + 4096 + 32768;     // [64][64] staging for bout_W chunk
    float* sqS   = bWs + 4096;            // [64][4]

    const float* bin  = flip ? g_bias1 : g_bias0;
    float*       bnew = flip ? g_bias0 : g_bias1;

    int t = threadIdx.x;
    long pair0 = (long)blockIdx.x * 64;

    {   // load 64x64 bias tile (coalesced float4)
        const float4* src = (const float4*)(bin + pair0*DD);
        float4* dst = (float4*)biasS;
        dst[t]       = src[t];
        dst[t + 512] = src[t + 512];
    }
    __syncthreads();

    int ty = t >> 6;          // 0..7   -> rows ty*8..ty*8+7
    int tx = t & 63;          // 0..63  -> cols tx*8..tx*8+7
    int r0 = ty * 8;
    int c0 = tx * 8;

    // ---- GEMM1: acc[i][k] packs column pairs (c0+2k, c0+2k+1) ----
    ull acc[8][4];
    #pragma unroll
    for (int i = 0; i < 8; i++)
        #pragma unroll
        for (int k = 0; k < 4; k++) acc[i][k] = 0ull;

    #pragma unroll 4
    for (int d = 0; d < DD; d++){
        const float* wrow = dW + d*HHD + c0;
        ulonglong2 wA = *(const ulonglong2*)wrow;        // cols c0..c0+3 packed
        ulonglong2 wB = *(const ulonglong2*)(wrow + 4);  // cols c0+4..c0+7
        #pragma unroll
        for (int i = 0; i < 8; i++){
            float av = biasS[(r0+i)*DD + d];             // broadcast LDS
            ull a2 = pk2(av, av);
            fma2(acc[i][0], a2, wA.x);
            fma2(acc[i][1], a2, wA.y);
            fma2(acc[i][2], a2, wB.x);
            fma2(acc[i][3], a2, wB.y);
        }
    }

    // ---- epilogue: +bias, mish, store beS, squared-norm partials ----
    int head = tx >> 4;   // cols c0..c0+7 all inside head = (tx*8)/128
    float2 dbv[4];
    #pragma unroll
    for (int k = 0; k < 4; k++) dbv[k] = *(const float2*)(db + c0 + 2*k);

    float ss[8];
    #pragma unroll
    for (int i = 0; i < 8; i++){
        float out[8]; float s = 0.f;
        #pragma unroll
        for (int k = 0; k < 4; k++){
            float2 v = upk2(acc[i][k]);
            float m0 = mishf(v.x + dbv[k].x);
            float m1 = mishf(v.y + dbv[k].y);
            out[2*k] = m0; out[2*k+1] = m1;
            s += m0*m0 + m1*m1;
        }
        float4* dst = (float4*)&beS[(r0+i)*HHD + c0];
        dst[0] = make_float4(out[0], out[1], out[2], out[3]);
        dst[1] = make_float4(out[4], out[5], out[6], out[7]);
        ss[i] = s;
    }
    // reduce squared sums over the 16 lanes of each head group
    #pragma unroll
    for (int i = 0; i < 8; i++){
        float s = ss[i];
        s += __shfl_xor_sync(0xffffffffu, s, 1);
        s += __shfl_xor_sync(0xffffffffu, s, 2);
        s += __shfl_xor_sync(0xffffffffu, s, 4);
        s += __shfl_xor_sync(0xffffffffu, s, 8);
        if ((t & 15) == 0) sqS[(r0+i)*4 + head] = s;
    }
    __syncthreads();
    if (t < 256){
        int r = t >> 2, h = t & 3;
        g_diffs[(long)h*NPAIR + pair0 + r] = sqrtf(sqS[r*4 + h]);
    }

    // ---- GEMM2: bias_new = mish(beS @ bout_W + bb) ----
    if (writeBias){
        int icol = t & 63;     // output column
        int rg   = t >> 6;     // rows rg*8 .. rg*8+7
        ull acc2[8];
        #pragma unroll
        for (int ii = 0; ii < 8; ii++) acc2[ii] = 0ull;

        for (int jc = 0; jc < HHD; jc += 64){
            __syncthreads();
            {   // stage bout_W rows jc..jc+63 (contiguous 16 KB)
                const float4* s4 = (const float4*)(bW + jc*DD);
                float4* d4 = (float4*)bWs;
                d4[t]       = s4[t];
                d4[t + 512] = s4[t + 512];
            }
            __syncthreads();
            #pragma unroll 4
            for (int j = 0; j < 64; j += 4){
                float w0 = bWs[(j+0)*DD + icol];
                float w1 = bWs[(j+1)*DD + icol];
                float w2 = bWs[(j+2)*DD + icol];
                float w3 = bWs[(j+3)*DD + icol];
                ull wp0 = pk2(w0, w1);
                ull wp1 = pk2(w2, w3);
                #pragma unroll
                for (int ii = 0; ii < 8; ii++){
                    // be[row][j..j+3] as two packed f32x2 (zero-cost reinterpret)
                    ulonglong2 bq = *(const ulonglong2*)&beS[(rg*8+ii)*HHD + jc + j];
                    fma2(acc2[ii], bq.x, wp0);   // lanes hold partial sums over j,j+1
                    fma2(acc2[ii], bq.y, wp1);   // and j+2,j+3 — merged at the end
                }
            }
        }
        float bbv = bb[icol];
        #pragma unroll
        for (int ii = 0; ii < 8; ii++){
            float2 v = upk2(acc2[ii]);
            float val = v.x + v.y + bbv;
            bnew[(pair0 + rg*8 + ii)*DD + icol] = mishf(val);
        }
    }
}

// ---------------- K5: attention (logits + softmax + attn@v), per (head, 16-row tile) ----
__global__ void __launch_bounds__(512,1) k_attn(float scale){
    int h  = blockIdx.y;
    int n0 = blockIdx.x * 16;
    __shared__ float qS[16*HD];      // 8 KB
    __shared__ float lg[16*NN_N];    // 32 KB
    int t = threadIdx.x;

    for (int idx = t; idx < 16*HD; idx += 512){
        int nn = idx >> 7, d = idx & 127;
        qS[idx] = g_qkv[(long)(n0+nn)*(3*HHD) + h*384 + d];
    }
    __syncthreads();

    {   // logits: thread = key index m
        int m = t;
        float acc[16];
        #pragma unroll
        for (int nn = 0; nn < 16; nn++) acc[nn] = 0.f;
        const float* kp = g_qkv + (long)m*(3*HHD) + h*384 + 128;
        #pragma unroll 4
        for (int d = 0; d < HD; d += 4){
            float4 kv = *(const float4*)(kp + d);
            #pragma unroll
            for (int nn = 0; nn < 16; nn++){
                float4 qv = *(const float4*)&qS[nn*HD + d];
                acc[nn] += qv.x*kv.x + qv.y*kv.y + qv.z*kv.z + qv.w*kv.w;
            }
        }
        const float* dp = g_diffs + (long)h*NPAIR + (long)n0*NN_N + m;
        #pragma unroll
        for (int nn = 0; nn < 16; nn++)
            lg[nn*NN_N + m] = acc[nn]*scale + dp[(long)nn*NN_N];
    }
    __syncthreads();

    {   // softmax per row (32 lanes per row)
        int row = t >> 5, lane = t & 31;
        float* Lr = lg + row*NN_N;
        float mx = -1e30f;
        for (int m = lane; m < NN_N; m += 32) mx = fmaxf(mx, Lr[m]);
        #pragma unroll
        for (int o = 16; o; o >>= 1) mx = fmaxf(mx, __shfl_xor_sync(0xffffffffu, mx, o));
        float sum = 0.f;
        for (int m = lane; m < NN_N; m += 32){
            float e = __expf(Lr[m] - mx); Lr[m] = e; sum += e;
        }
        #pragma unroll
        for (int o = 16; o; o >>= 1) sum += __shfl_xor_sync(0xffffffffu, sum, o);
        float inv = 1.f / sum;
        for (int m = lane; m < NN_N; m += 32) Lr[m] *= inv;
    }
    __syncthreads();

    {   // vals = attn @ v
        int d = t & 127, ng = t >> 7;          // 4 rows per thread
        float acc[4] = {0.f, 0.f, 0.f, 0.f};
        const float* vp = g_qkv + h*384 + 256 + d;
        #pragma unroll 4
        for (int m = 0; m < NN_N; m++){
            float vv = vp[(long)m*(3*HHD)];
            #pragma unroll
            for (int k = 0; k < 4; k++) acc[k] += lg[(ng*4+k)*NN_N + m] * vv;
        }
        #pragma unroll
        for (int k = 0; k < 4; k++)
            g_vals[(long)(n0 + ng*4 + k)*HHD + h*HD + d] = acc[k];
    }
}

// ---------------- K5b: x = LN2(x + vals @ o_W + o_b) ----------------
__global__ void k_oln(const float* __restrict__ oW, const float* __restrict__ ob,
                      const float* __restrict__ g2, const float* __restrict__ b2){
    int n = blockIdx.x, i = threadIdx.x;   // 64 threads
    const float* vr = g_vals + (long)n*HHD;
    float a0 = 0.f, a1 = 0.f;
    #pragma unroll 4
    for (int j = 0; j < HHD; j += 2){
        a0 += vr[j]   * oW[j*DD + i];
        a1 += vr[j+1] * oW[(j+1)*DD + i];
    }
    float xv = g_x[n*DD + i] + a0 + a1 + ob[i];
    __shared__ float s[DD];
    s[i] = xv; __syncthreads();
    float mu = 0.f;
    #pragma unroll
    for (int k = 0; k < DD; k++) mu += s[k];
    mu *= (1.f/DD);
    float var = 0.f;
    #pragma unroll
    for (int k = 0; k < DD; k++){ float dd = s[k]-mu; var += dd*dd; }
    var *= (1.f/DD);
    g_x[n*DD + i] = (xv - mu) * rsqrtf(var + EPSV) * g2[i] + b2[i];
}

// ---------------- K6: out = x @ out_W + out_b ----------------
__global__ void k_out(const float* __restrict__ W, const float* __restrict__ bo,
                      float* __restrict__ out){
    int n = threadIdx.x;                   // <<<1,512>>>
    float acc = bo[0];
    #pragma unroll
    for (int d = 0; d < DD; d++) acc += g_x[n*DD + d] * W[d];
    out[n] = acc;
}

// ---------------- launcher ----------------
extern "C" void kernel_launch(void* const* d_in, const int* in_sizes, int n_in,
                              void* d_out, int out_size){
    const float* nf    = (const float*)d_in[0];
    const float* amds  = (const float*)d_in[1];
    const float* embW  = (const float*)d_in[2];
    const float* embb  = (const float*)d_in[3];
    const float* bembW = (const float*)d_in[4];
    const float* bembb = (const float*)d_in[5];
    const float* ln1g  = (const float*)d_in[6];
    const float* ln1b  = (const float*)d_in[7];
    const float* ln2g  = (const float*)d_in[8];
    const float* ln2b  = (const float*)d_in[9];
    const float* qkvW  = (const float*)d_in[10];
    const float* qkvb  = (const float*)d_in[11];
    const float* diffW = (const float*)d_in[12];
    const float* diffb = (const float*)d_in[13];
    const float* oW    = (const float*)d_in[14];
    const float* ob    = (const float*)d_in[15];
    const float* boutW = (const float*)d_in[16];
    const float* boutb = (const float*)d_in[17];
    const float* outW  = (const float*)d_in[18];
    const float* outb  = (const float*)d_in[19];

    cudaFuncSetAttribute(k_be, cudaFuncAttributeMaxDynamicSharedMemorySize, BE_SMEM);

    k_embed<<<NN_N, DD>>>(nf, amds, embW, embb, bembW, bembb, ln1g, ln1b);
    k_biasinit<<<NPAIR*DD/512, 512>>>();

    float scale = 1.f / sqrtf((float)HD);
    for (int l = 0; l < LAYERS; l++){
        k_qkv<<<NN_N/8, 512>>>(qkvW + (long)l*DD*3*HHD, qkvb + l*3*HHD);
        k_be<<<NPAIR/64, 512, BE_SMEM>>>(diffW + (long)l*DD*HHD, diffb + l*HHD,
                                         boutW + (long)l*HHD*DD, boutb + l*DD,
                                         l & 1, (l < LAYERS-1) ? 1 : 0);
        k_attn<<<dim3(NN_N/16, HH), 512>>>(scale);
        k_oln<<<NN_N, DD>>>(oW + (long)l*HHD*DD, ob + l*DD, ln2g, ln2b);
    }
    k_out<<<1, NN_N>>>(outW, outb, (float*)d_out);
}

// round 4
// speedup vs baseline: 1.1999x; 1.1999x over previous
#include <cuda_runtime.h>
#include <math.h>
#include <stdint.h>

#define NN_N   512
#define FB     256
#define DD     64
#define HH     4
#define HD     128
#define HHD    512
#define LAYERS 4
#define KDIM   100
#define NPAIR  (NN_N*NN_N)
#define EPSV   1e-5f
#define ROWS   128                 /* pair-rows per k_be block */
#define NBLK   (NPAIR/ROWS)        /* 2048 */

typedef unsigned long long ull;

// ---------------- device scratch (allocation-free) ----------------
// bias tensors stored TRANSPOSED per 128-row block: [blk][64 k][128 rows]
__device__ float g_bias0[NPAIR*DD];
__device__ float g_bias1[NPAIR*DD];
__device__ float g_diffs[HH*NPAIR];   // [h][n][m]
__device__ float g_x[NN_N*DD];
__device__ float g_b0[NN_N*DD];
__device__ float g_qkv[NN_N*3*HHD];
__device__ float g_vals[NN_N*HHD];

// ---------------- helpers ----------------
__device__ __forceinline__ ull pk2(float lo, float hi){
    ull r; asm("mov.b64 %0, {%1,%2};" : "=l"(r) : "f"(lo), "f"(hi)); return r;
}
__device__ __forceinline__ float2 upk2(ull v){
    float2 r; asm("mov.b64 {%0,%1}, %2;" : "=f"(r.x), "=f"(r.y) : "l"(v)); return r;
}
__device__ __forceinline__ void fma2(ull &d, ull a, ull b){
    asm("fma.rn.f32x2 %0, %1, %2, %3;" : "=l"(d) : "l"(a), "l"(b), "l"(d));
}
__device__ __forceinline__ uint32_t swz(uint32_t o){ return o ^ ((o>>3)&0x70u); }
// mish(x) = x*(1 - 2/(u*(u+2)+2)), u = e^x   (2 MUFU)
__device__ __forceinline__ float mish2(float x){
    float u = __expf(x);
    float t = fmaf(u, u, 2.f*u);
    return x * (1.f - __fdividef(2.f, t + 2.f));
}

// ---------------- K1: embeddings + LN1 ----------------
__global__ void k_embed(const float* __restrict__ nf, const float* __restrict__ am,
                        const float* __restrict__ eW, const float* __restrict__ eb,
                        const float* __restrict__ bW, const float* __restrict__ bbv,
                        const float* __restrict__ g1, const float* __restrict__ b1){
    int n = blockIdx.x, d = threadIdx.x;
    float acc = eb[d];
    for (int f = 0; f < FB; f++) acc += nf[n*FB + f] * eW[f*DD + d];
    float b0 = bbv[d];
    for (int k = 0; k < KDIM; k++) b0 += am[n*KDIM + k] * bW[k*DD + d];
    g_b0[n*DD + d] = b0;
    __shared__ float s[DD];
    s[d] = acc; __syncthreads();
    float mu = 0.f;
    #pragma unroll
    for (int k = 0; k < DD; k++) mu += s[k];
    mu *= (1.f/DD);
    float var = 0.f;
    #pragma unroll
    for (int k = 0; k < DD; k++){ float dd = s[k]-mu; var += dd*dd; }
    var *= (1.f/DD);
    g_x[n*DD + d] = (acc - mu) * rsqrtf(var + EPSV) * g1[d] + b1[d];
}

// ---------------- K2: bias init (transposed layout) ----------------
__global__ void k_biasinit(){      // grid NBLK, 256 threads
    int blk = blockIdx.x;
    int n  = blk >> 2;             // 4 blocks per n (512 m's / 128 rows)
    int m0 = (blk & 3) * ROWS;
    __shared__ float bn[DD];
    __shared__ float bm[ROWS*65];
    int t = threadIdx.x;
    if (t < DD) bn[t] = g_b0[n*DD + t];
    for (int i = t; i < ROWS*DD; i += 256){
        int r = i >> 6, k = i & 63;
        bm[r*65 + k] = g_b0[m0*DD + i];
    }
    __syncthreads();
    float* out = g_bias0 + (long)blk * (ROWS*DD);
    for (int i = t; i < ROWS*DD; i += 256){
        int k = i >> 7, r = i & 127;
        out[i] = bm[r*65 + k] - bn[k];
    }
}

// ---------------- K3: qkv ----------------
__global__ void __launch_bounds__(512,1)
k_qkv(const float* __restrict__ W, const float* __restrict__ b){
    int n0 = blockIdx.x * 8;
    __shared__ float xs[8*DD];
    int t = threadIdx.x;
    xs[t] = g_x[n0*DD + t];
    __syncthreads();
    for (int j = t; j < 3*HHD; j += 512){
        float acc[8];
        float bv = b[j];
        #pragma unroll
        for (int r = 0; r < 8; r++) acc[r] = bv;
        #pragma unroll 8
        for (int d = 0; d < DD; d++){
            float w = W[d*(3*HHD) + j];
            #pragma unroll
            for (int r = 0; r < 8; r++) acc[r] += xs[r*DD + d] * w;
        }
        #pragma unroll
        for (int r = 0; r < 8; r++) g_qkv[(long)(n0+r)*(3*HHD) + j] = acc[r];
    }
}

// ---------------- K4: register-tiled FFMA2 fused be kernel ----------------
// block: 128 pair-rows, 256 threads. 8 chunks of 64 cols:
//   GEMM1: be_chunk = mish(biasT @ W1_c + db)  -> beT smem + sq-norm partials
//   GEMM2: acc2 += beT @ W2_c  (register-persistent), final mish -> biasT'
#define SO_BT 0
#define SO_BE 8192
#define SO_W1 16384
#define SO_W2 20736
#define SO_SQ 25088
#define BE_SMEM ((25088+512)*4)

__device__ __forceinline__ void gemm_step(const char* smA, const float* smW,
                                          ull (&acc)[4][4], uint32_t aLoOff,
                                          uint32_t aHiOff, int c0){
    #pragma unroll 4
    for (int k = 0; k < 64; k++){
        ulonglong2 aLo = *(const ulonglong2*)(smA + k*512 + aLoOff);
        ulonglong2 aHi = *(const ulonglong2*)(smA + k*512 + aHiOff);
        const float* wr = smW + k*68 + c0;
        #pragma unroll
        for (int j = 0; j < 4; j++){
            float wv = wr[j];
            ull b = pk2(wv, wv);
            fma2(acc[0][j], aLo.x, b);
            fma2(acc[1][j], aLo.y, b);
            fma2(acc[2][j], aHi.x, b);
            fma2(acc[3][j], aHi.y, b);
        }
    }
}

__global__ void __launch_bounds__(256,1)
k_be(const float* __restrict__ dW, const float* __restrict__ db,
     const float* __restrict__ bW, const float* __restrict__ bb,
     int flip, int writeBias){
    extern __shared__ float smf[];
    char* smc = (char*)smf;
    int t = threadIdx.x, w = t>>5, lane = t&31;
    int wr = w>>2, wc = w&3;
    int rl = lane>>2, cl = lane&3;
    int r0 = wr*64 + rl*8;
    int c0 = wc*16 + cl*4;
    uint32_t aLoOff = swz((uint32_t)(r0*4));
    uint32_t aHiOff = swz((uint32_t)(r0*4 + 16));
    long blk = blockIdx.x;
    long pair0 = blk * ROWS;

    const float* binT = (flip ? g_bias1 : g_bias0) + blk*(ROWS*DD);
    float*       bnew = (flip ? g_bias0 : g_bias1) + blk*(ROWS*DD);

    // prologue: copy biasT [64][128] into swizzled smem
    for (int i = t; i < 2048; i += 256){
        int k = i >> 5, r4 = i & 31;
        float4 v = ((const float4*)binT)[i];
        *(float4*)(smc + k*512 + swz((uint32_t)(r4*16))) = v;
    }
    for (int i = t; i < 512; i += 256) smf[SO_SQ + i] = 0.f;

    ull acc2[4][4];
    #pragma unroll
    for (int p = 0; p < 4; p++)
        #pragma unroll
        for (int j = 0; j < 4; j++) acc2[p][j] = 0ull;

    for (int c = 0; c < 8; c++){
        __syncthreads();   // W tiles / beT free for reuse
        // stage W1 chunk [64][64] (+W2 if needed), padded rows of 68
        for (int i = t; i < 1024; i += 256){
            int k = i >> 4, q = i & 15;
            float4 v = *(const float4*)(dW + k*HHD + c*64 + q*4);
            *(float4*)&smf[SO_W1 + k*68 + q*4] = v;
            if (writeBias){
                float4 u = *(const float4*)(bW + (c*64 + k)*DD + q*4);
                *(float4*)&smf[SO_W2 + k*68 + q*4] = u;
            }
        }
        __syncthreads();

        // GEMM1
        ull acc1[4][4];
        #pragma unroll
        for (int p = 0; p < 4; p++)
            #pragma unroll
            for (int j = 0; j < 4; j++) acc1[p][j] = 0ull;
        gemm_step(smc + SO_BT*4, smf + SO_W1, acc1, aLoOff, aHiOff, c0);

        // epilogue: +db, mish, write beT (swizzled), sq partials
        float rs[8];
        #pragma unroll
        for (int i = 0; i < 8; i++) rs[i] = 0.f;
        float mv[4][4][2];
        #pragma unroll
        for (int j = 0; j < 4; j++){
            float dbv = __ldg(&db[c*64 + c0 + j]);
            #pragma unroll
            for (int p = 0; p < 4; p++){
                float2 v = upk2(acc1[p][j]);
                float m0 = mish2(v.x + dbv);
                float m1 = mish2(v.y + dbv);
                mv[p][j][0] = m0; mv[p][j][1] = m1;
                rs[2*p]   = fmaf(m0, m0, rs[2*p]);
                rs[2*p+1] = fmaf(m1, m1, rs[2*p+1]);
            }
        }
        #pragma unroll
        for (int j = 0; j < 4; j++){
            char* base = smc + SO_BE*4 + (c0 + j)*512;
            *(float4*)(base + aLoOff) = make_float4(mv[0][j][0], mv[0][j][1], mv[1][j][0], mv[1][j][1]);
            *(float4*)(base + aHiOff) = make_float4(mv[2][j][0], mv[2][j][1], mv[3][j][0], mv[3][j][1]);
        }
        #pragma unroll
        for (int i = 0; i < 8; i++){
            float s = rs[i];
            s += __shfl_xor_sync(0xffffffffu, s, 1);
            s += __shfl_xor_sync(0xffffffffu, s, 2);
            if (cl == 0) smf[SO_SQ + (r0+i)*4 + wc] += s;
        }
        __syncthreads();

        // head boundary: diffs = sqrt(sum of sq partials), reset accumulators
        if (c & 1){
            if (t < ROWS){
                float s = smf[SO_SQ + t*4+0] + smf[SO_SQ + t*4+1]
                        + smf[SO_SQ + t*4+2] + smf[SO_SQ + t*4+3];
                g_diffs[(long)(c>>1)*NPAIR + pair0 + t] = sqrtf(s);
                smf[SO_SQ + t*4+0] = 0.f; smf[SO_SQ + t*4+1] = 0.f;
                smf[SO_SQ + t*4+2] = 0.f; smf[SO_SQ + t*4+3] = 0.f;
            }
        }

        // GEMM2 (accumulate across chunks)
        if (writeBias)
            gemm_step(smc + SO_BE*4, smf + SO_W2, acc2, aLoOff, aHiOff, c0);
    }

    // final: bias' = mish(acc2 + bb), transposed store
    if (writeBias){
        #pragma unroll
        for (int j = 0; j < 4; j++){
            float bbv = __ldg(&bb[c0 + j]);
            float o[8];
            #pragma unroll
            for (int p = 0; p < 4; p++){
                float2 v = upk2(acc2[p][j]);
                o[2*p]   = mish2(v.x + bbv);
                o[2*p+1] = mish2(v.y + bbv);
            }
            float* dst = bnew + (long)(c0 + j)*ROWS + r0;
            *(float4*)dst       = make_float4(o[0], o[1], o[2], o[3]);
            *(float4*)(dst + 4) = make_float4(o[4], o[5], o[6], o[7]);
        }
    }
}

// ---------------- K5: attention ----------------
__global__ void __launch_bounds__(512,1) k_attn(float scale){
    int h  = blockIdx.y;
    int n0 = blockIdx.x * 16;
    __shared__ float qS[16*HD];
    __shared__ float lg[16*NN_N];
    int t = threadIdx.x;

    for (int idx = t; idx < 16*HD; idx += 512){
        int nn = idx >> 7, d = idx & 127;
        qS[idx] = g_qkv[(long)(n0+nn)*(3*HHD) + h*384 + d];
    }
    __syncthreads();
    {
        int m = t;
        float acc[16];
        #pragma unroll
        for (int nn = 0; nn < 16; nn++) acc[nn] = 0.f;
        const float* kp = g_qkv + (long)m*(3*HHD) + h*384 + 128;
        #pragma unroll 4
        for (int d = 0; d < HD; d += 4){
            float4 kv = *(const float4*)(kp + d);
            #pragma unroll
            for (int nn = 0; nn < 16; nn++){
                float4 qv = *(const float4*)&qS[nn*HD + d];
                acc[nn] += qv.x*kv.x + qv.y*kv.y + qv.z*kv.z + qv.w*kv.w;
            }
        }
        const float* dp = g_diffs + (long)h*NPAIR + (long)n0*NN_N + m;
        #pragma unroll
        for (int nn = 0; nn < 16; nn++)
            lg[nn*NN_N + m] = acc[nn]*scale + dp[(long)nn*NN_N];
    }
    __syncthreads();
    {
        int row = t >> 5, lane = t & 31;
        float* Lr = lg + row*NN_N;
        float mx = -1e30f;
        for (int m = lane; m < NN_N; m += 32) mx = fmaxf(mx, Lr[m]);
        #pragma unroll
        for (int o = 16; o; o >>= 1) mx = fmaxf(mx, __shfl_xor_sync(0xffffffffu, mx, o));
        float sum = 0.f;
        for (int m = lane; m < NN_N; m += 32){
            float e = __expf(Lr[m] - mx); Lr[m] = e; sum += e;
        }
        #pragma unroll
        for (int o = 16; o; o >>= 1) sum += __shfl_xor_sync(0xffffffffu, sum, o);
        float inv = 1.f / sum;
        for (int m = lane; m < NN_N; m += 32) Lr[m] *= inv;
    }
    __syncthreads();
    {
        int d = t & 127, ng = t >> 7;
        float acc[4] = {0.f, 0.f, 0.f, 0.f};
        const float* vp = g_qkv + h*384 + 256 + d;
        #pragma unroll 4
        for (int m = 0; m < NN_N; m++){
            float vv = vp[(long)m*(3*HHD)];
            #pragma unroll
            for (int k = 0; k < 4; k++) acc[k] += lg[(ng*4+k)*NN_N + m] * vv;
        }
        #pragma unroll
        for (int k = 0; k < 4; k++)
            g_vals[(long)(n0 + ng*4 + k)*HHD + h*HD + d] = acc[k];
    }
}

// ---------------- K5b: x = LN2(x + vals @ o_W + o_b) ----------------
__global__ void k_oln(const float* __restrict__ oW, const float* __restrict__ ob,
                      const float* __restrict__ g2, const float* __restrict__ b2){
    int n = blockIdx.x, i = threadIdx.x;
    const float* vr = g_vals + (long)n*HHD;
    float a0 = 0.f, a1 = 0.f;
    #pragma unroll 4
    for (int j = 0; j < HHD; j += 2){
        a0 += vr[j]   * oW[j*DD + i];
        a1 += vr[j+1] * oW[(j+1)*DD + i];
    }
    float xv = g_x[n*DD + i] + a0 + a1 + ob[i];
    __shared__ float s[DD];
    s[i] = xv; __syncthreads();
    float mu = 0.f;
    #pragma unroll
    for (int k = 0; k < DD; k++) mu += s[k];
    mu *= (1.f/DD);
    float var = 0.f;
    #pragma unroll
    for (int k = 0; k < DD; k++){ float dd = s[k]-mu; var += dd*dd; }
    var *= (1.f/DD);
    g_x[n*DD + i] = (xv - mu) * rsqrtf(var + EPSV) * g2[i] + b2[i];
}

// ---------------- K6 ----------------
__global__ void k_out(const float* __restrict__ W, const float* __restrict__ bo,
                      float* __restrict__ out){
    int n = threadIdx.x;
    float acc = bo[0];
    #pragma unroll
    for (int d = 0; d < DD; d++) acc += g_x[n*DD + d] * W[d];
    out[n] = acc;
}

// ---------------- launcher ----------------
extern "C" void kernel_launch(void* const* d_in, const int* in_sizes, int n_in,
                              void* d_out, int out_size){
    const float* nf    = (const float*)d_in[0];
    const float* amds  = (const float*)d_in[1];
    const float* embW  = (const float*)d_in[2];
    const float* embb  = (const float*)d_in[3];
    const float* bembW = (const float*)d_in[4];
    const float* bembb = (const float*)d_in[5];
    const float* ln1g  = (const float*)d_in[6];
    const float* ln1b  = (const float*)d_in[7];
    const float* ln2g  = (const float*)d_in[8];
    const float* ln2b  = (const float*)d_in[9];
    const float* qkvW  = (const float*)d_in[10];
    const float* qkvb  = (const float*)d_in[11];
    const float* diffW = (const float*)d_in[12];
    const float* diffb = (const float*)d_in[13];
    const float* oW    = (const float*)d_in[14];
    const float* ob    = (const float*)d_in[15];
    const float* boutW = (const float*)d_in[16];
    const float* boutb = (const float*)d_in[17];
    const float* outW  = (const float*)d_in[18];
    const float* outb  = (const float*)d_in[19];

    cudaFuncSetAttribute(k_be, cudaFuncAttributeMaxDynamicSharedMemorySize, BE_SMEM);

    k_embed<<<NN_N, DD>>>(nf, amds, embW, embb, bembW, bembb, ln1g, ln1b);
    k_biasinit<<<NBLK, 256>>>();

    float scale = 1.f / sqrtf((float)HD);
    for (int l = 0; l < LAYERS; l++){
        k_qkv<<<NN_N/8, 512>>>(qkvW + (long)l*DD*3*HHD, qkvb + l*3*HHD);
        k_be<<<NBLK, 256, BE_SMEM>>>(diffW + (long)l*DD*HHD, diffb + (long)l*HHD,
                                     boutW + (long)l*HHD*DD, boutb + (long)l*DD,
                                     l & 1, (l < LAYERS-1) ? 1 : 0);
        k_attn<<<dim3(NN_N/16, HH), 512>>>(scale);
        k_oln<<<NN_N, DD>>>(oW + (long)l*HHD*DD, ob + l*DD, ln2g, ln2b);
    }
    k_out<<<1, NN_N>>>(outW, outb, (float*)d_out);
}

// round 5
// speedup vs baseline: 1.7897x; 1.4915x over previous
#include <cuda_runtime.h>
#include <cuda_fp16.h>
#include <math.h>
#include <stdint.h>

#define NN_N   512
#define FB     256
#define DD     64
#define HH     4
#define HD     128
#define HHD    512
#define LAYERS 4
#define KDIM   100
#define NPAIR  (NN_N*NN_N)
#define EPSV   1e-5f
#define ROWS   128
#define NBLK   (NPAIR/ROWS)      /* 2048 */
#define PADK   72                /* halves per smem row (conflict-free) */

// ---------------- device scratch ----------------
__device__ float g_bias0[NPAIR*DD];   // row-major [pair][64]
__device__ float g_bias1[NPAIR*DD];
__device__ float g_diffs[HH*NPAIR];
__device__ float g_x[NN_N*DD];
__device__ float g_b0[NN_N*DD];
__device__ float g_qkv[NN_N*3*HHD];
__device__ float g_vals[NN_N*HHD];
// pre-split / transposed / padded weights: [l][chunk][64 n][72 k] halves
__device__ __half g_w1h[LAYERS*8*64*PADK];
__device__ __half g_w1l[LAYERS*8*64*PADK];
__device__ __half g_w2h[LAYERS*8*64*PADK];
__device__ __half g_w2l[LAYERS*8*64*PADK];

// ---------------- helpers ----------------
__device__ __forceinline__ float mish2(float x){
    float u = __expf(x);
    float t = fmaf(u, u, 2.f*u);
    return x * (1.f - __fdividef(2.f, t + 2.f));
}
__device__ __forceinline__ void mma16816(float (&d)[4], const uint32_t* a, const uint32_t* b){
    asm volatile("mma.sync.aligned.m16n8k16.row.col.f32.f16.f16.f32 "
        "{%0,%1,%2,%3}, {%4,%5,%6,%7}, {%8,%9}, {%0,%1,%2,%3};"
        : "+f"(d[0]), "+f"(d[1]), "+f"(d[2]), "+f"(d[3])
        : "r"(a[0]), "r"(a[1]), "r"(a[2]), "r"(a[3]), "r"(b[0]), "r"(b[1]));
}

// fp16-split 3-product GEMM: D += A(128x64) @ B^T(64x64)  (B stored [n][k])
__device__ __forceinline__ void mma_gemm(const __half* sAh, const __half* sAl,
                                         const __half* sBh, const __half* sBl,
                                         float (&d)[2][4][4],
                                         int q, int qt, int wrow, int wcol){
    #pragma unroll
    for (int k0 = 0; k0 < 64; k0 += 16){
        uint32_t ah[2][4], al[2][4];
        #pragma unroll
        for (int ma = 0; ma < 2; ma++){
            int rb = wrow*32 + ma*16 + q;
            const __half* ph = sAh + rb*PADK + k0 + qt*2;
            const __half* pl = sAl + rb*PADK + k0 + qt*2;
            ah[ma][0] = *(const uint32_t*)(ph);
            ah[ma][1] = *(const uint32_t*)(ph + 8*PADK);
            ah[ma][2] = *(const uint32_t*)(ph + 8);
            ah[ma][3] = *(const uint32_t*)(ph + 8*PADK + 8);
            al[ma][0] = *(const uint32_t*)(pl);
            al[ma][1] = *(const uint32_t*)(pl + 8*PADK);
            al[ma][2] = *(const uint32_t*)(pl + 8);
            al[ma][3] = *(const uint32_t*)(pl + 8*PADK + 8);
        }
        #pragma unroll
        for (int na = 0; na < 4; na++){
            int nb = wcol*32 + na*8 + q;
            const __half* qh = sBh + nb*PADK + k0 + qt*2;
            const __half* ql = sBl + nb*PADK + k0 + qt*2;
            uint32_t bh[2], bl[2];
            bh[0] = *(const uint32_t*)(qh); bh[1] = *(const uint32_t*)(qh + 8);
            bl[0] = *(const uint32_t*)(ql); bl[1] = *(const uint32_t*)(ql + 8);
            #pragma unroll
            for (int ma = 0; ma < 2; ma++){
                mma16816(d[ma][na], ah[ma], bh);
                mma16816(d[ma][na], ah[ma], bl);
                mma16816(d[ma][na], al[ma], bh);
            }
        }
    }
}

// ---------------- K0: weight split/transpose/pad prep ----------------
__global__ void k_wsplit(const float* __restrict__ dW, const float* __restrict__ bW){
    int idx = blockIdx.x*256 + threadIdx.x;     // 4*8*64*64 = 131072
    int k = idx & 63;
    int n = (idx>>6) & 63;
    int c = (idx>>12) & 7;
    int l = idx>>15;
    int dst = ((l*8 + c)*64 + n)*PADK + k;
    float v1 = dW[(long)l*DD*HHD + (long)k*HHD + c*64 + n];
    __half h1 = __float2half_rn(v1);
    g_w1h[dst] = h1;
    g_w1l[dst] = __float2half_rn(v1 - __half2float(h1));
    float v2 = bW[(long)l*HHD*DD + (long)(c*64 + k)*DD + n];
    __half h2 = __float2half_rn(v2);
    g_w2h[dst] = h2;
    g_w2l[dst] = __float2half_rn(v2 - __half2float(h2));
}

// ---------------- K1: embeddings + LN1 ----------------
__global__ void k_embed(const float* __restrict__ nf, const float* __restrict__ am,
                        const float* __restrict__ eW, const float* __restrict__ eb,
                        const float* __restrict__ bW, const float* __restrict__ bbv,
                        const float* __restrict__ g1, const float* __restrict__ b1){
    int n = blockIdx.x, d = threadIdx.x;
    float acc = eb[d];
    for (int f = 0; f < FB; f++) acc += nf[n*FB + f] * eW[f*DD + d];
    float b0 = bbv[d];
    for (int k = 0; k < KDIM; k++) b0 += am[n*KDIM + k] * bW[k*DD + d];
    g_b0[n*DD + d] = b0;
    __shared__ float s[DD];
    s[d] = acc; __syncthreads();
    float mu = 0.f;
    #pragma unroll
    for (int k = 0; k < DD; k++) mu += s[k];
    mu *= (1.f/DD);
    float var = 0.f;
    #pragma unroll
    for (int k = 0; k < DD; k++){ float dd = s[k]-mu; var += dd*dd; }
    var *= (1.f/DD);
    g_x[n*DD + d] = (acc - mu) * rsqrtf(var + EPSV) * g1[d] + b1[d];
}

// ---------------- K2: bias init (row-major) ----------------
__global__ void k_biasinit(){
    long idx = (long)blockIdx.x * blockDim.x + threadIdx.x;
    int d = (int)(idx & 63);
    long pair = idx >> 6;
    int m = (int)(pair & 511);
    int n = (int)(pair >> 9);
    g_bias0[idx] = g_b0[m*DD + d] - g_b0[n*DD + d];
}

// ---------------- K3: qkv ----------------
__global__ void __launch_bounds__(512,1)
k_qkv(const float* __restrict__ W, const float* __restrict__ b){
    int n0 = blockIdx.x * 8;
    __shared__ float xs[8*DD];
    int t = threadIdx.x;
    xs[t] = g_x[n0*DD + t];
    __syncthreads();
    for (int j = t; j < 3*HHD; j += 512){
        float acc[8];
        float bv = b[j];
        #pragma unroll
        for (int r = 0; r < 8; r++) acc[r] = bv;
        #pragma unroll 8
        for (int d = 0; d < DD; d++){
            float w = W[d*(3*HHD) + j];
            #pragma unroll
            for (int r = 0; r < 8; r++) acc[r] += xs[r*DD + d] * w;
        }
        #pragma unroll
        for (int r = 0; r < 8; r++) g_qkv[(long)(n0+r)*(3*HHD) + j] = acc[r];
    }
}

// ---------------- K4: HMMA fp16-split fused be kernel ----------------
// smem (halves): A hi/lo [128][72], be hi/lo [128][72], W1 hi/lo [64][72], W2 hi/lo [64][72]
#define SA_H 0
#define SA_L 9216
#define SE_H 18432
#define SE_L 27648
#define SW1H 36864
#define SW1L 41472
#define SW2H 46080
#define SW2L 50688
#define SM_HALVES 55296
#define BE_SMEM (SM_HALVES*2 + 512)

__global__ void __launch_bounds__(256,1)
k_be(int l, const float* __restrict__ db, const float* __restrict__ bb,
     int flip, int writeBias){
    extern __shared__ __half smh[];
    float* sq = (float*)(smh + SM_HALVES);
    int t = threadIdx.x, w = t>>5, lane = t&31;
    int wrow = w>>1, wcol = w&1;
    int q = lane>>2, qt = lane&3;
    long blk = blockIdx.x;
    long pair0 = blk * ROWS;

    const float* bin  = (flip ? g_bias1 : g_bias0) + pair0*DD;
    float*       bnew = (flip ? g_bias0 : g_bias1) + pair0*DD;

    // prologue: bias tile fp32 -> hi/lo half planes
    for (int i = t; i < 2048; i += 256){       // 2048 float4 = 128x64
        int r = i >> 4, c4 = (i & 15)*4;
        float4 v = ((const float4*)bin)[i];
        __half2 h0 = __floats2half2_rn(v.x, v.y);
        __half2 h1 = __floats2half2_rn(v.z, v.w);
        float2 f0 = __half22float2(h0);
        float2 f1 = __half22float2(h1);
        __half2 l0 = __floats2half2_rn(v.x - f0.x, v.y - f0.y);
        __half2 l1 = __floats2half2_rn(v.z - f1.x, v.w - f1.y);
        __half2* dh = (__half2*)(smh + SA_H + r*PADK + c4);
        __half2* dl = (__half2*)(smh + SA_L + r*PADK + c4);
        dh[0] = h0; dh[1] = h1;
        dl[0] = l0; dl[1] = l1;
    }
    if (t < 128) sq[t] = 0.f;

    float acc2[2][4][4];
    #pragma unroll
    for (int ma = 0; ma < 2; ma++)
        #pragma unroll
        for (int na = 0; na < 4; na++)
            #pragma unroll
            for (int i = 0; i < 4; i++) acc2[ma][na][i] = 0.f;

    for (int c = 0; c < 8; c++){
        __syncthreads();
        {   // stage weight chunk images (contiguous, 576 float4 per plane)
            long wb = ((long)(l*8 + c) * 64) * PADK;   // halves; *2 bytes, 16B-aligned
            const float4* s1h = (const float4*)(g_w1h + wb);
            const float4* s1l = (const float4*)(g_w1l + wb);
            float4* d1h = (float4*)(smh + SW1H);
            float4* d1l = (float4*)(smh + SW1L);
            for (int i = t; i < 576; i += 256){ d1h[i] = s1h[i]; d1l[i] = s1l[i]; }
            if (writeBias){
                const float4* s2h = (const float4*)(g_w2h + wb);
                const float4* s2l = (const float4*)(g_w2l + wb);
                float4* d2h = (float4*)(smh + SW2H);
                float4* d2l = (float4*)(smh + SW2L);
                for (int i = t; i < 576; i += 256){ d2h[i] = s2h[i]; d2l[i] = s2l[i]; }
            }
        }
        __syncthreads();

        // GEMM1
        float d1[2][4][4];
        #pragma unroll
        for (int ma = 0; ma < 2; ma++)
            #pragma unroll
            for (int na = 0; na < 4; na++)
                #pragma unroll
                for (int i = 0; i < 4; i++) d1[ma][na][i] = 0.f;
        mma_gemm(smh+SA_H, smh+SA_L, smh+SW1H, smh+SW1L, d1, q, qt, wrow, wcol);

        // epilogue: +db, mish, sq partials, split -> be planes
        float rs[2][2] = {{0.f,0.f},{0.f,0.f}};
        #pragma unroll
        for (int ma = 0; ma < 2; ma++){
            int row0 = wrow*32 + ma*16 + q;
            #pragma unroll
            for (int na = 0; na < 4; na++){
                int colp = wcol*32 + na*8 + qt*2;
                float m0 = mish2(d1[ma][na][0] + __ldg(&db[c*64 + colp]));
                float m1 = mish2(d1[ma][na][1] + __ldg(&db[c*64 + colp + 1]));
                float m2 = mish2(d1[ma][na][2] + __ldg(&db[c*64 + colp]));
                float m3 = mish2(d1[ma][na][3] + __ldg(&db[c*64 + colp + 1]));
                rs[ma][0] = fmaf(m0,m0, fmaf(m1,m1, rs[ma][0]));
                rs[ma][1] = fmaf(m2,m2, fmaf(m3,m3, rs[ma][1]));
                __half2 h01 = __floats2half2_rn(m0, m1);
                __half2 h23 = __floats2half2_rn(m2, m3);
                float2 f01 = __half22float2(h01);
                float2 f23 = __half22float2(h23);
                __half2 l01 = __floats2half2_rn(m0 - f01.x, m1 - f01.y);
                __half2 l23 = __floats2half2_rn(m2 - f23.x, m3 - f23.y);
                *(__half2*)(smh + SE_H + row0*PADK + colp)       = h01;
                *(__half2*)(smh + SE_L + row0*PADK + colp)       = l01;
                *(__half2*)(smh + SE_H + (row0+8)*PADK + colp)   = h23;
                *(__half2*)(smh + SE_L + (row0+8)*PADK + colp)   = l23;
            }
        }
        #pragma unroll
        for (int ma = 0; ma < 2; ma++){
            #pragma unroll
            for (int hh = 0; hh < 2; hh++){
                float s = rs[ma][hh];
                s += __shfl_xor_sync(0xffffffffu, s, 1);
                s += __shfl_xor_sync(0xffffffffu, s, 2);
                if (qt == 0) atomicAdd(&sq[wrow*32 + ma*16 + q + hh*8], s);
            }
        }
        __syncthreads();
        if (c & 1){
            if (t < 128){
                g_diffs[(long)(c>>1)*NPAIR + pair0 + t] = sqrtf(sq[t]);
                sq[t] = 0.f;
            }
        }
        // GEMM2 (accumulate across chunks)
        if (writeBias)
            mma_gemm(smh+SE_H, smh+SE_L, smh+SW2H, smh+SW2L, acc2, q, qt, wrow, wcol);
    }

    // final: bias' = mish(acc2 + bb)
    if (writeBias){
        #pragma unroll
        for (int ma = 0; ma < 2; ma++){
            #pragma unroll
            for (int na = 0; na < 4; na++){
                int colp = wcol*32 + na*8 + qt*2;
                float bb0 = __ldg(&bb[colp]);
                float bb1 = __ldg(&bb[colp + 1]);
                int row0 = wrow*32 + ma*16 + q;
                float2 v0 = { mish2(acc2[ma][na][0] + bb0), mish2(acc2[ma][na][1] + bb1) };
                float2 v1 = { mish2(acc2[ma][na][2] + bb0), mish2(acc2[ma][na][3] + bb1) };
                *(float2*)&bnew[(long)row0*DD + colp]     = v0;
                *(float2*)&bnew[(long)(row0+8)*DD + colp] = v1;
            }
        }
    }
}

// ---------------- K5: attention ----------------
__global__ void __launch_bounds__(512,1) k_attn(float scale){
    int h  = blockIdx.y;
    int n0 = blockIdx.x * 16;
    __shared__ float qS[16*HD];
    __shared__ float lg[16*NN_N];
    int t = threadIdx.x;

    for (int idx = t; idx < 16*HD; idx += 512){
        int nn = idx >> 7, d = idx & 127;
        qS[idx] = g_qkv[(long)(n0+nn)*(3*HHD) + h*384 + d];
    }
    __syncthreads();
    {
        int m = t;
        float acc[16];
        #pragma unroll
        for (int nn = 0; nn < 16; nn++) acc[nn] = 0.f;
        const float* kp = g_qkv + (long)m*(3*HHD) + h*384 + 128;
        #pragma unroll 4
        for (int d = 0; d < HD; d += 4){
            float4 kv = *(const float4*)(kp + d);
            #pragma unroll
            for (int nn = 0; nn < 16; nn++){
                float4 qv = *(const float4*)&qS[nn*HD + d];
                acc[nn] += qv.x*kv.x + qv.y*kv.y + qv.z*kv.z + qv.w*kv.w;
            }
        }
        const float* dp = g_diffs + (long)h*NPAIR + (long)n0*NN_N + m;
        #pragma unroll
        for (int nn = 0; nn < 16; nn++)
            lg[nn*NN_N + m] = acc[nn]*scale + dp[(long)nn*NN_N];
    }
    __syncthreads();
    {
        int row = t >> 5, lane = t & 31;
        float* Lr = lg + row*NN_N;
        float mx = -1e30f;
        for (int m = lane; m < NN_N; m += 32) mx = fmaxf(mx, Lr[m]);
        #pragma unroll
        for (int o = 16; o; o >>= 1) mx = fmaxf(mx, __shfl_xor_sync(0xffffffffu, mx, o));
        float sum = 0.f;
        for (int m = lane; m < NN_N; m += 32){
            float e = __expf(Lr[m] - mx); Lr[m] = e; sum += e;
        }
        #pragma unroll
        for (int o = 16; o; o >>= 1) sum += __shfl_xor_sync(0xffffffffu, sum, o);
        float inv = 1.f / sum;
        for (int m = lane; m < NN_N; m += 32) Lr[m] *= inv;
    }
    __syncthreads();
    {
        int d = t & 127, ng = t >> 7;
        float acc[4] = {0.f, 0.f, 0.f, 0.f};
        const float* vp = g_qkv + h*384 + 256 + d;
        #pragma unroll 4
        for (int m = 0; m < NN_N; m++){
            float vv = vp[(long)m*(3*HHD)];
            #pragma unroll
            for (int k = 0; k < 4; k++) acc[k] += lg[(ng*4+k)*NN_N + m] * vv;
        }
        #pragma unroll
        for (int k = 0; k < 4; k++)
            g_vals[(long)(n0 + ng*4 + k)*HHD + h*HD + d] = acc[k];
    }
}

// ---------------- K5b: x = LN2(x + vals @ o_W + o_b) ----------------
__global__ void k_oln(const float* __restrict__ oW, const float* __restrict__ ob,
                      const float* __restrict__ g2, const float* __restrict__ b2){
    int n = blockIdx.x, i = threadIdx.x;
    const float* vr = g_vals + (long)n*HHD;
    float a0 = 0.f, a1 = 0.f;
    #pragma unroll 4
    for (int j = 0; j < HHD; j += 2){
        a0 += vr[j]   * oW[j*DD + i];
        a1 += vr[j+1] * oW[(j+1)*DD + i];
    }
    float xv = g_x[n*DD + i] + a0 + a1 + ob[i];
    __shared__ float s[DD];
    s[i] = xv; __syncthreads();
    float mu = 0.f;
    #pragma unroll
    for (int k = 0; k < DD; k++) mu += s[k];
    mu *= (1.f/DD);
    float var = 0.f;
    #pragma unroll
    for (int k = 0; k < DD; k++){ float dd = s[k]-mu; var += dd*dd; }
    var *= (1.f/DD);
    g_x[n*DD + i] = (xv - mu) * rsqrtf(var + EPSV) * g2[i] + b2[i];
}

// ---------------- K6 ----------------
__global__ void k_out(const float* __restrict__ W, const float* __restrict__ bo,
                      float* __restrict__ out){
    int n = threadIdx.x;
    float acc = bo[0];
    #pragma unroll
    for (int d = 0; d < DD; d++) acc += g_x[n*DD + d] * W[d];
    out[n] = acc;
}

// ---------------- launcher ----------------
extern "C" void kernel_launch(void* const* d_in, const int* in_sizes, int n_in,
                              void* d_out, int out_size){
    const float* nf    = (const float*)d_in[0];
    const float* amds  = (const float*)d_in[1];
    const float* embW  = (const float*)d_in[2];
    const float* embb  = (const float*)d_in[3];
    const float* bembW = (const float*)d_in[4];
    const float* bembb = (const float*)d_in[5];
    const float* ln1g  = (const float*)d_in[6];
    const float* ln1b  = (const float*)d_in[7];
    const float* ln2g  = (const float*)d_in[8];
    const float* ln2b  = (const float*)d_in[9];
    const float* qkvW  = (const float*)d_in[10];
    const float* qkvb  = (const float*)d_in[11];
    const float* diffW = (const float*)d_in[12];
    const float* diffb = (const float*)d_in[13];
    const float* oW    = (const float*)d_in[14];
    const float* ob    = (const float*)d_in[15];
    const float* boutW = (const float*)d_in[16];
    const float* boutb = (const float*)d_in[17];
    const float* outW  = (const float*)d_in[18];
    const float* outb  = (const float*)d_in[19];

    cudaFuncSetAttribute(k_be, cudaFuncAttributeMaxDynamicSharedMemorySize, BE_SMEM);

    k_wsplit<<<512, 256>>>(diffW, boutW);
    k_embed<<<NN_N, DD>>>(nf, amds, embW, embb, bembW, bembb, ln1g, ln1b);
    k_biasinit<<<NPAIR*DD/512, 512>>>();

    float scale = 1.f / sqrtf((float)HD);
    for (int l = 0; l < LAYERS; l++){
        k_qkv<<<NN_N/8, 512>>>(qkvW + (long)l*DD*3*HHD, qkvb + l*3*HHD);
        k_be<<<NBLK, 256, BE_SMEM>>>(l, diffb + (long)l*HHD, boutb + (long)l*DD,
                                     l & 1, (l < LAYERS-1) ? 1 : 0);
        k_attn<<<dim3(NN_N/16, HH), 512>>>(scale);
        k_oln<<<NN_N, DD>>>(oW + (long)l*HHD*DD, ob + l*DD, ln2g, ln2b);
    }
    k_out<<<1, NN_N>>>(outW, outb, (float*)d_out);
}

// round 6
// speedup vs baseline: 2.0563x; 1.1490x over previous
#include <cuda_runtime.h>
#include <cuda_fp16.h>
#include <math.h>
#include <stdint.h>

#define NN_N   512
#define FB     256
#define DD     64
#define HH     4
#define HD     128
#define HHD    512
#define LAYERS 4
#define KDIM   100
#define NPAIR  (NN_N*NN_N)
#define EPSV   1e-5f
#define ROWS   128
#define NBLK   (NPAIR/ROWS)      /* 2048 */
#define PADK   72                /* halves per smem row (conflict-free) */

// ---------------- device scratch ----------------
__device__ float g_bias0[NPAIR*DD];   // row-major [pair][64]
__device__ float g_bias1[NPAIR*DD];
__device__ float g_diffs[HH*NPAIR];
__device__ float g_x[NN_N*DD];
__device__ float g_b0[NN_N*DD];
__device__ float g_qkv[NN_N*3*HHD];
__device__ float g_vals[NN_N*HHD];
// combined weight images: [l][chunk][plane(4: w1h,w1l,w2h,w2l)][64 n][72 k] halves
__device__ __align__(16) __half g_wimg[LAYERS*8*4*64*PADK];

// ---------------- helpers ----------------
__device__ __forceinline__ uint32_t smem_u32(const void* p){
    uint32_t a; asm("{ .reg .u64 t; cvta.to.shared.u64 t, %1; cvt.u32.u64 %0, t; }" : "=r"(a) : "l"(p));
    return a;
}
__device__ __forceinline__ float mish2(float x){
    float u = __expf(x);
    float t = fmaf(u, u, 2.f*u);
    return x * (1.f - __fdividef(2.f, t + 2.f));
}
__device__ __forceinline__ void mma16816(float (&d)[4], const uint32_t* a, const uint32_t* b){
    asm volatile("mma.sync.aligned.m16n8k16.row.col.f32.f16.f16.f32 "
        "{%0,%1,%2,%3}, {%4,%5,%6,%7}, {%8,%9}, {%0,%1,%2,%3};"
        : "+f"(d[0]), "+f"(d[1]), "+f"(d[2]), "+f"(d[3])
        : "r"(a[0]), "r"(a[1]), "r"(a[2]), "r"(a[3]), "r"(b[0]), "r"(b[1]));
}
#define LDSM4(R, addr) \
    asm volatile("ldmatrix.sync.aligned.m8n8.x4.shared.b16 {%0,%1,%2,%3}, [%4];" \
        : "=r"((R)[0]), "=r"((R)[1]), "=r"((R)[2]), "=r"((R)[3]) : "r"(addr))
__device__ __forceinline__ void cp16(uint32_t dst, const void* src){
    asm volatile("cp.async.ca.shared.global [%0], [%1], 16;" :: "r"(dst), "l"(src));
}
#define CP_COMMIT() asm volatile("cp.async.commit_group;" ::: "memory")
#define CP_WAIT0()  asm volatile("cp.async.wait_group 0;" ::: "memory")

// fp16-split 3-product GEMM with ldmatrix fragment loads.
// A: [128][PADK] hi/lo planes (rows = output rows). B: [64 n][PADK] hi/lo planes.
__device__ __forceinline__ void mma_gemm_ld(uint32_t sAh, uint32_t sAl,
                                            uint32_t sBh, uint32_t sBl,
                                            float (&d)[2][4][4],
                                            int lane, int wrow, int wcol){
    int lrow = lane & 7, seg = lane >> 3;
    int rsel = (seg & 1) << 3;      // +8 rows for segments 1,3
    int csel = (seg & 2) << 2;      // +8 half-cols for segments 2,3
    #pragma unroll
    for (int k0 = 0; k0 < 64; k0 += 16){
        uint32_t ah[2][4], al[2][4], bh[2][4], bl[2][4];
        #pragma unroll
        for (int ma = 0; ma < 2; ma++){
            int r = wrow*32 + ma*16 + lrow + rsel;
            uint32_t off = (uint32_t)((r*PADK + k0 + csel) * 2);
            LDSM4(ah[ma], sAh + off);
            LDSM4(al[ma], sAl + off);
        }
        #pragma unroll
        for (int nb = 0; nb < 2; nb++){
            int n = wcol*32 + nb*16 + lrow + rsel;
            uint32_t off = (uint32_t)((n*PADK + k0 + csel) * 2);
            LDSM4(bh[nb], sBh + off);
            LDSM4(bl[nb], sBl + off);
        }
        #pragma unroll
        for (int ma = 0; ma < 2; ma++)
            #pragma unroll
            for (int nb = 0; nb < 2; nb++)
                #pragma unroll
                for (int j = 0; j < 2; j++){
                    int na = nb*2 + j;
                    uint32_t Bh[2] = { bh[nb][j], bh[nb][2+j] };
                    uint32_t Bl[2] = { bl[nb][j], bl[nb][2+j] };
                    mma16816(d[ma][na], ah[ma], Bh);
                    mma16816(d[ma][na], ah[ma], Bl);
                    mma16816(d[ma][na], al[ma], Bh);
                }
    }
}

// ---------------- K0: weight split into combined images ----------------
__global__ void k_wsplit(const float* __restrict__ dW, const float* __restrict__ bW){
    int idx = blockIdx.x*256 + threadIdx.x;     // 4*8*64*64 = 131072
    int k = idx & 63;
    int n = (idx>>6) & 63;
    int c = (idx>>12) & 7;
    int l = idx>>15;
    long base = ((long)(l*8 + c)*4)*64*PADK;
    long e = (long)n*PADK + k;
    float v1 = dW[(long)l*DD*HHD + (long)k*HHD + c*64 + n];   // W1^T[n][k]
    __half h1 = __float2half_rn(v1);
    g_wimg[base + e] = h1;
    g_wimg[base + 64*PADK + e] = __float2half_rn(v1 - __half2float(h1));
    float v2 = bW[(long)l*HHD*DD + (long)(c*64 + k)*DD + n];  // W2^T[n][j=c*64+k]
    __half h2 = __float2half_rn(v2);
    g_wimg[base + 2*64*PADK + e] = h2;
    g_wimg[base + 3*64*PADK + e] = __float2half_rn(v2 - __half2float(h2));
}

// ---------------- K1: embeddings + LN1 ----------------
__global__ void k_embed(const float* __restrict__ nf, const float* __restrict__ am,
                        const float* __restrict__ eW, const float* __restrict__ eb,
                        const float* __restrict__ bW, const float* __restrict__ bbv,
                        const float* __restrict__ g1, const float* __restrict__ b1){
    int n = blockIdx.x, d = threadIdx.x;
    float acc = eb[d];
    for (int f = 0; f < FB; f++) acc += nf[n*FB + f] * eW[f*DD + d];
    float b0 = bbv[d];
    for (int k = 0; k < KDIM; k++) b0 += am[n*KDIM + k] * bW[k*DD + d];
    g_b0[n*DD + d] = b0;
    __shared__ float s[DD];
    s[d] = acc; __syncthreads();
    float mu = 0.f;
    #pragma unroll
    for (int k = 0; k < DD; k++) mu += s[k];
    mu *= (1.f/DD);
    float var = 0.f;
    #pragma unroll
    for (int k = 0; k < DD; k++){ float dd = s[k]-mu; var += dd*dd; }
    var *= (1.f/DD);
    g_x[n*DD + d] = (acc - mu) * rsqrtf(var + EPSV) * g1[d] + b1[d];
}

// ---------------- K2: bias init ----------------
__global__ void k_biasinit(){
    long idx = (long)blockIdx.x * blockDim.x + threadIdx.x;
    int d = (int)(idx & 63);
    long pair = idx >> 6;
    int m = (int)(pair & 511);
    int n = (int)(pair >> 9);
    g_bias0[idx] = g_b0[m*DD + d] - g_b0[n*DD + d];
}

// ---------------- K3: qkv ----------------
__global__ void __launch_bounds__(512,1)
k_qkv(const float* __restrict__ W, const float* __restrict__ b){
    int n0 = blockIdx.x * 8;
    __shared__ float xs[8*DD];
    int t = threadIdx.x;
    xs[t] = g_x[n0*DD + t];
    __syncthreads();
    for (int j = t; j < 3*HHD; j += 512){
        float acc[8];
        float bv = b[j];
        #pragma unroll
        for (int r = 0; r < 8; r++) acc[r] = bv;
        #pragma unroll 8
        for (int d = 0; d < DD; d++){
            float w = W[d*(3*HHD) + j];
            #pragma unroll
            for (int r = 0; r < 8; r++) acc[r] += xs[r*DD + d] * w;
        }
        #pragma unroll
        for (int r = 0; r < 8; r++) g_qkv[(long)(n0+r)*(3*HHD) + j] = acc[r];
    }
}

// ---------------- K4: HMMA + ldmatrix + cp.async fused be kernel ----------------
// smem bytes: A hi/lo [128][72]h, E hi/lo [128][72]h, 2 W buffers (4 planes each), sq
#define SA_H   0
#define SA_L   18432
#define SE_H   36864
#define SE_L   55296
#define SW     73728          /* two 36864B buffers */
#define WBUF   36864
#define WPLANE 9216           /* 64*72 halves */
#define SQ_OFF 147456
#define BE_SMEM (147456 + 512)

__global__ void __launch_bounds__(256,1)
k_be(int l, const float* __restrict__ db, const float* __restrict__ bb,
     int flip, int writeBias){
    extern __shared__ __half smh[];
    float* sq = (float*)((char*)smh + SQ_OFF);
    uint32_t sbase = smem_u32(smh);
    int t = threadIdx.x, w = t>>5, lane = t&31;
    int wrow = w>>1, wcol = w&1;
    int q = lane>>2, qt = lane&3;
    long blk = blockIdx.x;
    long pair0 = blk * ROWS;

    const float* bin  = (flip ? g_bias1 : g_bias0) + pair0*DD;
    float*       bnew = (flip ? g_bias0 : g_bias1) + pair0*DD;

    // prefetch chunk 0 weights (async), then convert bias tile while it flies
    {
        const char* src = (const char*)(g_wimg + ((long)(l*8 + 0))*4*64*PADK);
        uint32_t dst = sbase + SW;
        for (int i = t; i < 2304; i += 256) cp16(dst + i*16, src + i*16);
        CP_COMMIT();
    }
    for (int i = t; i < 2048; i += 256){       // 2048 float4 = 128x64
        int r = i >> 4, c4 = (i & 15)*4;
        float4 v = ((const float4*)bin)[i];
        __half2 h0 = __floats2half2_rn(v.x, v.y);
        __half2 h1 = __floats2half2_rn(v.z, v.w);
        float2 f0 = __half22float2(h0);
        float2 f1 = __half22float2(h1);
        __half2 l0 = __floats2half2_rn(v.x - f0.x, v.y - f0.y);
        __half2 l1 = __floats2half2_rn(v.z - f1.x, v.w - f1.y);
        __half2* dh = (__half2*)((char*)smh + SA_H + (r*PADK + c4)*2);
        __half2* dl = (__half2*)((char*)smh + SA_L + (r*PADK + c4)*2);
        dh[0] = h0; dh[1] = h1;
        dl[0] = l0; dl[1] = l1;
    }
    if (t < 128) sq[t] = 0.f;

    float acc2[2][4][4];
    #pragma unroll
    for (int ma = 0; ma < 2; ma++)
        #pragma unroll
        for (int na = 0; na < 4; na++)
            #pragma unroll
            for (int i = 0; i < 4; i++) acc2[ma][na][i] = 0.f;

    for (int c = 0; c < 8; c++){
        CP_WAIT0();
        __syncthreads();                        // chunk c weights + A/E planes ready
        uint32_t wbuf = sbase + SW + (uint32_t)(c & 1)*WBUF;
        if (c < 7){                             // prefetch next chunk into alt buffer
            const char* src = (const char*)(g_wimg + ((long)(l*8 + c + 1))*4*64*PADK);
            uint32_t dst = sbase + SW + (uint32_t)((c+1) & 1)*WBUF;
            for (int i = t; i < 2304; i += 256) cp16(dst + i*16, src + i*16);
            CP_COMMIT();
        }

        // GEMM1: d1 = biasA @ W1_c^T
        float d1[2][4][4];
        #pragma unroll
        for (int ma = 0; ma < 2; ma++)
            #pragma unroll
            for (int na = 0; na < 4; na++)
                #pragma unroll
                for (int i = 0; i < 4; i++) d1[ma][na][i] = 0.f;
        mma_gemm_ld(sbase + SA_H, sbase + SA_L, wbuf, wbuf + WPLANE,
                    d1, lane, wrow, wcol);

        // epilogue: +db, mish, sq partials, split -> E planes
        float dbv[8];
        #pragma unroll
        for (int na = 0; na < 4; na++){
            int colp = wcol*32 + na*8 + qt*2;
            dbv[2*na]   = __ldg(&db[c*64 + colp]);
            dbv[2*na+1] = __ldg(&db[c*64 + colp + 1]);
        }
        float rs[2][2] = {{0.f,0.f},{0.f,0.f}};
        #pragma unroll
        for (int ma = 0; ma < 2; ma++){
            int row0 = wrow*32 + ma*16 + q;
            #pragma unroll
            for (int na = 0; na < 4; na++){
                int colp = wcol*32 + na*8 + qt*2;
                float m0 = mish2(d1[ma][na][0] + dbv[2*na]);
                float m1 = mish2(d1[ma][na][1] + dbv[2*na+1]);
                float m2 = mish2(d1[ma][na][2] + dbv[2*na]);
                float m3 = mish2(d1[ma][na][3] + dbv[2*na+1]);
                rs[ma][0] = fmaf(m0,m0, fmaf(m1,m1, rs[ma][0]));
                rs[ma][1] = fmaf(m2,m2, fmaf(m3,m3, rs[ma][1]));
                __half2 h01 = __floats2half2_rn(m0, m1);
                __half2 h23 = __floats2half2_rn(m2, m3);
                float2 f01 = __half22float2(h01);
                float2 f23 = __half22float2(h23);
                __half2 l01 = __floats2half2_rn(m0 - f01.x, m1 - f01.y);
                __half2 l23 = __floats2half2_rn(m2 - f23.x, m3 - f23.y);
                *(__half2*)((char*)smh + SE_H + (row0*PADK + colp)*2)     = h01;
                *(__half2*)((char*)smh + SE_L + (row0*PADK + colp)*2)     = l01;
                *(__half2*)((char*)smh + SE_H + ((row0+8)*PADK + colp)*2) = h23;
                *(__half2*)((char*)smh + SE_L + ((row0+8)*PADK + colp)*2) = l23;
            }
        }
        #pragma unroll
        for (int ma = 0; ma < 2; ma++)
            #pragma unroll
            for (int hh = 0; hh < 2; hh++){
                float s = rs[ma][hh];
                s += __shfl_xor_sync(0xffffffffu, s, 1);
                s += __shfl_xor_sync(0xffffffffu, s, 2);
                if (qt == 0) atomicAdd(&sq[wrow*32 + ma*16 + q + hh*8], s);
            }
        __syncthreads();
        if (c & 1){
            if (t < 128){
                g_diffs[(long)(c>>1)*NPAIR + pair0 + t] = sqrtf(sq[t]);
                sq[t] = 0.f;
            }
        }
        // GEMM2: acc2 += E @ W2_c^T  (accumulate across chunks)
        if (writeBias)
            mma_gemm_ld(sbase + SE_H, sbase + SE_L, wbuf + 2*WPLANE, wbuf + 3*WPLANE,
                        acc2, lane, wrow, wcol);
    }

    // final: bias' = mish(acc2 + bb)
    if (writeBias){
        #pragma unroll
        for (int ma = 0; ma < 2; ma++){
            #pragma unroll
            for (int na = 0; na < 4; na++){
                int colp = wcol*32 + na*8 + qt*2;
                float bb0 = __ldg(&bb[colp]);
                float bb1 = __ldg(&bb[colp + 1]);
                int row0 = wrow*32 + ma*16 + q;
                float2 v0 = { mish2(acc2[ma][na][0] + bb0), mish2(acc2[ma][na][1] + bb1) };
                float2 v1 = { mish2(acc2[ma][na][2] + bb0), mish2(acc2[ma][na][3] + bb1) };
                *(float2*)&bnew[(long)row0*DD + colp]     = v0;
                *(float2*)&bnew[(long)(row0+8)*DD + colp] = v1;
            }
        }
    }
}

// ---------------- K5: attention ----------------
__global__ void __launch_bounds__(512,1) k_attn(float scale){
    int h  = blockIdx.y;
    int n0 = blockIdx.x * 16;
    __shared__ float qS[16*HD];
    __shared__ float lg[16*NN_N];
    int t = threadIdx.x;

    for (int idx = t; idx < 16*HD; idx += 512){
        int nn = idx >> 7, d = idx & 127;
        qS[idx] = g_qkv[(long)(n0+nn)*(3*HHD) + h*384 + d];
    }
    __syncthreads();
    {
        int m = t;
        float acc[16];
        #pragma unroll
        for (int nn = 0; nn < 16; nn++) acc[nn] = 0.f;
        const float* kp = g_qkv + (long)m*(3*HHD) + h*384 + 128;
        #pragma unroll 4
        for (int d = 0; d < HD; d += 4){
            float4 kv = *(const float4*)(kp + d);
            #pragma unroll
            for (int nn = 0; nn < 16; nn++){
                float4 qv = *(const float4*)&qS[nn*HD + d];
                acc[nn] += qv.x*kv.x + qv.y*kv.y + qv.z*kv.z + qv.w*kv.w;
            }
        }
        const float* dp = g_diffs + (long)h*NPAIR + (long)n0*NN_N + m;
        #pragma unroll
        for (int nn = 0; nn < 16; nn++)
            lg[nn*NN_N + m] = acc[nn]*scale + dp[(long)nn*NN_N];
    }
    __syncthreads();
    {
        int row = t >> 5, lane = t & 31;
        float* Lr = lg + row*NN_N;
        float mx = -1e30f;
        for (int m = lane; m < NN_N; m += 32) mx = fmaxf(mx, Lr[m]);
        #pragma unroll
        for (int o = 16; o; o >>= 1) mx = fmaxf(mx, __shfl_xor_sync(0xffffffffu, mx, o));
        float sum = 0.f;
        for (int m = lane; m < NN_N; m += 32){
            float e = __expf(Lr[m] - mx); Lr[m] = e; sum += e;
        }
        #pragma unroll
        for (int o = 16; o; o >>= 1) sum += __shfl_xor_sync(0xffffffffu, sum, o);
        float inv = 1.f / sum;
        for (int m = lane; m < NN_N; m += 32) Lr[m] *= inv;
    }
    __syncthreads();
    {
        int d = t & 127, ng = t >> 7;
        float acc[4] = {0.f, 0.f, 0.f, 0.f};
        const float* vp = g_qkv + h*384 + 256 + d;
        #pragma unroll 4
        for (int m = 0; m < NN_N; m++){
            float vv = vp[(long)m*(3*HHD)];
            #pragma unroll
            for (int k = 0; k < 4; k++) acc[k] += lg[(ng*4+k)*NN_N + m] * vv;
        }
        #pragma unroll
        for (int k = 0; k < 4; k++)
            g_vals[(long)(n0 + ng*4 + k)*HHD + h*HD + d] = acc[k];
    }
}

// ---------------- K5b: x = LN2(x + vals @ o_W + o_b) ----------------
__global__ void k_oln(const float* __restrict__ oW, const float* __restrict__ ob,
                      const float* __restrict__ g2, const float* __restrict__ b2){
    int n = blockIdx.x, i = threadIdx.x;
    const float* vr = g_vals + (long)n*HHD;
    float a0 = 0.f, a1 = 0.f;
    #pragma unroll 4
    for (int j = 0; j < HHD; j += 2){
        a0 += vr[j]   * oW[j*DD + i];
        a1 += vr[j+1] * oW[(j+1)*DD + i];
    }
    float xv = g_x[n*DD + i] + a0 + a1 + ob[i];
    __shared__ float s[DD];
    s[i] = xv; __syncthreads();
    float mu = 0.f;
    #pragma unroll
    for (int k = 0; k < DD; k++) mu += s[k];
    mu *= (1.f/DD);
    float var = 0.f;
    #pragma unroll
    for (int k = 0; k < DD; k++){ float dd = s[k]-mu; var += dd*dd; }
    var *= (1.f/DD);
    g_x[n*DD + i] = (xv - mu) * rsqrtf(var + EPSV) * g2[i] + b2[i];
}

// ---------------- K6 ----------------
__global__ void k_out(const float* __restrict__ W, const float* __restrict__ bo,
                      float* __restrict__ out){
    int n = threadIdx.x;
    float acc = bo[0];
    #pragma unroll
    for (int d = 0; d < DD; d++) acc += g_x[n*DD + d] * W[d];
    out[n] = acc;
}

// ---------------- launcher ----------------
extern "C" void kernel_launch(void* const* d_in, const int* in_sizes, int n_in,
                              void* d_out, int out_size){
    const float* nf    = (const float*)d_in[0];
    const float* amds  = (const float*)d_in[1];
    const float* embW  = (const float*)d_in[2];
    const float* embb  = (const float*)d_in[3];
    const float* bembW = (const float*)d_in[4];
    const float* bembb = (const float*)d_in[5];
    const float* ln1g  = (const float*)d_in[6];
    const float* ln1b  = (const float*)d_in[7];
    const float* ln2g  = (const float*)d_in[8];
    const float* ln2b  = (const float*)d_in[9];
    const float* qkvW  = (const float*)d_in[10];
    const float* qkvb  = (const float*)d_in[11];
    const float* diffW = (const float*)d_in[12];
    const float* diffb = (const float*)d_in[13];
    const float* oW    = (const float*)d_in[14];
    const float* ob    = (const float*)d_in[15];
    const float* boutW = (const float*)d_in[16];
    const float* boutb = (const float*)d_in[17];
    const float* outW  = (const float*)d_in[18];
    const float* outb  = (const float*)d_in[19];

    cudaFuncSetAttribute(k_be, cudaFuncAttributeMaxDynamicSharedMemorySize, BE_SMEM);

    k_wsplit<<<512, 256>>>(diffW, boutW);
    k_embed<<<NN_N, DD>>>(nf, amds, embW, embb, bembW, bembb, ln1g, ln1b);
    k_biasinit<<<NPAIR*DD/512, 512>>>();

    float scale = 1.f / sqrtf((float)HD);
    for (int l = 0; l < LAYERS; l++){
        k_qkv<<<NN_N/8, 512>>>(qkvW + (long)l*DD*3*HHD, qkvb + l*3*HHD);
        k_be<<<NBLK, 256, BE_SMEM>>>(l, diffb + (long)l*HHD, boutb + (long)l*DD,
                                     l & 1, (l < LAYERS-1) ? 1 : 0);
        k_attn<<<dim3(NN_N/16, HH), 512>>>(scale);
        k_oln<<<NN_N, DD>>>(oW + (long)l*HHD*DD, ob + l*DD, ln2g, ln2b);
    }
    k_out<<<1, NN_N>>>(outW, outb, (float*)d_out);
}

// round 7
// speedup vs baseline: 2.4188x; 1.1763x over previous
#include <cuda_runtime.h>
#include <cuda_fp16.h>
#include <math.h>
#include <stdint.h>

#define NN_N   512
#define FB     256
#define DD     64
#define HH     4
#define HD     128
#define HHD    512
#define LAYERS 4
#define KDIM   100
#define NPAIR  (NN_N*NN_N)
#define EPSV   1e-5f
#define ROWS   128
#define NBLK   (NPAIR/ROWS)      /* 2048 */
#define PADK   72                /* halves per smem row (conflict-free) */

// ---------------- device scratch ----------------
__device__ float g_bias0[NPAIR*DD];   // row-major [pair][64]
__device__ float g_bias1[NPAIR*DD];
__device__ float g_diffs[HH*NPAIR];
__device__ float g_x[NN_N*DD];
__device__ float g_b0[NN_N*DD];
__device__ float g_qkv[NN_N*3*HHD];
__device__ float g_vals[NN_N*HHD];
// combined weight images: [l][chunk][plane(4: w1h,w1l,w2h,w2l)][64 n][72 k] halves
__device__ __align__(16) __half g_wimg[LAYERS*8*4*64*PADK];

// ---------------- helpers ----------------
__device__ __forceinline__ uint32_t smem_u32(const void* p){
    uint32_t a; asm("{ .reg .u64 t; cvta.to.shared.u64 t, %1; cvt.u32.u64 %0, t; }" : "=r"(a) : "l"(p));
    return a;
}
__device__ __forceinline__ float mish2(float x){
    float u = __expf(x);
    float t = fmaf(u, u, 2.f*u);
    return x * (1.f - __fdividef(2.f, t + 2.f));
}
__device__ __forceinline__ void mma16816(float (&d)[4], const uint32_t* a, const uint32_t* b){
    asm volatile("mma.sync.aligned.m16n8k16.row.col.f32.f16.f16.f32 "
        "{%0,%1,%2,%3}, {%4,%5,%6,%7}, {%8,%9}, {%0,%1,%2,%3};"
        : "+f"(d[0]), "+f"(d[1]), "+f"(d[2]), "+f"(d[3])
        : "r"(a[0]), "r"(a[1]), "r"(a[2]), "r"(a[3]), "r"(b[0]), "r"(b[1]));
}
#define LDSM4(R, addr) \
    asm volatile("ldmatrix.sync.aligned.m8n8.x4.shared.b16 {%0,%1,%2,%3}, [%4];" \
        : "=r"((R)[0]), "=r"((R)[1]), "=r"((R)[2]), "=r"((R)[3]) : "r"(addr))
__device__ __forceinline__ void cp16(uint32_t dst, const void* src){
    asm volatile("cp.async.ca.shared.global [%0], [%1], 16;" :: "r"(dst), "l"(src));
}
#define CP_COMMIT() asm volatile("cp.async.commit_group;" ::: "memory")
#define CP_WAIT1()  asm volatile("cp.async.wait_group 1;" ::: "memory")

// fp16-split 3-product GEMM with ldmatrix fragment loads.
__device__ __forceinline__ void mma_gemm_ld(uint32_t sAh, uint32_t sAl,
                                            uint32_t sBh, uint32_t sBl,
                                            float (&d)[2][4][4],
                                            int lane, int wrow, int wcol){
    int lrow = lane & 7, seg = lane >> 3;
    int rsel = (seg & 1) << 3;
    int csel = (seg & 2) << 2;
    #pragma unroll
    for (int k0 = 0; k0 < 64; k0 += 16){
        uint32_t ah[2][4], al[2][4], bh[2][4], bl[2][4];
        #pragma unroll
        for (int ma = 0; ma < 2; ma++){
            int r = wrow*32 + ma*16 + lrow + rsel;
            uint32_t off = (uint32_t)((r*PADK + k0 + csel) * 2);
            LDSM4(ah[ma], sAh + off);
            LDSM4(al[ma], sAl + off);
        }
        #pragma unroll
        for (int nb = 0; nb < 2; nb++){
            int n = wcol*32 + nb*16 + lrow + rsel;
            uint32_t off = (uint32_t)((n*PADK + k0 + csel) * 2);
            LDSM4(bh[nb], sBh + off);
            LDSM4(bl[nb], sBl + off);
        }
        #pragma unroll
        for (int ma = 0; ma < 2; ma++)
            #pragma unroll
            for (int nb = 0; nb < 2; nb++)
                #pragma unroll
                for (int j = 0; j < 2; j++){
                    int na = nb*2 + j;
                    uint32_t Bh[2] = { bh[nb][j], bh[nb][2+j] };
                    uint32_t Bl[2] = { bl[nb][j], bl[nb][2+j] };
                    mma16816(d[ma][na], ah[ma], Bh);
                    mma16816(d[ma][na], ah[ma], Bl);
                    mma16816(d[ma][na], al[ma], Bh);
                }
    }
}

// ---------------- K0: weight split into combined images ----------------
__global__ void k_wsplit(const float* __restrict__ dW, const float* __restrict__ bW){
    int idx = blockIdx.x*256 + threadIdx.x;     // 131072
    int k = idx & 63;
    int n = (idx>>6) & 63;
    int c = (idx>>12) & 7;
    int l = idx>>15;
    long base = ((long)(l*8 + c)*4)*64*PADK;
    long e = (long)n*PADK + k;
    float v1 = dW[(long)l*DD*HHD + (long)k*HHD + c*64 + n];   // W1^T[n][k]
    __half h1 = __float2half_rn(v1);
    g_wimg[base + e] = h1;
    g_wimg[base + 64*PADK + e] = __float2half_rn(v1 - __half2float(h1));
    float v2 = bW[(long)l*HHD*DD + (long)(c*64 + k)*DD + n];  // W2^T[n][j]
    __half h2 = __float2half_rn(v2);
    g_wimg[base + 2*64*PADK + e] = h2;
    g_wimg[base + 3*64*PADK + e] = __float2half_rn(v2 - __half2float(h2));
}

// ---------------- K1: embeddings + LN1 ----------------
__global__ void k_embed(const float* __restrict__ nf, const float* __restrict__ am,
                        const float* __restrict__ eW, const float* __restrict__ eb,
                        const float* __restrict__ bW, const float* __restrict__ bbv,
                        const float* __restrict__ g1, const float* __restrict__ b1){
    int n = blockIdx.x, d = threadIdx.x;
    float acc = eb[d];
    for (int f = 0; f < FB; f++) acc += nf[n*FB + f] * eW[f*DD + d];
    float b0 = bbv[d];
    for (int k = 0; k < KDIM; k++) b0 += am[n*KDIM + k] * bW[k*DD + d];
    g_b0[n*DD + d] = b0;
    __shared__ float s[DD];
    s[d] = acc; __syncthreads();
    float mu = 0.f;
    #pragma unroll
    for (int k = 0; k < DD; k++) mu += s[k];
    mu *= (1.f/DD);
    float var = 0.f;
    #pragma unroll
    for (int k = 0; k < DD; k++){ float dd = s[k]-mu; var += dd*dd; }
    var *= (1.f/DD);
    g_x[n*DD + d] = (acc - mu) * rsqrtf(var + EPSV) * g1[d] + b1[d];
}

// ---------------- K2: bias init ----------------
__global__ void k_biasinit(){
    long idx = (long)blockIdx.x * blockDim.x + threadIdx.x;
    int d = (int)(idx & 63);
    long pair = idx >> 6;
    int m = (int)(pair & 511);
    int n = (int)(pair >> 9);
    g_bias0[idx] = g_b0[m*DD + d] - g_b0[n*DD + d];
}

// ---------------- K3: qkv ----------------
__global__ void __launch_bounds__(512,1)
k_qkv(const float* __restrict__ W, const float* __restrict__ b){
    int n0 = blockIdx.x * 8;
    __shared__ float xs[8*DD];
    int t = threadIdx.x;
    xs[t] = g_x[n0*DD + t];
    __syncthreads();
    for (int j = t; j < 3*HHD; j += 512){
        float acc[8];
        float bv = b[j];
        #pragma unroll
        for (int r = 0; r < 8; r++) acc[r] = bv;
        #pragma unroll 8
        for (int d = 0; d < DD; d++){
            float w = W[d*(3*HHD) + j];
            #pragma unroll
            for (int r = 0; r < 8; r++) acc[r] += xs[r*DD + d] * w;
        }
        #pragma unroll
        for (int r = 0; r < 8; r++) g_qkv[(long)(n0+r)*(3*HHD) + j] = acc[r];
    }
}

// ---------------- K4: HMMA fused be kernel, 2 CTAs/SM ----------------
// smem bytes: A hi/lo 36864, E hi/lo 36864, W planes 36864 (w1h,w1l,w2h,w2l), sq 512
#define SA_H    0
#define SA_L    18432
#define SE_H    36864
#define SE_L    55296
#define SW1     73728          /* w1h @ +0, w1l @ +9216 */
#define SW2     92160          /* w2h @ +0, w2l @ +9216 */
#define WPLANE  9216           /* bytes per plane */
#define WCHUNK  36864          /* bytes per (l,chunk) image */
#define SQ_OFF  110592
#define BE_SMEM (110592 + 512)

__global__ void __launch_bounds__(256,2)
k_be(int l, const float* __restrict__ db, const float* __restrict__ bb,
     int flip, int writeBias){
    extern __shared__ __half smh[];
    float* sq = (float*)((char*)smh + SQ_OFF);
    uint32_t sbase = smem_u32(smh);
    int t = threadIdx.x, w = t>>5, lane = t&31;
    int wrow = w>>1, wcol = w&1;
    int q = lane>>2, qt = lane&3;
    long blk = blockIdx.x;
    long pair0 = blk * ROWS;

    const float* bin  = (flip ? g_bias1 : g_bias0) + pair0*DD;
    float*       bnew = (flip ? g_bias0 : g_bias1) + pair0*DD;
    const char*  wsrc = (const char*)g_wimg + (long)(l*8)*WCHUNK;

    // prologue: async-prefetch w1(0) then w2(0), convert bias tile meanwhile
    for (int i = t; i < 1152; i += 256) cp16(sbase + SW1 + i*16, wsrc + i*16);
    CP_COMMIT();
    if (writeBias)
        for (int i = t; i < 1152; i += 256) cp16(sbase + SW2 + i*16, wsrc + 18432 + i*16);
    CP_COMMIT();

    for (int i = t; i < 2048; i += 256){       // 2048 float4 = 128x64
        int r = i >> 4, c4 = (i & 15)*4;
        float4 v = ((const float4*)bin)[i];
        __half2 h0 = __floats2half2_rn(v.x, v.y);
        __half2 h1 = __floats2half2_rn(v.z, v.w);
        float2 f0 = __half22float2(h0);
        float2 f1 = __half22float2(h1);
        __half2 l0 = __floats2half2_rn(v.x - f0.x, v.y - f0.y);
        __half2 l1 = __floats2half2_rn(v.z - f1.x, v.w - f1.y);
        __half2* dh = (__half2*)((char*)smh + SA_H + (r*PADK + c4)*2);
        __half2* dl = (__half2*)((char*)smh + SA_L + (r*PADK + c4)*2);
        dh[0] = h0; dh[1] = h1;
        dl[0] = l0; dl[1] = l1;
    }
    if (t < 128) sq[t] = 0.f;

    float acc2[2][4][4];
    #pragma unroll
    for (int ma = 0; ma < 2; ma++)
        #pragma unroll
        for (int na = 0; na < 4; na++)
            #pragma unroll
            for (int i = 0; i < 4; i++) acc2[ma][na][i] = 0.f;

    for (int c = 0; c < 8; c++){
        CP_WAIT1();                // w1(c) landed (w2(c) may still fly)
        __syncthreads();

        // GEMM1: d1 = biasA @ W1_c^T
        float d1[2][4][4];
        #pragma unroll
        for (int ma = 0; ma < 2; ma++)
            #pragma unroll
            for (int na = 0; na < 4; na++)
                #pragma unroll
                for (int i = 0; i < 4; i++) d1[ma][na][i] = 0.f;
        mma_gemm_ld(sbase + SA_H, sbase + SA_L, sbase + SW1, sbase + SW1 + WPLANE,
                    d1, lane, wrow, wcol);
        __syncthreads();           // all warps done reading w1 planes

        // prefetch w1(c+1) over the epilogue
        if (c < 7)
            for (int i = t; i < 1152; i += 256)
                cp16(sbase + SW1 + i*16, wsrc + (long)(c+1)*WCHUNK + i*16);
        CP_COMMIT();               // always commit (empty on c==7)

        // epilogue: +db, mish, sq partials, split -> E planes
        float dbv[8];
        #pragma unroll
        for (int na = 0; na < 4; na++){
            int colp = wcol*32 + na*8 + qt*2;
            dbv[2*na]   = __ldg(&db[c*64 + colp]);
            dbv[2*na+1] = __ldg(&db[c*64 + colp + 1]);
        }
        float rs[2][2] = {{0.f,0.f},{0.f,0.f}};
        #pragma unroll
        for (int ma = 0; ma < 2; ma++){
            int row0 = wrow*32 + ma*16 + q;
            #pragma unroll
            for (int na = 0; na < 4; na++){
                int colp = wcol*32 + na*8 + qt*2;
                float m0 = mish2(d1[ma][na][0] + dbv[2*na]);
                float m1 = mish2(d1[ma][na][1] + dbv[2*na+1]);
                float m2 = mish2(d1[ma][na][2] + dbv[2*na]);
                float m3 = mish2(d1[ma][na][3] + dbv[2*na+1]);
                rs[ma][0] = fmaf(m0,m0, fmaf(m1,m1, rs[ma][0]));
                rs[ma][1] = fmaf(m2,m2, fmaf(m3,m3, rs[ma][1]));
                __half2 h01 = __floats2half2_rn(m0, m1);
                __half2 h23 = __floats2half2_rn(m2, m3);
                float2 f01 = __half22float2(h01);
                float2 f23 = __half22float2(h23);
                __half2 l01 = __floats2half2_rn(m0 - f01.x, m1 - f01.y);
                __half2 l23 = __floats2half2_rn(m2 - f23.x, m3 - f23.y);
                *(__half2*)((char*)smh + SE_H + (row0*PADK + colp)*2)     = h01;
                *(__half2*)((char*)smh + SE_L + (row0*PADK + colp)*2)     = l01;
                *(__half2*)((char*)smh + SE_H + ((row0+8)*PADK + colp)*2) = h23;
                *(__half2*)((char*)smh + SE_L + ((row0+8)*PADK + colp)*2) = l23;
            }
        }
        #pragma unroll
        for (int ma = 0; ma < 2; ma++)
            #pragma unroll
            for (int hh = 0; hh < 2; hh++){
                float s = rs[ma][hh];
                s += __shfl_xor_sync(0xffffffffu, s, 1);
                s += __shfl_xor_sync(0xffffffffu, s, 2);
                if (qt == 0) atomicAdd(&sq[wrow*32 + ma*16 + q + hh*8], s);
            }

        CP_WAIT1();                // w2(c) landed (w1(c+1) may still fly)
        __syncthreads();           // E planes + sq visible, w2 ready

        // GEMM2: acc2 += E @ W2_c^T
        if (writeBias)
            mma_gemm_ld(sbase + SE_H, sbase + SE_L, sbase + SW2, sbase + SW2 + WPLANE,
                        acc2, lane, wrow, wcol);
        __syncthreads();           // done reading w2 + E

        // prefetch w2(c+1)
        if (c < 7 && writeBias)
            for (int i = t; i < 1152; i += 256)
                cp16(sbase + SW2 + i*16, wsrc + (long)(c+1)*WCHUNK + 18432 + i*16);
        CP_COMMIT();               // always commit

        if (c & 1){
            if (t < 128){
                g_diffs[(long)(c>>1)*NPAIR + pair0 + t] = sqrtf(sq[t]);
                sq[t] = 0.f;
            }
        }
    }

    // final: bias' = mish(acc2 + bb)
    if (writeBias){
        #pragma unroll
        for (int ma = 0; ma < 2; ma++){
            #pragma unroll
            for (int na = 0; na < 4; na++){
                int colp = wcol*32 + na*8 + qt*2;
                float bb0 = __ldg(&bb[colp]);
                float bb1 = __ldg(&bb[colp + 1]);
                int row0 = wrow*32 + ma*16 + q;
                float2 v0 = { mish2(acc2[ma][na][0] + bb0), mish2(acc2[ma][na][1] + bb1) };
                float2 v1 = { mish2(acc2[ma][na][2] + bb0), mish2(acc2[ma][na][3] + bb1) };
                *(float2*)&bnew[(long)row0*DD + colp]     = v0;
                *(float2*)&bnew[(long)(row0+8)*DD + colp] = v1;
            }
        }
    }
}

// ---------------- K5: attention ----------------
__global__ void __launch_bounds__(512,1) k_attn(float scale){
    int h  = blockIdx.y;
    int n0 = blockIdx.x * 16;
    __shared__ float qS[16*HD];
    __shared__ float lg[16*NN_N];
    int t = threadIdx.x;

    for (int idx = t; idx < 16*HD; idx += 512){
        int nn = idx >> 7, d = idx & 127;
        qS[idx] = g_qkv[(long)(n0+nn)*(3*HHD) + h*384 + d];
    }
    __syncthreads();
    {
        int m = t;
        float acc[16];
        #pragma unroll
        for (int nn = 0; nn < 16; nn++) acc[nn] = 0.f;
        const float* kp = g_qkv + (long)m*(3*HHD) + h*384 + 128;
        #pragma unroll 4
        for (int d = 0; d < HD; d += 4){
            float4 kv = *(const float4*)(kp + d);
            #pragma unroll
            for (int nn = 0; nn < 16; nn++){
                float4 qv = *(const float4*)&qS[nn*HD + d];
                acc[nn] += qv.x*kv.x + qv.y*kv.y + qv.z*kv.z + qv.w*kv.w;
            }
        }
        const float* dp = g_diffs + (long)h*NPAIR + (long)n0*NN_N + m;
        #pragma unroll
        for (int nn = 0; nn < 16; nn++)
            lg[nn*NN_N + m] = acc[nn]*scale + dp[(long)nn*NN_N];
    }
    __syncthreads();
    {
        int row = t >> 5, lane = t & 31;
        float* Lr = lg + row*NN_N;
        float mx = -1e30f;
        for (int m = lane; m < NN_N; m += 32) mx = fmaxf(mx, Lr[m]);
        #pragma unroll
        for (int o = 16; o; o >>= 1) mx = fmaxf(mx, __shfl_xor_sync(0xffffffffu, mx, o));
        float sum = 0.f;
        for (int m = lane; m < NN_N; m += 32){
            float e = __expf(Lr[m] - mx); Lr[m] = e; sum += e;
        }
        #pragma unroll
        for (int o = 16; o; o >>= 1) sum += __shfl_xor_sync(0xffffffffu, sum, o);
        float inv = 1.f / sum;
        for (int m = lane; m < NN_N; m += 32) Lr[m] *= inv;
    }
    __syncthreads();
    {
        int d = t & 127, ng = t >> 7;
        float acc[4] = {0.f, 0.f, 0.f, 0.f};
        const float* vp = g_qkv + h*384 + 256 + d;
        #pragma unroll 4
        for (int m = 0; m < NN_N; m++){
            float vv = vp[(long)m*(3*HHD)];
            #pragma unroll
            for (int k = 0; k < 4; k++) acc[k] += lg[(ng*4+k)*NN_N + m] * vv;
        }
        #pragma unroll
        for (int k = 0; k < 4; k++)
            g_vals[(long)(n0 + ng*4 + k)*HHD + h*HD + d] = acc[k];
    }
}

// ---------------- K5b: x = LN2(x + vals @ o_W + o_b), 8 rows/block ----------------
__global__ void __launch_bounds__(512,1)
k_oln(const float* __restrict__ oW, const float* __restrict__ ob,
      const float* __restrict__ g2, const float* __restrict__ b2){
    int n0 = blockIdx.x * 8;           // 64 blocks
    __shared__ float vs[8*HHD];        // 16 KB
    __shared__ float s[8*DD];
    int t = threadIdx.x;
    for (int i = t; i < 8*HHD/4; i += 512)
        ((float4*)vs)[i] = ((const float4*)(g_vals + (long)n0*HHD))[i];
    __syncthreads();
    int r = t >> 6, i = t & 63;
    float acc = 0.f;
    #pragma unroll 8
    for (int j = 0; j < HHD; j++)
        acc += vs[r*HHD + j] * oW[j*DD + i];
    float xv = g_x[(n0+r)*DD + i] + acc + ob[i];
    s[r*DD + i] = xv;
    __syncthreads();
    float mu = 0.f;
    #pragma unroll
    for (int k = 0; k < DD; k++) mu += s[r*DD + k];
    mu *= (1.f/DD);
    float var = 0.f;
    #pragma unroll
    for (int k = 0; k < DD; k++){ float dd = s[r*DD + k]-mu; var += dd*dd; }
    var *= (1.f/DD);
    g_x[(n0+r)*DD + i] = (xv - mu) * rsqrtf(var + EPSV) * g2[i] + b2[i];
}

// ---------------- K6 ----------------
__global__ void k_out(const float* __restrict__ W, const float* __restrict__ bo,
                      float* __restrict__ out){
    int n = threadIdx.x;
    float acc = bo[0];
    #pragma unroll
    for (int d = 0; d < DD; d++) acc += g_x[n*DD + d] * W[d];
    out[n] = acc;
}

// ---------------- launcher ----------------
extern "C" void kernel_launch(void* const* d_in, const int* in_sizes, int n_in,
                              void* d_out, int out_size){
    const float* nf    = (const float*)d_in[0];
    const float* amds  = (const float*)d_in[1];
    const float* embW  = (const float*)d_in[2];
    const float* embb  = (const float*)d_in[3];
    const float* bembW = (const float*)d_in[4];
    const float* bembb = (const float*)d_in[5];
    const float* ln1g  = (const float*)d_in[6];
    const float* ln1b  = (const float*)d_in[7];
    const float* ln2g  = (const float*)d_in[8];
    const float* ln2b  = (const float*)d_in[9];
    const float* qkvW  = (const float*)d_in[10];
    const float* qkvb  = (const float*)d_in[11];
    const float* diffW = (const float*)d_in[12];
    const float* diffb = (const float*)d_in[13];
    const float* oW    = (const float*)d_in[14];
    const float* ob    = (const float*)d_in[15];
    const float* boutW = (const float*)d_in[16];
    const float* boutb = (const float*)d_in[17];
    const float* outW  = (const float*)d_in[18];
    const float* outb  = (const float*)d_in[19];

    cudaFuncSetAttribute(k_be, cudaFuncAttributeMaxDynamicSharedMemorySize, BE_SMEM);

    k_wsplit<<<512, 256>>>(diffW, boutW);
    k_embed<<<NN_N, DD>>>(nf, amds, embW, embb, bembW, bembb, ln1g, ln1b);
    k_biasinit<<<NPAIR*DD/512, 512>>>();

    float scale = 1.f / sqrtf((float)HD);
    for (int l = 0; l < LAYERS; l++){
        k_qkv<<<NN_N/8, 512>>>(qkvW + (long)l*DD*3*HHD, qkvb + l*3*HHD);
        k_be<<<NBLK, 256, BE_SMEM>>>(l, diffb + (long)l*HHD, boutb + (long)l*DD,
                                     l & 1, (l < LAYERS-1) ? 1 : 0);
        k_attn<<<dim3(NN_N/16, HH), 512>>>(scale);
        k_oln<<<NN_N/8, 512>>>(oW + (long)l*HHD*DD, ob + l*DD, ln2g, ln2b);
    }
    k_out<<<1, NN_N>>>(outW, outb, (float*)d_out);
}

// round 8
// speedup vs baseline: 2.6114x; 1.0796x over previous
#include <cuda_runtime.h>
#include <cuda_fp16.h>
#include <math.h>
#include <stdint.h>

#define NN_N   512
#define FB     256
#define DD     64
#define HH     4
#define HD     128
#define HHD    512
#define LAYERS 4
#define KDIM   100
#define NPAIR  (NN_N*NN_N)
#define EPSV   1e-5f
#define ROWS   128
#define NBLK   (NPAIR/ROWS)      /* 2048 */
#define PADK   72                /* halves per smem row (conflict-free) */
#define QPAD   68                /* floats per QT smem row */

// ---------------- device scratch ----------------
__device__ float g_bias0[NPAIR*DD];   // ping (written by layer0, read by layer2... flip logic)
__device__ float g_bias1[NPAIR*DD];   // pong
__device__ float g_diffs[HH*NPAIR];
__device__ float g_x[NN_N*DD];
__device__ float g_b0[NN_N*DD];
__device__ float g_Q[NN_N*HHD];       // Q = b0 @ W1_layer0   [512][512]
__device__ float g_qkv[NN_N*3*HHD];
__device__ float g_vals[NN_N*HHD];
// combined weight images: [l][chunk][plane(4: w1h,w1l,w2h,w2l)][64 n][72 k] halves
__device__ __align__(16) __half g_wimg[LAYERS*8*4*64*PADK];

// ---------------- helpers ----------------
__device__ __forceinline__ uint32_t smem_u32(const void* p){
    uint32_t a; asm("{ .reg .u64 t; cvta.to.shared.u64 t, %1; cvt.u32.u64 %0, t; }" : "=r"(a) : "l"(p));
    return a;
}
__device__ __forceinline__ float mish2(float x){
    float u = __expf(x);
    float t = fmaf(u, u, 2.f*u);
    return x * (1.f - __fdividef(2.f, t + 2.f));
}
__device__ __forceinline__ void mma16816(float (&d)[4], const uint32_t* a, const uint32_t* b){
    asm volatile("mma.sync.aligned.m16n8k16.row.col.f32.f16.f16.f32 "
        "{%0,%1,%2,%3}, {%4,%5,%6,%7}, {%8,%9}, {%0,%1,%2,%3};"
        : "+f"(d[0]), "+f"(d[1]), "+f"(d[2]), "+f"(d[3])
        : "r"(a[0]), "r"(a[1]), "r"(a[2]), "r"(a[3]), "r"(b[0]), "r"(b[1]));
}
#define LDSM4(R, addr) \
    asm volatile("ldmatrix.sync.aligned.m8n8.x4.shared.b16 {%0,%1,%2,%3}, [%4];" \
        : "=r"((R)[0]), "=r"((R)[1]), "=r"((R)[2]), "=r"((R)[3]) : "r"(addr))
__device__ __forceinline__ void cp16(uint32_t dst, const void* src){
    asm volatile("cp.async.ca.shared.global [%0], [%1], 16;" :: "r"(dst), "l"(src));
}
#define CP_COMMIT() asm volatile("cp.async.commit_group;" ::: "memory")
#define CP_WAIT1()  asm volatile("cp.async.wait_group 1;" ::: "memory")

// fp16-split 3-product GEMM with ldmatrix fragment loads.
__device__ __forceinline__ void mma_gemm_ld(uint32_t sAh, uint32_t sAl,
                                            uint32_t sBh, uint32_t sBl,
                                            float (&d)[2][4][4],
                                            int lane, int wrow, int wcol){
    int lrow = lane & 7, seg = lane >> 3;
    int rsel = (seg & 1) << 3;
    int csel = (seg & 2) << 2;
    #pragma unroll
    for (int k0 = 0; k0 < 64; k0 += 16){
        uint32_t ah[2][4], al[2][4], bh[2][4], bl[2][4];
        #pragma unroll
        for (int ma = 0; ma < 2; ma++){
            int r = wrow*32 + ma*16 + lrow + rsel;
            uint32_t off = (uint32_t)((r*PADK + k0 + csel) * 2);
            LDSM4(ah[ma], sAh + off);
            LDSM4(al[ma], sAl + off);
        }
        #pragma unroll
        for (int nb = 0; nb < 2; nb++){
            int n = wcol*32 + nb*16 + lrow + rsel;
            uint32_t off = (uint32_t)((n*PADK + k0 + csel) * 2);
            LDSM4(bh[nb], sBh + off);
            LDSM4(bl[nb], sBl + off);
        }
        #pragma unroll
        for (int ma = 0; ma < 2; ma++)
            #pragma unroll
            for (int nb = 0; nb < 2; nb++)
                #pragma unroll
                for (int j = 0; j < 2; j++){
                    int na = nb*2 + j;
                    uint32_t Bh[2] = { bh[nb][j], bh[nb][2+j] };
                    uint32_t Bl[2] = { bl[nb][j], bl[nb][2+j] };
                    mma16816(d[ma][na], ah[ma], Bh);
                    mma16816(d[ma][na], ah[ma], Bl);
                    mma16816(d[ma][na], al[ma], Bh);
                }
    }
}

// ---------------- K0: weight split into combined images ----------------
__global__ void k_wsplit(const float* __restrict__ dW, const float* __restrict__ bW){
    int idx = blockIdx.x*256 + threadIdx.x;     // 131072
    int k = idx & 63;
    int n = (idx>>6) & 63;
    int c = (idx>>12) & 7;
    int l = idx>>15;
    long base = ((long)(l*8 + c)*4)*64*PADK;
    long e = (long)n*PADK + k;
    float v1 = dW[(long)l*DD*HHD + (long)k*HHD + c*64 + n];   // W1^T[n][k]
    __half h1 = __float2half_rn(v1);
    g_wimg[base + e] = h1;
    g_wimg[base + 64*PADK + e] = __float2half_rn(v1 - __half2float(h1));
    float v2 = bW[(long)l*HHD*DD + (long)(c*64 + k)*DD + n];  // W2^T[n][j]
    __half h2 = __float2half_rn(v2);
    g_wimg[base + 2*64*PADK + e] = h2;
    g_wimg[base + 3*64*PADK + e] = __float2half_rn(v2 - __half2float(h2));
}

// ---------------- K1: embeddings + LN1 ----------------
__global__ void k_embed(const float* __restrict__ nf, const float* __restrict__ am,
                        const float* __restrict__ eW, const float* __restrict__ eb,
                        const float* __restrict__ bW, const float* __restrict__ bbv,
                        const float* __restrict__ g1, const float* __restrict__ b1){
    int n = blockIdx.x, d = threadIdx.x;
    float acc = eb[d];
    for (int f = 0; f < FB; f++) acc += nf[n*FB + f] * eW[f*DD + d];
    float b0 = bbv[d];
    for (int k = 0; k < KDIM; k++) b0 += am[n*KDIM + k] * bW[k*DD + d];
    g_b0[n*DD + d] = b0;
    __shared__ float s[DD];
    s[d] = acc; __syncthreads();
    float mu = 0.f;
    #pragma unroll
    for (int k = 0; k < DD; k++) mu += s[k];
    mu *= (1.f/DD);
    float var = 0.f;
    #pragma unroll
    for (int k = 0; k < DD; k++){ float dd = s[k]-mu; var += dd*dd; }
    var *= (1.f/DD);
    g_x[n*DD + d] = (acc - mu) * rsqrtf(var + EPSV) * g1[d] + b1[d];
}

// ---------------- K2: Q = b0 @ diffW_layer0 ----------------
__global__ void __launch_bounds__(512,1)
k_pq(const float* __restrict__ W){
    int n0 = blockIdx.x * 8;            // 64 blocks
    __shared__ float xs[8*DD];
    int t = threadIdx.x;
    xs[t] = g_b0[n0*DD + t];
    __syncthreads();
    int j = t;                          // 512 cols, one per thread
    float acc[8];
    #pragma unroll
    for (int r = 0; r < 8; r++) acc[r] = 0.f;
    #pragma unroll 8
    for (int d = 0; d < DD; d++){
        float w = W[d*HHD + j];
        #pragma unroll
        for (int r = 0; r < 8; r++) acc[r] += xs[r*DD + d] * w;
    }
    #pragma unroll
    for (int r = 0; r < 8; r++) g_Q[(long)(n0+r)*HHD + j] = acc[r];
}

// ---------------- K3: qkv (layer 0 only; later layers fused into k_oln) ----------------
__global__ void __launch_bounds__(512,1)
k_qkv(const float* __restrict__ W, const float* __restrict__ b){
    int n0 = blockIdx.x * 8;
    __shared__ float xs[8*DD];
    int t = threadIdx.x;
    xs[t] = g_x[n0*DD + t];
    __syncthreads();
    for (int j = t; j < 3*HHD; j += 512){
        float acc[8];
        float bv = b[j];
        #pragma unroll
        for (int r = 0; r < 8; r++) acc[r] = bv;
        #pragma unroll 8
        for (int d = 0; d < DD; d++){
            float w = W[d*(3*HHD) + j];
            #pragma unroll
            for (int r = 0; r < 8; r++) acc[r] += xs[r*DD + d] * w;
        }
        #pragma unroll
        for (int r = 0; r < 8; r++) g_qkv[(long)(n0+r)*(3*HHD) + j] = acc[r];
    }
}

// ---------------- K4: HMMA fused be kernel, 2 CTAs/SM ----------------
// smem bytes: A hi/lo 36864 (or QT 34816 on layer0), E hi/lo 36864, W 36864, sq 512
#define SA_H    0
#define SA_L    18432
#define SE_H    36864
#define SE_L    55296
#define SW1     73728          /* w1h @ +0, w1l @ +9216 */
#define SW2     92160          /* w2h @ +0, w2l @ +9216 */
#define WPLANE  9216
#define WCHUNK  36864
#define SQ_OFF  110592
#define BE_SMEM (110592 + 512)

__global__ void __launch_bounds__(256,2)
k_be(int l, const float* __restrict__ db, const float* __restrict__ bb,
     int flip, int writeBias, int isL0){
    extern __shared__ __half smh[];
    float* sq = (float*)((char*)smh + SQ_OFF);
    float* QT = (float*)smh;                 // layer0: [128][QPAD] f32
    uint32_t sbase = smem_u32(smh);
    int t = threadIdx.x, w = t>>5, lane = t&31;
    int wrow = w>>1, wcol = w&1;
    int q = lane>>2, qt = lane&3;
    long blk = blockIdx.x;
    long pair0 = blk * ROWS;
    int nrow   = (int)(blk >> 2);            // layer0: query index n
    int m_base = (int)(blk & 3) * ROWS;      // layer0: first key index m

    const float* bin  = (flip ? g_bias1 : g_bias0) + pair0*DD;
    float*       bnew = (flip ? g_bias0 : g_bias1) + pair0*DD;
    const char*  wsrc = (const char*)g_wimg + (long)(l*8)*WCHUNK;

    // prologue: group order must be [slotA(0)][w2(0)] then alternating
    if (isL0){
        for (int i = t; i < 2048; i += 256){      // QT chunk0: [128][16 f4]
            int r = i >> 4, f4 = i & 15;
            cp16(sbase + (uint32_t)((r*QPAD + f4*4)*4),
                 g_Q + (long)(m_base + r)*HHD + f4*4);
        }
        CP_COMMIT();
        for (int i = t; i < 1152; i += 256) cp16(sbase + SW2 + i*16, wsrc + 2*WPLANE + i*16);
        CP_COMMIT();
    } else {
        for (int i = t; i < 1152; i += 256) cp16(sbase + SW1 + i*16, wsrc + i*16);
        CP_COMMIT();
        if (writeBias)
            for (int i = t; i < 1152; i += 256) cp16(sbase + SW2 + i*16, wsrc + 2*WPLANE + i*16);
        CP_COMMIT();
        for (int i = t; i < 2048; i += 256){      // bias tile -> A hi/lo planes
            int r = i >> 4, c4 = (i & 15)*4;
            float4 v = ((const float4*)bin)[i];
            __half2 h0 = __floats2half2_rn(v.x, v.y);
            __half2 h1 = __floats2half2_rn(v.z, v.w);
            float2 f0 = __half22float2(h0);
            float2 f1 = __half22float2(h1);
            __half2 l0 = __floats2half2_rn(v.x - f0.x, v.y - f0.y);
            __half2 l1 = __floats2half2_rn(v.z - f1.x, v.w - f1.y);
            __half2* dh = (__half2*)((char*)smh + SA_H + (r*PADK + c4)*2);
            __half2* dl = (__half2*)((char*)smh + SA_L + (r*PADK + c4)*2);
            dh[0] = h0; dh[1] = h1;
            dl[0] = l0; dl[1] = l1;
        }
    }
    if (t < 128) sq[t] = 0.f;

    float acc2[2][4][4];
    #pragma unroll
    for (int ma = 0; ma < 2; ma++)
        #pragma unroll
        for (int na = 0; na < 4; na++)
            #pragma unroll
            for (int i = 0; i < 4; i++) acc2[ma][na][i] = 0.f;

    for (int c = 0; c < 8; c++){
        CP_WAIT1();                // slotA(c) landed (w2(c) may still fly)
        __syncthreads();

        float d1[2][4][4];
        if (isL0){
            // d1 = Q[m][col] - Q[n][col] directly from staged QT + L2-hot qn row
            float qnv[8];
            #pragma unroll
            for (int na = 0; na < 4; na++){
                int colp = wcol*32 + na*8 + qt*2;
                qnv[2*na]   = __ldg(&g_Q[(long)nrow*HHD + c*64 + colp]);
                qnv[2*na+1] = __ldg(&g_Q[(long)nrow*HHD + c*64 + colp + 1]);
            }
            #pragma unroll
            for (int ma = 0; ma < 2; ma++){
                int r0 = wrow*32 + ma*16 + q;
                #pragma unroll
                for (int na = 0; na < 4; na++){
                    int colp = wcol*32 + na*8 + qt*2;
                    d1[ma][na][0] = QT[r0*QPAD + colp]     - qnv[2*na];
                    d1[ma][na][1] = QT[r0*QPAD + colp + 1] - qnv[2*na+1];
                    d1[ma][na][2] = QT[(r0+8)*QPAD + colp]     - qnv[2*na];
                    d1[ma][na][3] = QT[(r0+8)*QPAD + colp + 1] - qnv[2*na+1];
                }
            }
            __syncthreads();       // done reading QT(c)
            if (c < 7)
                for (int i = t; i < 2048; i += 256){
                    int r = i >> 4, f4 = i & 15;
                    cp16(sbase + (uint32_t)((r*QPAD + f4*4)*4),
                         g_Q + (long)(m_base + r)*HHD + (c+1)*64 + f4*4);
                }
            CP_COMMIT();
        } else {
            #pragma unroll
            for (int ma = 0; ma < 2; ma++)
                #pragma unroll
                for (int na = 0; na < 4; na++)
                    #pragma unroll
                    for (int i = 0; i < 4; i++) d1[ma][na][i] = 0.f;
            mma_gemm_ld(sbase + SA_H, sbase + SA_L, sbase + SW1, sbase + SW1 + WPLANE,
                        d1, lane, wrow, wcol);
            __syncthreads();       // done reading w1(c)
            if (c < 7)
                for (int i = t; i < 1152; i += 256)
                    cp16(sbase + SW1 + i*16, wsrc + (long)(c+1)*WCHUNK + i*16);
            CP_COMMIT();
        }

        // epilogue: +db, mish, sq partials, split -> E planes
        float dbv[8];
        #pragma unroll
        for (int na = 0; na < 4; na++){
            int colp = wcol*32 + na*8 + qt*2;
            dbv[2*na]   = __ldg(&db[c*64 + colp]);
            dbv[2*na+1] = __ldg(&db[c*64 + colp + 1]);
        }
        float rs[2][2] = {{0.f,0.f},{0.f,0.f}};
        #pragma unroll
        for (int ma = 0; ma < 2; ma++){
            int row0 = wrow*32 + ma*16 + q;
            #pragma unroll
            for (int na = 0; na < 4; na++){
                int colp = wcol*32 + na*8 + qt*2;
                float m0 = mish2(d1[ma][na][0] + dbv[2*na]);
                float m1 = mish2(d1[ma][na][1] + dbv[2*na+1]);
                float m2 = mish2(d1[ma][na][2] + dbv[2*na]);
                float m3 = mish2(d1[ma][na][3] + dbv[2*na+1]);
                rs[ma][0] = fmaf(m0,m0, fmaf(m1,m1, rs[ma][0]));
                rs[ma][1] = fmaf(m2,m2, fmaf(m3,m3, rs[ma][1]));
                __half2 h01 = __floats2half2_rn(m0, m1);
                __half2 h23 = __floats2half2_rn(m2, m3);
                float2 f01 = __half22float2(h01);
                float2 f23 = __half22float2(h23);
                __half2 l01 = __floats2half2_rn(m0 - f01.x, m1 - f01.y);
                __half2 l23 = __floats2half2_rn(m2 - f23.x, m3 - f23.y);
                *(__half2*)((char*)smh + SE_H + (row0*PADK + colp)*2)     = h01;
                *(__half2*)((char*)smh + SE_L + (row0*PADK + colp)*2)     = l01;
                *(__half2*)((char*)smh + SE_H + ((row0+8)*PADK + colp)*2) = h23;
                *(__half2*)((char*)smh + SE_L + ((row0+8)*PADK + colp)*2) = l23;
            }
        }
        #pragma unroll
        for (int ma = 0; ma < 2; ma++)
            #pragma unroll
            for (int hh = 0; hh < 2; hh++){
                float s = rs[ma][hh];
                s += __shfl_xor_sync(0xffffffffu, s, 1);
                s += __shfl_xor_sync(0xffffffffu, s, 2);
                if (qt == 0) atomicAdd(&sq[wrow*32 + ma*16 + q + hh*8], s);
            }

        CP_WAIT1();                // w2(c) landed (slotA(c+1) may still fly)
        __syncthreads();           // E planes + sq visible, w2 ready

        // GEMM2: acc2 += E @ W2_c^T
        if (writeBias)
            mma_gemm_ld(sbase + SE_H, sbase + SE_L, sbase + SW2, sbase + SW2 + WPLANE,
                        acc2, lane, wrow, wcol);
        __syncthreads();           // done reading w2 + E

        if (c < 7 && writeBias)
            for (int i = t; i < 1152; i += 256)
                cp16(sbase + SW2 + i*16, wsrc + (long)(c+1)*WCHUNK + 2*WPLANE + i*16);
        CP_COMMIT();

        if (c & 1){
            if (t < 128){
                g_diffs[(long)(c>>1)*NPAIR + pair0 + t] = sqrtf(sq[t]);
                sq[t] = 0.f;
            }
        }
    }

    // final: bias' = mish(acc2 + bb)
    if (writeBias){
        #pragma unroll
        for (int ma = 0; ma < 2; ma++){
            #pragma unroll
            for (int na = 0; na < 4; na++){
                int colp = wcol*32 + na*8 + qt*2;
                float bb0 = __ldg(&bb[colp]);
                float bb1 = __ldg(&bb[colp + 1]);
                int row0 = wrow*32 + ma*16 + q;
                float2 v0 = { mish2(acc2[ma][na][0] + bb0), mish2(acc2[ma][na][1] + bb1) };
                float2 v1 = { mish2(acc2[ma][na][2] + bb0), mish2(acc2[ma][na][3] + bb1) };
                *(float2*)&bnew[(long)row0*DD + colp]     = v0;
                *(float2*)&bnew[(long)(row0+8)*DD + colp] = v1;
            }
        }
    }
}

// ---------------- K5: attention ----------------
__global__ void __launch_bounds__(512,1) k_attn(float scale){
    int h  = blockIdx.y;
    int n0 = blockIdx.x * 16;
    __shared__ float qS[16*HD];
    __shared__ float lg[16*NN_N];
    int t = threadIdx.x;

    for (int idx = t; idx < 16*HD; idx += 512){
        int nn = idx >> 7, d = idx & 127;
        qS[idx] = g_qkv[(long)(n0+nn)*(3*HHD) + h*384 + d];
    }
    __syncthreads();
    {
        int m = t;
        float acc[16];
        #pragma unroll
        for (int nn = 0; nn < 16; nn++) acc[nn] = 0.f;
        const float* kp = g_qkv + (long)m*(3*HHD) + h*384 + 128;
        #pragma unroll 4
        for (int d = 0; d < HD; d += 4){
            float4 kv = *(const float4*)(kp + d);
            #pragma unroll
            for (int nn = 0; nn < 16; nn++){
                float4 qv = *(const float4*)&qS[nn*HD + d];
                acc[nn] += qv.x*kv.x + qv.y*kv.y + qv.z*kv.z + qv.w*kv.w;
            }
        }
        const float* dp = g_diffs + (long)h*NPAIR + (long)n0*NN_N + m;
        #pragma unroll
        for (int nn = 0; nn < 16; nn++)
            lg[nn*NN_N + m] = acc[nn]*scale + dp[(long)nn*NN_N];
    }
    __syncthreads();
    {
        int row = t >> 5, lane = t & 31;
        float* Lr = lg + row*NN_N;
        float mx = -1e30f;
        for (int m = lane; m < NN_N; m += 32) mx = fmaxf(mx, Lr[m]);
        #pragma unroll
        for (int o = 16; o; o >>= 1) mx = fmaxf(mx, __shfl_xor_sync(0xffffffffu, mx, o));
        float sum = 0.f;
        for (int m = lane; m < NN_N; m += 32){
            float e = __expf(Lr[m] - mx); Lr[m] = e; sum += e;
        }
        #pragma unroll
        for (int o = 16; o; o >>= 1) sum += __shfl_xor_sync(0xffffffffu, sum, o);
        float inv = 1.f / sum;
        for (int m = lane; m < NN_N; m += 32) Lr[m] *= inv;
    }
    __syncthreads();
    {
        int d = t & 127, ng = t >> 7;
        float acc[4] = {0.f, 0.f, 0.f, 0.f};
        const float* vp = g_qkv + h*384 + 256 + d;
        #pragma unroll 4
        for (int m = 0; m < NN_N; m++){
            float vv = vp[(long)m*(3*HHD)];
            #pragma unroll
            for (int k = 0; k < 4; k++) acc[k] += lg[(ng*4+k)*NN_N + m] * vv;
        }
        #pragma unroll
        for (int k = 0; k < 4; k++)
            g_vals[(long)(n0 + ng*4 + k)*HHD + h*HD + d] = acc[k];
    }
}

// ---------------- K5b: x = LN2(x + vals@oW + ob), + fused next-layer qkv / final out ----------------
__global__ void __launch_bounds__(512,1)
k_oln(const float* __restrict__ oW, const float* __restrict__ ob,
      const float* __restrict__ g2, const float* __restrict__ b2,
      const float* __restrict__ qW, const float* __restrict__ qb, int doQkv,
      const float* __restrict__ outW, const float* __restrict__ outb,
      float* __restrict__ out, int doOut){
    int n0 = blockIdx.x * 8;           // 64 blocks
    __shared__ float vs[8*HHD];        // 16 KB
    __shared__ float s[8*DD];
    int t = threadIdx.x;
    for (int i = t; i < 8*HHD/4; i += 512)
        ((float4*)vs)[i] = ((const float4*)(g_vals + (long)n0*HHD))[i];
    __syncthreads();
    int r = t >> 6, i = t & 63;
    float acc = 0.f;
    #pragma unroll 8
    for (int j = 0; j < HHD; j++)
        acc += vs[r*HHD + j] * oW[j*DD + i];
    float xv = g_x[(n0+r)*DD + i] + acc + ob[i];
    s[r*DD + i] = xv;
    __syncthreads();
    float mu = 0.f;
    #pragma unroll
    for (int k = 0; k < DD; k++) mu += s[r*DD + k];
    mu *= (1.f/DD);
    float var = 0.f;
    #pragma unroll
    for (int k = 0; k < DD; k++){ float dd = s[r*DD + k]-mu; var += dd*dd; }
    var *= (1.f/DD);
    float xn = (xv - mu) * rsqrtf(var + EPSV) * g2[i] + b2[i];
    g_x[(n0+r)*DD + i] = xn;
    __syncthreads();
    s[r*DD + i] = xn;                  // post-LN x for fused consumers
    __syncthreads();
    if (doQkv){
        for (int j = t; j < 3*HHD; j += 512){
            float a2[8];
            float bv = qb[j];
            #pragma unroll
            for (int rr = 0; rr < 8; rr++) a2[rr] = bv;
            #pragma unroll 8
            for (int d = 0; d < DD; d++){
                float w = qW[d*(3*HHD) + j];
                #pragma unroll
                for (int rr = 0; rr < 8; rr++) a2[rr] += s[rr*DD + d] * w;
            }
            #pragma unroll
            for (int rr = 0; rr < 8; rr++) g_qkv[(long)(n0+rr)*(3*HHD) + j] = a2[rr];
        }
    }
    if (doOut && t < 8){
        float a = outb[0];
        #pragma unroll
        for (int d = 0; d < DD; d++) a += s[t*DD + d] * outW[d];
        out[n0 + t] = a;
    }
}

// ---------------- launcher ----------------
extern "C" void kernel_launch(void* const* d_in, const int* in_sizes, int n_in,
                              void* d_out, int out_size){
    const float* nf    = (const float*)d_in[0];
    const float* amds  = (const float*)d_in[1];
    const float* embW  = (const float*)d_in[2];
    const float* embb  = (const float*)d_in[3];
    const float* bembW = (const float*)d_in[4];
    const float* bembb = (const float*)d_in[5];
    const float* ln1g  = (const float*)d_in[6];
    const float* ln1b  = (const float*)d_in[7];
    const float* ln2g  = (const float*)d_in[8];
    const float* ln2b  = (const float*)d_in[9];
    const float* qkvW  = (const float*)d_in[10];
    const float* qkvb  = (const float*)d_in[11];
    const float* diffW = (const float*)d_in[12];
    const float* diffb = (const float*)d_in[13];
    const float* oW    = (const float*)d_in[14];
    const float* ob    = (const float*)d_in[15];
    const float* boutW = (const float*)d_in[16];
    const float* boutb = (const float*)d_in[17];
    const float* outW  = (const float*)d_in[18];
    const float* outb  = (const float*)d_in[19];

    cudaFuncSetAttribute(k_be, cudaFuncAttributeMaxDynamicSharedMemorySize, BE_SMEM);

    k_wsplit<<<512, 256>>>(diffW, boutW);
    k_embed<<<NN_N, DD>>>(nf, amds, embW, embb, bembW, bembb, ln1g, ln1b);
    k_pq<<<NN_N/8, 512>>>(diffW);                         // Q = b0 @ W1_layer0
    k_qkv<<<NN_N/8, 512>>>(qkvW, qkvb);                   // layer-0 qkv

    float scale = 1.f / sqrtf((float)HD);
    for (int l = 0; l < LAYERS; l++){
        k_be<<<NBLK, 256, BE_SMEM>>>(l, diffb + (long)l*HHD, boutb + (long)l*DD,
                                     l & 1, (l < LAYERS-1) ? 1 : 0, (l == 0) ? 1 : 0);
        k_attn<<<dim3(NN_N/16, HH), 512>>>(scale);
        int last = (l == LAYERS-1);
        k_oln<<<NN_N/8, 512>>>(oW + (long)l*HHD*DD, ob + l*DD, ln2g, ln2b,
                               qkvW + (long)(l+1)*DD*3*HHD, qkvb + (long)(l+1)*3*HHD,
                               last ? 0 : 1,
                               outW, outb, (float*)d_out, last);
    }
}

// round 11
// speedup vs baseline: 2.8250x; 1.0818x over previous
#include <cuda_runtime.h>
#include <cuda_fp16.h>
#include <math.h>
#include <stdint.h>

#define NN_N   512
#define FB     256
#define DD     64
#define HH     4
#define HD     128
#define HHD    512
#define LAYERS 4
#define KDIM   100
#define NPAIR  (NN_N*NN_N)
#define EPSV   1e-5f
#define ROWS   128
#define NBLK   (NPAIR/ROWS)      /* 2048 */
#define PADK   72                /* halves per smem row (conflict-free) */
#define QPAD   68                /* floats per QT smem row */

// ---------------- device scratch ----------------
__device__ float g_bias0[NPAIR*DD];
__device__ float g_bias1[NPAIR*DD];
__device__ float g_diffs[2*HH*NPAIR];   // double-buffered by layer parity
__device__ float g_x[NN_N*DD];
__device__ float g_b0[NN_N*DD];
__device__ float g_Q[NN_N*HHD];
__device__ float g_qkv[NN_N*3*HHD];
__device__ float g_vals[NN_N*HHD];
__device__ __align__(16) __half g_wimg[LAYERS*8*4*64*PADK];

// ---------------- helpers ----------------
__device__ __forceinline__ uint32_t smem_u32(const void* p){
    uint32_t a; asm("{ .reg .u64 t; cvta.to.shared.u64 t, %1; cvt.u32.u64 %0, t; }" : "=r"(a) : "l"(p));
    return a;
}
__device__ __forceinline__ float mish2(float x){
    float u = __expf(x);
    float t = fmaf(u, u, 2.f*u);
    return x * (1.f - __fdividef(2.f, t + 2.f));
}
__device__ __forceinline__ void mma16816(float (&d)[4], const uint32_t* a, const uint32_t* b){
    asm volatile("mma.sync.aligned.m16n8k16.row.col.f32.f16.f16.f32 "
        "{%0,%1,%2,%3}, {%4,%5,%6,%7}, {%8,%9}, {%0,%1,%2,%3};"
        : "+f"(d[0]), "+f"(d[1]), "+f"(d[2]), "+f"(d[3])
        : "r"(a[0]), "r"(a[1]), "r"(a[2]), "r"(a[3]), "r"(b[0]), "r"(b[1]));
}
#define LDSM4(R, addr) \
    asm volatile("ldmatrix.sync.aligned.m8n8.x4.shared.b16 {%0,%1,%2,%3}, [%4];" \
        : "=r"((R)[0]), "=r"((R)[1]), "=r"((R)[2]), "=r"((R)[3]) : "r"(addr))
__device__ __forceinline__ void cp16(uint32_t dst, const void* src){
    asm volatile("cp.async.ca.shared.global [%0], [%1], 16;" :: "r"(dst), "l"(src));
}
#define CP_COMMIT() asm volatile("cp.async.commit_group;" ::: "memory")
#define CP_WAIT1()  asm volatile("cp.async.wait_group 1;" ::: "memory")
#define CP_WAIT0()  asm volatile("cp.async.wait_group 0;" ::: "memory")

// fp16-split 3-product GEMM with ldmatrix fragment loads.
__device__ __forceinline__ void mma_gemm_ld(uint32_t sAh, uint32_t sAl,
                                            uint32_t sBh, uint32_t sBl,
                                            float (&d)[2][4][4],
                                            int lane, int wrow, int wcol){
    int lrow = lane & 7, seg = lane >> 3;
    int rsel = (seg & 1) << 3;
    int csel = (seg & 2) << 2;
    #pragma unroll
    for (int k0 = 0; k0 < 64; k0 += 16){
        uint32_t ah[2][4], al[2][4], bh[2][4], bl[2][4];
        #pragma unroll
        for (int ma = 0; ma < 2; ma++){
            int r = wrow*32 + ma*16 + lrow + rsel;
            uint32_t off = (uint32_t)((r*PADK + k0 + csel) * 2);
            LDSM4(ah[ma], sAh + off);
            LDSM4(al[ma], sAl + off);
        }
        #pragma unroll
        for (int nb = 0; nb < 2; nb++){
            int n = wcol*32 + nb*16 + lrow + rsel;
            uint32_t off = (uint32_t)((n*PADK + k0 + csel) * 2);
            LDSM4(bh[nb], sBh + off);
            LDSM4(bl[nb], sBl + off);
        }
        #pragma unroll
        for (int ma = 0; ma < 2; ma++)
            #pragma unroll
            for (int nb = 0; nb < 2; nb++)
                #pragma unroll
                for (int j = 0; j < 2; j++){
                    int na = nb*2 + j;
                    uint32_t Bh[2] = { bh[nb][j], bh[nb][2+j] };
                    uint32_t Bl[2] = { bl[nb][j], bl[nb][2+j] };
                    mma16816(d[ma][na], ah[ma], Bh);
                    mma16816(d[ma][na], ah[ma], Bl);
                    mma16816(d[ma][na], al[ma], Bh);
                }
    }
}

// ---------------- K0: weight split into combined images ----------------
__global__ void k_wsplit(const float* __restrict__ dW, const float* __restrict__ bW){
    int idx = blockIdx.x*256 + threadIdx.x;     // 131072
    int k = idx & 63;
    int n = (idx>>6) & 63;
    int c = (idx>>12) & 7;
    int l = idx>>15;
    long base = ((long)(l*8 + c)*4)*64*PADK;
    long e = (long)n*PADK + k;
    float v1 = dW[(long)l*DD*HHD + (long)k*HHD + c*64 + n];   // W1^T[n][k]
    __half h1 = __float2half_rn(v1);
    g_wimg[base + e] = h1;
    g_wimg[base + 64*PADK + e] = __float2half_rn(v1 - __half2float(h1));
    float v2 = bW[(long)l*HHD*DD + (long)(c*64 + k)*DD + n];  // W2^T[n][j]
    __half h2 = __float2half_rn(v2);
    g_wimg[base + 2*64*PADK + e] = h2;
    g_wimg[base + 3*64*PADK + e] = __float2half_rn(v2 - __half2float(h2));
}

// ---------------- K1: embeddings + LN1 ----------------
__global__ void k_embed(const float* __restrict__ nf, const float* __restrict__ am,
                        const float* __restrict__ eW, const float* __restrict__ eb,
                        const float* __restrict__ bW, const float* __restrict__ bbv,
                        const float* __restrict__ g1, const float* __restrict__ b1){
    int n = blockIdx.x, d = threadIdx.x;
    float acc = eb[d];
    for (int f = 0; f < FB; f++) acc += nf[n*FB + f] * eW[f*DD + d];
    float b0 = bbv[d];
    for (int k = 0; k < KDIM; k++) b0 += am[n*KDIM + k] * bW[k*DD + d];
    g_b0[n*DD + d] = b0;
    __shared__ float s[DD];
    s[d] = acc; __syncthreads();
    float mu = 0.f;
    #pragma unroll
    for (int k = 0; k < DD; k++) mu += s[k];
    mu *= (1.f/DD);
    float var = 0.f;
    #pragma unroll
    for (int k = 0; k < DD; k++){ float dd = s[k]-mu; var += dd*dd; }
    var *= (1.f/DD);
    g_x[n*DD + d] = (acc - mu) * rsqrtf(var + EPSV) * g1[d] + b1[d];
}

// ---------------- K2: Q = b0 @ diffW_layer0 ----------------
__global__ void __launch_bounds__(512,1)
k_pq(const float* __restrict__ W){
    int n0 = blockIdx.x * 8;
    __shared__ float xs[8*DD];
    int t = threadIdx.x;
    xs[t] = g_b0[n0*DD + t];
    __syncthreads();
    int j = t;
    float acc[8];
    #pragma unroll
    for (int r = 0; r < 8; r++) acc[r] = 0.f;
    #pragma unroll 8
    for (int d = 0; d < DD; d++){
        float w = W[d*HHD + j];
        #pragma unroll
        for (int r = 0; r < 8; r++) acc[r] += xs[r*DD + d] * w;
    }
    #pragma unroll
    for (int r = 0; r < 8; r++) g_Q[(long)(n0+r)*HHD + j] = acc[r];
}

// ---------------- K3: qkv (layer 0 only) ----------------
__global__ void __launch_bounds__(512,1)
k_qkv(const float* __restrict__ W, const float* __restrict__ b){
    int n0 = blockIdx.x * 8;
    __shared__ float xs[8*DD];
    int t = threadIdx.x;
    xs[t] = g_x[n0*DD + t];
    __syncthreads();
    for (int j = t; j < 3*HHD; j += 512){
        float acc[8];
        float bv = b[j];
        #pragma unroll
        for (int r = 0; r < 8; r++) acc[r] = bv;
        #pragma unroll 8
        for (int d = 0; d < DD; d++){
            float w = W[d*(3*HHD) + j];
            #pragma unroll
            for (int r = 0; r < 8; r++) acc[r] += xs[r*DD + d] * w;
        }
        #pragma unroll
        for (int r = 0; r < 8; r++) g_qkv[(long)(n0+r)*(3*HHD) + j] = acc[r];
    }
}

// ---------------- K4: HMMA fused be kernel, 2 CTAs/SM ----------------
#define SA_H    0
#define SA_L    18432
#define SE_H    36864
#define SE_L    55296
#define SW1     73728
#define SW2     92160
#define WPLANE  9216
#define WCHUNK  36864
#define SQ_OFF  110592
#define BE_SMEM (110592 + 512)

__global__ void __launch_bounds__(256,2)
k_be(int l, const float* __restrict__ db, const float* __restrict__ bb,
     int flip, int writeBias, int isL0, int dbuf){
    extern __shared__ __half smh[];
    float* sq = (float*)((char*)smh + SQ_OFF);
    float* QT = (float*)smh;
    uint32_t sbase = smem_u32(smh);
    int t = threadIdx.x, w = t>>5, lane = t&31;
    int wrow = w>>1, wcol = w&1;
    int q = lane>>2, qt = lane&3;
    long blk = blockIdx.x;
    long pair0 = blk * ROWS;
    int nrow   = (int)(blk >> 2);
    int m_base = (int)(blk & 3) * ROWS;
    float* dif = g_diffs + (long)dbuf*HH*NPAIR;

    const float* bin  = (flip ? g_bias1 : g_bias0) + pair0*DD;
    float*       bnew = (flip ? g_bias0 : g_bias1) + pair0*DD;
    const char*  wsrc = (const char*)g_wimg + (long)(l*8)*WCHUNK;

    // prologue
    if (isL0){
        for (int i = t; i < 2048; i += 256){
            int r = i >> 4, f4 = i & 15;
            cp16(sbase + (uint32_t)((r*QPAD + f4*4)*4),
                 g_Q + (long)(m_base + r)*HHD + f4*4);
        }
        CP_COMMIT();
        for (int i = t; i < 1152; i += 256) cp16(sbase + SW2 + i*16, wsrc + 2*WPLANE + i*16);
        CP_COMMIT();
    } else {
        for (int i = t; i < 1152; i += 256) cp16(sbase + SW1 + i*16, wsrc + i*16);
        CP_COMMIT();
        if (writeBias){
            for (int i = t; i < 1152; i += 256) cp16(sbase + SW2 + i*16, wsrc + 2*WPLANE + i*16);
            CP_COMMIT();
        }
        for (int i = t; i < 2048; i += 256){
            int r = i >> 4, c4 = (i & 15)*4;
            float4 v = ((const float4*)bin)[i];
            __half2 h0 = __floats2half2_rn(v.x, v.y);
            __half2 h1 = __floats2half2_rn(v.z, v.w);
            float2 f0 = __half22float2(h0);
            float2 f1 = __half22float2(h1);
            __half2 l0 = __floats2half2_rn(v.x - f0.x, v.y - f0.y);
            __half2 l1 = __floats2half2_rn(v.z - f1.x, v.w - f1.y);
            __half2* dh = (__half2*)((char*)smh + SA_H + (r*PADK + c4)*2);
            __half2* dl = (__half2*)((char*)smh + SA_L + (r*PADK + c4)*2);
            dh[0] = h0; dh[1] = h1;
            dl[0] = l0; dl[1] = l1;
        }
    }
    if (t < 128) sq[t] = 0.f;

    float acc2[2][4][4];
    #pragma unroll
    for (int ma = 0; ma < 2; ma++)
        #pragma unroll
        for (int na = 0; na < 4; na++)
            #pragma unroll
            for (int i = 0; i < 4; i++) acc2[ma][na][i] = 0.f;

    for (int c = 0; c < 8; c++){
        if (writeBias) CP_WAIT1(); else CP_WAIT0();
        __syncthreads();

        float d1[2][4][4];
        if (isL0){
            float qnv[8];
            #pragma unroll
            for (int na = 0; na < 4; na++){
                int colp = wcol*32 + na*8 + qt*2;
                qnv[2*na]   = __ldg(&g_Q[(long)nrow*HHD + c*64 + colp]);
                qnv[2*na+1] = __ldg(&g_Q[(long)nrow*HHD + c*64 + colp + 1]);
            }
            #pragma unroll
            for (int ma = 0; ma < 2; ma++){
                int r0 = wrow*32 + ma*16 + q;
                #pragma unroll
                for (int na = 0; na < 4; na++){
                    int colp = wcol*32 + na*8 + qt*2;
                    d1[ma][na][0] = QT[r0*QPAD + colp]     - qnv[2*na];
                    d1[ma][na][1] = QT[r0*QPAD + colp + 1] - qnv[2*na+1];
                    d1[ma][na][2] = QT[(r0+8)*QPAD + colp]     - qnv[2*na];
                    d1[ma][na][3] = QT[(r0+8)*QPAD + colp + 1] - qnv[2*na+1];
                }
            }
            __syncthreads();
            if (c < 7)
                for (int i = t; i < 2048; i += 256){
                    int r = i >> 4, f4 = i & 15;
                    cp16(sbase + (uint32_t)((r*QPAD + f4*4)*4),
                         g_Q + (long)(m_base + r)*HHD + (c+1)*64 + f4*4);
                }
            CP_COMMIT();
        } else {
            #pragma unroll
            for (int ma = 0; ma < 2; ma++)
                #pragma unroll
                for (int na = 0; na < 4; na++)
                    #pragma unroll
                    for (int i = 0; i < 4; i++) d1[ma][na][i] = 0.f;
            mma_gemm_ld(sbase + SA_H, sbase + SA_L, sbase + SW1, sbase + SW1 + WPLANE,
                        d1, lane, wrow, wcol);
            __syncthreads();
            if (c < 7)
                for (int i = t; i < 1152; i += 256)
                    cp16(sbase + SW1 + i*16, wsrc + (long)(c+1)*WCHUNK + i*16);
            CP_COMMIT();
        }

        // epilogue: +db, mish, sq partials (+ E-plane split/store only if GEMM2 follows)
        float dbv[8];
        #pragma unroll
        for (int na = 0; na < 4; na++){
            int colp = wcol*32 + na*8 + qt*2;
            dbv[2*na]   = __ldg(&db[c*64 + colp]);
            dbv[2*na+1] = __ldg(&db[c*64 + colp + 1]);
        }
        float rs[2][2] = {{0.f,0.f},{0.f,0.f}};
        #pragma unroll
        for (int ma = 0; ma < 2; ma++){
            int row0 = wrow*32 + ma*16 + q;
            #pragma unroll
            for (int na = 0; na < 4; na++){
                int colp = wcol*32 + na*8 + qt*2;
                float m0 = mish2(d1[ma][na][0] + dbv[2*na]);
                float m1 = mish2(d1[ma][na][1] + dbv[2*na+1]);
                float m2 = mish2(d1[ma][na][2] + dbv[2*na]);
                float m3 = mish2(d1[ma][na][3] + dbv[2*na+1]);
                rs[ma][0] = fmaf(m0,m0, fmaf(m1,m1, rs[ma][0]));
                rs[ma][1] = fmaf(m2,m2, fmaf(m3,m3, rs[ma][1]));
                if (writeBias){
                    __half2 h01 = __floats2half2_rn(m0, m1);
                    __half2 h23 = __floats2half2_rn(m2, m3);
                    float2 f01 = __half22float2(h01);
                    float2 f23 = __half22float2(h23);
                    __half2 l01 = __floats2half2_rn(m0 - f01.x, m1 - f01.y);
                    __half2 l23 = __floats2half2_rn(m2 - f23.x, m3 - f23.y);
                    *(__half2*)((char*)smh + SE_H + (row0*PADK + colp)*2)     = h01;
                    *(__half2*)((char*)smh + SE_L + (row0*PADK + colp)*2)     = l01;
                    *(__half2*)((char*)smh + SE_H + ((row0+8)*PADK + colp)*2) = h23;
                    *(__half2*)((char*)smh + SE_L + ((row0+8)*PADK + colp)*2) = l23;
                }
            }
        }
        #pragma unroll
        for (int ma = 0; ma < 2; ma++)
            #pragma unroll
            for (int hh = 0; hh < 2; hh++){
                float s = rs[ma][hh];
                s += __shfl_xor_sync(0xffffffffu, s, 1);
                s += __shfl_xor_sync(0xffffffffu, s, 2);
                if (qt == 0) atomicAdd(&sq[wrow*32 + ma*16 + q + hh*8], s);
            }

        if (writeBias){
            CP_WAIT1();
            __syncthreads();           // E planes + sq visible, w2 ready
            mma_gemm_ld(sbase + SE_H, sbase + SE_L, sbase + SW2, sbase + SW2 + WPLANE,
                        acc2, lane, wrow, wcol);
            __syncthreads();
            if (c < 7)
                for (int i = t; i < 1152; i += 256)
                    cp16(sbase + SW2 + i*16, wsrc + (long)(c+1)*WCHUNK + 2*WPLANE + i*16);
            CP_COMMIT();
            if (c & 1){
                if (t < 128){
                    dif[(long)(c>>1)*NPAIR + pair0 + t] = sqrtf(sq[t]);
                    sq[t] = 0.f;
                }
            }
        } else {
            if (c & 1){
                __syncthreads();       // order atomicAdds before read/reset
                if (t < 128){
                    dif[(long)(c>>1)*NPAIR + pair0 + t] = sqrtf(sq[t]);
                    sq[t] = 0.f;
                }
            }
        }
    }

    // final: bias' = mish(acc2 + bb)
    if (writeBias){
        #pragma unroll
        for (int ma = 0; ma < 2; ma++){
            #pragma unroll
            for (int na = 0; na < 4; na++){
                int colp = wcol*32 + na*8 + qt*2;
                float bb0 = __ldg(&bb[colp]);
                float bb1 = __ldg(&bb[colp + 1]);
                int row0 = wrow*32 + ma*16 + q;
                float2 v0 = { mish2(acc2[ma][na][0] + bb0), mish2(acc2[ma][na][1] + bb1) };
                float2 v1 = { mish2(acc2[ma][na][2] + bb0), mish2(acc2[ma][na][3] + bb1) };
                *(float2*)&bnew[(long)row0*DD + colp]     = v0;
                *(float2*)&bnew[(long)(row0+8)*DD + colp] = v1;
            }
        }
    }
}

// ---------------- K5: attention ----------------
__global__ void __launch_bounds__(512,1) k_attn(float scale, int dbuf){
    int h  = blockIdx.y;
    int n0 = blockIdx.x * 16;
    __shared__ float qS[16*HD];
    __shared__ float lg[16*NN_N];
    int t = threadIdx.x;
    const float* dif = g_diffs + (long)dbuf*HH*NPAIR;

    for (int idx = t; idx < 16*HD; idx += 512){
        int nn = idx >> 7, d = idx & 127;
        qS[idx] = g_qkv[(long)(n0+nn)*(3*HHD) + h*384 + d];
    }
    __syncthreads();
    {
        int m = t;
        float acc[16];
        #pragma unroll
        for (int nn = 0; nn < 16; nn++) acc[nn] = 0.f;
        const float* kp = g_qkv + (long)m*(3*HHD) + h*384 + 128;
        #pragma unroll 4
        for (int d = 0; d < HD; d += 4){
            float4 kv = *(const float4*)(kp + d);
            #pragma unroll
            for (int nn = 0; nn < 16; nn++){
                float4 qv = *(const float4*)&qS[nn*HD + d];
                acc[nn] += qv.x*kv.x + qv.y*kv.y + qv.z*kv.z + qv.w*kv.w;
            }
        }
        const float* dp = dif + (long)h*NPAIR + (long)n0*NN_N + m;
        #pragma unroll
        for (int nn = 0; nn < 16; nn++)
            lg[nn*NN_N + m] = acc[nn]*scale + dp[(long)nn*NN_N];
    }
    __syncthreads();
    {
        int row = t >> 5, lane = t & 31;
        float* Lr = lg + row*NN_N;
        float mx = -1e30f;
        for (int m = lane; m < NN_N; m += 32) mx = fmaxf(mx, Lr[m]);
        #pragma unroll
        for (int o = 16; o; o >>= 1) mx = fmaxf(mx, __shfl_xor_sync(0xffffffffu, mx, o));
        float sum = 0.f;
        for (int m = lane; m < NN_N; m += 32){
            float e = __expf(Lr[m] - mx); Lr[m] = e; sum += e;
        }
        #pragma unroll
        for (int o = 16; o; o >>= 1) sum += __shfl_xor_sync(0xffffffffu, sum, o);
        float inv = 1.f / sum;
        for (int m = lane; m < NN_N; m += 32) Lr[m] *= inv;
    }
    __syncthreads();
    {
        int d = t & 127, ng = t >> 7;
        float acc[4] = {0.f, 0.f, 0.f, 0.f};
        const float* vp = g_qkv + h*384 + 256 + d;
        #pragma unroll 4
        for (int m = 0; m < NN_N; m++){
            float vv = vp[(long)m*(3*HHD)];
            #pragma unroll
            for (int k = 0; k < 4; k++) acc[k] += lg[(ng*4+k)*NN_N + m] * vv;
        }
        #pragma unroll
        for (int k = 0; k < 4; k++)
            g_vals[(long)(n0 + ng*4 + k)*HHD + h*HD + d] = acc[k];
    }
}

// ---------------- K5b: oln + fused next-layer qkv / final out ----------------
__global__ void __launch_bounds__(512,1)
k_oln(const float* __restrict__ oW, const float* __restrict__ ob,
      const float* __restrict__ g2, const float* __restrict__ b2,
      const float* __restrict__ qW, const float* __restrict__ qb, int doQkv,
      const float* __restrict__ outW, const float* __restrict__ outb,
      float* __restrict__ out, int doOut){
    int n0 = blockIdx.x * 8;
    __shared__ float vs[8*HHD];
    __shared__ float s[8*DD];
    int t = threadIdx.x;
    for (int i = t; i < 8*HHD/4; i += 512)
        ((float4*)vs)[i] = ((const float4*)(g_vals + (long)n0*HHD))[i];
    __syncthreads();
    int r = t >> 6, i = t & 63;
    float acc = 0.f;
    #pragma unroll 8
    for (int j = 0; j < HHD; j++)
        acc += vs[r*HHD + j] * oW[j*DD + i];
    float xv = g_x[(n0+r)*DD + i] + acc + ob[i];
    s[r*DD + i] = xv;
    __syncthreads();
    float mu = 0.f;
    #pragma unroll
    for (int k = 0; k < DD; k++) mu += s[r*DD + k];
    mu *= (1.f/DD);
    float var = 0.f;
    #pragma unroll
    for (int k = 0; k < DD; k++){ float dd = s[r*DD + k]-mu; var += dd*dd; }
    var *= (1.f/DD);
    float xn = (xv - mu) * rsqrtf(var + EPSV) * g2[i] + b2[i];
    g_x[(n0+r)*DD + i] = xn;
    __syncthreads();
    s[r*DD + i] = xn;
    __syncthreads();
    if (doQkv){
        for (int j = t; j < 3*HHD; j += 512){
            float a2[8];
            float bv = qb[j];
            #pragma unroll
            for (int rr = 0; rr < 8; rr++) a2[rr] = bv;
            #pragma unroll 8
            for (int d = 0; d < DD; d++){
                float w = qW[d*(3*HHD) + j];
                #pragma unroll
                for (int rr = 0; rr < 8; rr++) a2[rr] += s[rr*DD + d] * w;
            }
            #pragma unroll
            for (int rr = 0; rr < 8; rr++) g_qkv[(long)(n0+rr)*(3*HHD) + j] = a2[rr];
        }
    }
    if (doOut && t < 8){
        float a = outb[0];
        #pragma unroll
        for (int d = 0; d < DD; d++) a += s[t*DD + d] * outW[d];
        out[n0 + t] = a;
    }
}

// ---------------- launcher (dual-stream pipeline) ----------------
extern "C" void kernel_launch(void* const* d_in, const int* in_sizes, int n_in,
                              void* d_out, int out_size){
    const float* nf    = (const float*)d_in[0];
    const float* amds  = (const float*)d_in[1];
    const float* embW  = (const float*)d_in[2];
    const float* embb  = (const float*)d_in[3];
    const float* bembW = (const float*)d_in[4];
    const float* bembb = (const float*)d_in[5];
    const float* ln1g  = (const float*)d_in[6];
    const float* ln1b  = (const float*)d_in[7];
    const float* ln2g  = (const float*)d_in[8];
    const float* ln2b  = (const float*)d_in[9];
    const float* qkvW  = (const float*)d_in[10];
    const float* qkvb  = (const float*)d_in[11];
    const float* diffW = (const float*)d_in[12];
    const float* diffb = (const float*)d_in[13];
    const float* oW    = (const float*)d_in[14];
    const float* ob    = (const float*)d_in[15];
    const float* boutW = (const float*)d_in[16];
    const float* boutb = (const float*)d_in[17];
    const float* outW  = (const float*)d_in[18];
    const float* outb  = (const float*)d_in[19];

    static int inited = 0;
    static cudaStream_t s1;
    static cudaEvent_t evBE[LAYERS], evAT[LAYERS], evJoin;
    if (!inited){
        cudaStreamCreateWithFlags(&s1, cudaStreamNonBlocking);
        for (int i = 0; i < LAYERS; i++){
            cudaEventCreateWithFlags(&evBE[i], cudaEventDisableTiming);
            cudaEventCreateWithFlags(&evAT[i], cudaEventDisableTiming);
        }
        cudaEventCreateWithFlags(&evJoin, cudaEventDisableTiming);
        cudaFuncSetAttribute(k_be, cudaFuncAttributeMaxDynamicSharedMemorySize, BE_SMEM);
        inited = 1;
    }

    k_wsplit<<<512, 256>>>(diffW, boutW);
    k_embed<<<NN_N, DD>>>(nf, amds, embW, embb, bembW, bembb, ln1g, ln1b);
    k_pq<<<NN_N/8, 512>>>(diffW);
    k_qkv<<<NN_N/8, 512>>>(qkvW, qkvb);

    float scale = 1.f / sqrtf((float)HD);
    for (int l = 0; l < LAYERS; l++){
        if (l >= 2) cudaStreamWaitEvent(0, evAT[l-2], 0);   // diffs buffer reuse guard
        k_be<<<NBLK, 256, BE_SMEM>>>(l, diffb + (long)l*HHD, boutb + (long)l*DD,
                                     l & 1, (l < LAYERS-1) ? 1 : 0,
                                     (l == 0) ? 1 : 0, l & 1);
        cudaEventRecord(evBE[l], 0);
        cudaStreamWaitEvent(s1, evBE[l], 0);
        k_attn<<<dim3(NN_N/16, HH), 512, 0, s1>>>(scale, l & 1);
        cudaEventRecord(evAT[l], s1);
        int last = (l == LAYERS-1);
        k_oln<<<NN_N/8, 512, 0, s1>>>(oW + (long)l*HHD*DD, ob + l*DD, ln2g, ln2b,
                                      qkvW + (long)(l+1)*DD*3*HHD,
                                      qkvb + (long)(l+1)*3*HHD, last ? 0 : 1,
                                      outW, outb, (float*)d_out, last);
    }
    cudaEventRecord(evJoin, s1);
    cudaStreamWaitEvent(0, evJoin, 0);
}

// round 12
// speedup vs baseline: 3.0944x; 1.0954x over previous
#include <cuda_runtime.h>
#include <cuda_fp16.h>
#include <math.h>
#include <stdint.h>

#define NN_N   512
#define FB     256
#define DD     64
#define HH     4
#define HD     128
#define HHD    512
#define LAYERS 4
#define KDIM   100
#define NPAIR  (NN_N*NN_N)
#define EPSV   1e-5f
#define ROWS   128
#define NBLK   (NPAIR/ROWS)      /* 2048 */
#define PADK   72                /* halves per smem row (conflict-free) */
#define QPAD   68                /* floats per QT smem row */

// ---------------- device scratch ----------------
__device__ float g_bias0[NPAIR*DD];
__device__ float g_bias1[NPAIR*DD];
__device__ float g_diffs[2*HH*NPAIR];   // double-buffered by layer parity
__device__ float g_x[NN_N*DD];
__device__ float g_b0[NN_N*DD];
__device__ float g_Q[NN_N*HHD];
__device__ float g_qkv[NN_N*3*HHD];
__device__ float g_vals[NN_N*HHD];
__device__ __align__(16) __half g_wimg[LAYERS*8*4*64*PADK];

// ---------------- helpers ----------------
__device__ __forceinline__ uint32_t smem_u32(const void* p){
    uint32_t a; asm("{ .reg .u64 t; cvta.to.shared.u64 t, %1; cvt.u32.u64 %0, t; }" : "=r"(a) : "l"(p));
    return a;
}
__device__ __forceinline__ float mish2(float x){
    float u = __expf(x);
    float t = fmaf(u, u, 2.f*u);
    return x * (1.f - __fdividef(2.f, t + 2.f));
}
__device__ __forceinline__ void mma16816(float (&d)[4], const uint32_t* a, const uint32_t* b){
    asm volatile("mma.sync.aligned.m16n8k16.row.col.f32.f16.f16.f32 "
        "{%0,%1,%2,%3}, {%4,%5,%6,%7}, {%8,%9}, {%0,%1,%2,%3};"
        : "+f"(d[0]), "+f"(d[1]), "+f"(d[2]), "+f"(d[3])
        : "r"(a[0]), "r"(a[1]), "r"(a[2]), "r"(a[3]), "r"(b[0]), "r"(b[1]));
}
#define LDSM4(R, addr) \
    asm volatile("ldmatrix.sync.aligned.m8n8.x4.shared.b16 {%0,%1,%2,%3}, [%4];" \
        : "=r"((R)[0]), "=r"((R)[1]), "=r"((R)[2]), "=r"((R)[3]) : "r"(addr))
__device__ __forceinline__ void cp16(uint32_t dst, const void* src){
    asm volatile("cp.async.ca.shared.global [%0], [%1], 16;" :: "r"(dst), "l"(src));
}
#define CP_COMMIT() asm volatile("cp.async.commit_group;" ::: "memory")
#define CP_WAIT1()  asm volatile("cp.async.wait_group 1;" ::: "memory")
#define CP_WAIT0()  asm volatile("cp.async.wait_group 0;" ::: "memory")

// fp16-split 3-product GEMM with ldmatrix fragment loads (GEMM1: full accuracy).
__device__ __forceinline__ void mma_gemm_ld(uint32_t sAh, uint32_t sAl,
                                            uint32_t sBh, uint32_t sBl,
                                            float (&d)[2][4][4],
                                            int lane, int wrow, int wcol){
    int lrow = lane & 7, seg = lane >> 3;
    int rsel = (seg & 1) << 3;
    int csel = (seg & 2) << 2;
    #pragma unroll
    for (int k0 = 0; k0 < 64; k0 += 16){
        uint32_t ah[2][4], al[2][4], bh[2][4], bl[2][4];
        #pragma unroll
        for (int ma = 0; ma < 2; ma++){
            int r = wrow*32 + ma*16 + lrow + rsel;
            uint32_t off = (uint32_t)((r*PADK + k0 + csel) * 2);
            LDSM4(ah[ma], sAh + off);
            LDSM4(al[ma], sAl + off);
        }
        #pragma unroll
        for (int nb = 0; nb < 2; nb++){
            int n = wcol*32 + nb*16 + lrow + rsel;
            uint32_t off = (uint32_t)((n*PADK + k0 + csel) * 2);
            LDSM4(bh[nb], sBh + off);
            LDSM4(bl[nb], sBl + off);
        }
        #pragma unroll
        for (int ma = 0; ma < 2; ma++)
            #pragma unroll
            for (int nb = 0; nb < 2; nb++)
                #pragma unroll
                for (int j = 0; j < 2; j++){
                    int na = nb*2 + j;
                    uint32_t Bh[2] = { bh[nb][j], bh[nb][2+j] };
                    uint32_t Bl[2] = { bl[nb][j], bl[nb][2+j] };
                    mma16816(d[ma][na], ah[ma], Bh);
                    mma16816(d[ma][na], ah[ma], Bl);
                    mma16816(d[ma][na], al[ma], Bh);
                }
    }
}

// fp16 2-product GEMM (GEMM2): A single plane (E_hi), B hi/lo split.
// error = E_lo·W2 ~ 2^-11 relative — diluted through norm + softmax downstream.
__device__ __forceinline__ void mma_gemm_ld2(uint32_t sAh,
                                             uint32_t sBh, uint32_t sBl,
                                             float (&d)[2][4][4],
                                             int lane, int wrow, int wcol){
    int lrow = lane & 7, seg = lane >> 3;
    int rsel = (seg & 1) << 3;
    int csel = (seg & 2) << 2;
    #pragma unroll
    for (int k0 = 0; k0 < 64; k0 += 16){
        uint32_t ah[2][4], bh[2][4], bl[2][4];
        #pragma unroll
        for (int ma = 0; ma < 2; ma++){
            int r = wrow*32 + ma*16 + lrow + rsel;
            uint32_t off = (uint32_t)((r*PADK + k0 + csel) * 2);
            LDSM4(ah[ma], sAh + off);
        }
        #pragma unroll
        for (int nb = 0; nb < 2; nb++){
            int n = wcol*32 + nb*16 + lrow + rsel;
            uint32_t off = (uint32_t)((n*PADK + k0 + csel) * 2);
            LDSM4(bh[nb], sBh + off);
            LDSM4(bl[nb], sBl + off);
        }
        #pragma unroll
        for (int ma = 0; ma < 2; ma++)
            #pragma unroll
            for (int nb = 0; nb < 2; nb++)
                #pragma unroll
                for (int j = 0; j < 2; j++){
                    int na = nb*2 + j;
                    uint32_t Bh[2] = { bh[nb][j], bh[nb][2+j] };
                    uint32_t Bl[2] = { bl[nb][j], bl[nb][2+j] };
                    mma16816(d[ma][na], ah[ma], Bh);
                    mma16816(d[ma][na], ah[ma], Bl);
                }
    }
}

// ---------------- K0: weight split into combined images ----------------
__global__ void k_wsplit(const float* __restrict__ dW, const float* __restrict__ bW){
    int idx = blockIdx.x*256 + threadIdx.x;     // 131072
    int k = idx & 63;
    int n = (idx>>6) & 63;
    int c = (idx>>12) & 7;
    int l = idx>>15;
    long base = ((long)(l*8 + c)*4)*64*PADK;
    long e = (long)n*PADK + k;
    float v1 = dW[(long)l*DD*HHD + (long)k*HHD + c*64 + n];   // W1^T[n][k]
    __half h1 = __float2half_rn(v1);
    g_wimg[base + e] = h1;
    g_wimg[base + 64*PADK + e] = __float2half_rn(v1 - __half2float(h1));
    float v2 = bW[(long)l*HHD*DD + (long)(c*64 + k)*DD + n];  // W2^T[n][j]
    __half h2 = __float2half_rn(v2);
    g_wimg[base + 2*64*PADK + e] = h2;
    g_wimg[base + 3*64*PADK + e] = __float2half_rn(v2 - __half2float(h2));
}

// ---------------- K1: embeddings + LN1 ----------------
__global__ void k_embed(const float* __restrict__ nf, const float* __restrict__ am,
                        const float* __restrict__ eW, const float* __restrict__ eb,
                        const float* __restrict__ bW, const float* __restrict__ bbv,
                        const float* __restrict__ g1, const float* __restrict__ b1){
    int n = blockIdx.x, d = threadIdx.x;
    float acc = eb[d];
    for (int f = 0; f < FB; f++) acc += nf[n*FB + f] * eW[f*DD + d];
    float b0 = bbv[d];
    for (int k = 0; k < KDIM; k++) b0 += am[n*KDIM + k] * bW[k*DD + d];
    g_b0[n*DD + d] = b0;
    __shared__ float s[DD];
    s[d] = acc; __syncthreads();
    float mu = 0.f;
    #pragma unroll
    for (int k = 0; k < DD; k++) mu += s[k];
    mu *= (1.f/DD);
    float var = 0.f;
    #pragma unroll
    for (int k = 0; k < DD; k++){ float dd = s[k]-mu; var += dd*dd; }
    var *= (1.f/DD);
    g_x[n*DD + d] = (acc - mu) * rsqrtf(var + EPSV) * g1[d] + b1[d];
}

// ---------------- K2: Q = b0 @ diffW_layer0 ----------------
__global__ void __launch_bounds__(512,1)
k_pq(const float* __restrict__ W){
    int n0 = blockIdx.x * 8;
    __shared__ float xs[8*DD];
    int t = threadIdx.x;
    xs[t] = g_b0[n0*DD + t];
    __syncthreads();
    int j = t;
    float acc[8];
    #pragma unroll
    for (int r = 0; r < 8; r++) acc[r] = 0.f;
    #pragma unroll 8
    for (int d = 0; d < DD; d++){
        float w = W[d*HHD + j];
        #pragma unroll
        for (int r = 0; r < 8; r++) acc[r] += xs[r*DD + d] * w;
    }
    #pragma unroll
    for (int r = 0; r < 8; r++) g_Q[(long)(n0+r)*HHD + j] = acc[r];
}

// ---------------- K3: qkv (layer 0 only) ----------------
__global__ void __launch_bounds__(512,1)
k_qkv(const float* __restrict__ W, const float* __restrict__ b){
    int n0 = blockIdx.x * 8;
    __shared__ float xs[8*DD];
    int t = threadIdx.x;
    xs[t] = g_x[n0*DD + t];
    __syncthreads();
    for (int j = t; j < 3*HHD; j += 512){
        float acc[8];
        float bv = b[j];
        #pragma unroll
        for (int r = 0; r < 8; r++) acc[r] = bv;
        #pragma unroll 8
        for (int d = 0; d < DD; d++){
            float w = W[d*(3*HHD) + j];
            #pragma unroll
            for (int r = 0; r < 8; r++) acc[r] += xs[r*DD + d] * w;
        }
        #pragma unroll
        for (int r = 0; r < 8; r++) g_qkv[(long)(n0+r)*(3*HHD) + j] = acc[r];
    }
}

// ---------------- K4: HMMA fused be kernel, 2 CTAs/SM ----------------
// smem bytes: A hi/lo 36864, E_hi 18432, W1 18432, W2 18432, sq 512
#define SA_H    0
#define SA_L    18432
#define SE_H    36864
#define SW1     55296          /* w1h @ +0, w1l @ +9216 */
#define SW2     73728          /* w2h @ +0, w2l @ +9216 */
#define WPLANE  9216
#define WCHUNK  36864
#define SQ_OFF  92160
#define BE_SMEM (92160 + 512)

__global__ void __launch_bounds__(256,2)
k_be(int l, const float* __restrict__ db, const float* __restrict__ bb,
     int flip, int writeBias, int isL0, int dbuf){
    extern __shared__ __half smh[];
    float* sq = (float*)((char*)smh + SQ_OFF);
    float* QT = (float*)smh;
    uint32_t sbase = smem_u32(smh);
    int t = threadIdx.x, w = t>>5, lane = t&31;
    int wrow = w>>1, wcol = w&1;
    int q = lane>>2, qt = lane&3;
    long blk = blockIdx.x;
    long pair0 = blk * ROWS;
    int nrow   = (int)(blk >> 2);
    int m_base = (int)(blk & 3) * ROWS;
    float* dif = g_diffs + (long)dbuf*HH*NPAIR;

    const float* bin  = (flip ? g_bias1 : g_bias0) + pair0*DD;
    float*       bnew = (flip ? g_bias0 : g_bias1) + pair0*DD;
    const char*  wsrc = (const char*)g_wimg + (long)(l*8)*WCHUNK;

    // prologue
    if (isL0){
        for (int i = t; i < 2048; i += 256){
            int r = i >> 4, f4 = i & 15;
            cp16(sbase + (uint32_t)((r*QPAD + f4*4)*4),
                 g_Q + (long)(m_base + r)*HHD + f4*4);
        }
        CP_COMMIT();
        for (int i = t; i < 1152; i += 256) cp16(sbase + SW2 + i*16, wsrc + 2*WPLANE + i*16);
        CP_COMMIT();
    } else {
        for (int i = t; i < 1152; i += 256) cp16(sbase + SW1 + i*16, wsrc + i*16);
        CP_COMMIT();
        if (writeBias){
            for (int i = t; i < 1152; i += 256) cp16(sbase + SW2 + i*16, wsrc + 2*WPLANE + i*16);
            CP_COMMIT();
        }
        for (int i = t; i < 2048; i += 256){
            int r = i >> 4, c4 = (i & 15)*4;
            float4 v = ((const float4*)bin)[i];
            __half2 h0 = __floats2half2_rn(v.x, v.y);
            __half2 h1 = __floats2half2_rn(v.z, v.w);
            float2 f0 = __half22float2(h0);
            float2 f1 = __half22float2(h1);
            __half2 l0 = __floats2half2_rn(v.x - f0.x, v.y - f0.y);
            __half2 l1 = __floats2half2_rn(v.z - f1.x, v.w - f1.y);
            __half2* dh = (__half2*)((char*)smh + SA_H + (r*PADK + c4)*2);
            __half2* dl = (__half2*)((char*)smh + SA_L + (r*PADK + c4)*2);
            dh[0] = h0; dh[1] = h1;
            dl[0] = l0; dl[1] = l1;
        }
    }
    if (t < 128) sq[t] = 0.f;

    float acc2[2][4][4];
    #pragma unroll
    for (int ma = 0; ma < 2; ma++)
        #pragma unroll
        for (int na = 0; na < 4; na++)
            #pragma unroll
            for (int i = 0; i < 4; i++) acc2[ma][na][i] = 0.f;

    for (int c = 0; c < 8; c++){
        if (writeBias) CP_WAIT1(); else CP_WAIT0();
        __syncthreads();

        float d1[2][4][4];
        if (isL0){
            float qnv[8];
            #pragma unroll
            for (int na = 0; na < 4; na++){
                int colp = wcol*32 + na*8 + qt*2;
                qnv[2*na]   = __ldg(&g_Q[(long)nrow*HHD + c*64 + colp]);
                qnv[2*na+1] = __ldg(&g_Q[(long)nrow*HHD + c*64 + colp + 1]);
            }
            #pragma unroll
            for (int ma = 0; ma < 2; ma++){
                int r0 = wrow*32 + ma*16 + q;
                #pragma unroll
                for (int na = 0; na < 4; na++){
                    int colp = wcol*32 + na*8 + qt*2;
                    d1[ma][na][0] = QT[r0*QPAD + colp]     - qnv[2*na];
                    d1[ma][na][1] = QT[r0*QPAD + colp + 1] - qnv[2*na+1];
                    d1[ma][na][2] = QT[(r0+8)*QPAD + colp]     - qnv[2*na];
                    d1[ma][na][3] = QT[(r0+8)*QPAD + colp + 1] - qnv[2*na+1];
                }
            }
            __syncthreads();
            if (c < 7)
                for (int i = t; i < 2048; i += 256){
                    int r = i >> 4, f4 = i & 15;
                    cp16(sbase + (uint32_t)((r*QPAD + f4*4)*4),
                         g_Q + (long)(m_base + r)*HHD + (c+1)*64 + f4*4);
                }
            CP_COMMIT();
        } else {
            #pragma unroll
            for (int ma = 0; ma < 2; ma++)
                #pragma unroll
                for (int na = 0; na < 4; na++)
                    #pragma unroll
                    for (int i = 0; i < 4; i++) d1[ma][na][i] = 0.f;
            mma_gemm_ld(sbase + SA_H, sbase + SA_L, sbase + SW1, sbase + SW1 + WPLANE,
                        d1, lane, wrow, wcol);
            __syncthreads();
            if (c < 7)
                for (int i = t; i < 1152; i += 256)
                    cp16(sbase + SW1 + i*16, wsrc + (long)(c+1)*WCHUNK + i*16);
            CP_COMMIT();
        }

        // epilogue: +db, mish, sq partials (+ E_hi plane store only if GEMM2 follows)
        float dbv[8];
        #pragma unroll
        for (int na = 0; na < 4; na++){
            int colp = wcol*32 + na*8 + qt*2;
            dbv[2*na]   = __ldg(&db[c*64 + colp]);
            dbv[2*na+1] = __ldg(&db[c*64 + colp + 1]);
        }
        float rs[2][2] = {{0.f,0.f},{0.f,0.f}};
        #pragma unroll
        for (int ma = 0; ma < 2; ma++){
            int row0 = wrow*32 + ma*16 + q;
            #pragma unroll
            for (int na = 0; na < 4; na++){
                int colp = wcol*32 + na*8 + qt*2;
                float m0 = mish2(d1[ma][na][0] + dbv[2*na]);
                float m1 = mish2(d1[ma][na][1] + dbv[2*na+1]);
                float m2 = mish2(d1[ma][na][2] + dbv[2*na]);
                float m3 = mish2(d1[ma][na][3] + dbv[2*na+1]);
                rs[ma][0] = fmaf(m0,m0, fmaf(m1,m1, rs[ma][0]));
                rs[ma][1] = fmaf(m2,m2, fmaf(m3,m3, rs[ma][1]));
                if (writeBias){
                    __half2 h01 = __floats2half2_rn(m0, m1);
                    __half2 h23 = __floats2half2_rn(m2, m3);
                    *(__half2*)((char*)smh + SE_H + (row0*PADK + colp)*2)     = h01;
                    *(__half2*)((char*)smh + SE_H + ((row0+8)*PADK + colp)*2) = h23;
                }
            }
        }
        #pragma unroll
        for (int ma = 0; ma < 2; ma++)
            #pragma unroll
            for (int hh = 0; hh < 2; hh++){
                float s = rs[ma][hh];
                s += __shfl_xor_sync(0xffffffffu, s, 1);
                s += __shfl_xor_sync(0xffffffffu, s, 2);
                if (qt == 0) atomicAdd(&sq[wrow*32 + ma*16 + q + hh*8], s);
            }

        if (writeBias){
            CP_WAIT1();
            __syncthreads();           // E_hi + sq visible, w2 ready
            mma_gemm_ld2(sbase + SE_H, sbase + SW2, sbase + SW2 + WPLANE,
                         acc2, lane, wrow, wcol);
            __syncthreads();
            if (c < 7)
                for (int i = t; i < 1152; i += 256)
                    cp16(sbase + SW2 + i*16, wsrc + (long)(c+1)*WCHUNK + 2*WPLANE + i*16);
            CP_COMMIT();
            if (c & 1){
                if (t < 128){
                    dif[(long)(c>>1)*NPAIR + pair0 + t] = sqrtf(sq[t]);
                    sq[t] = 0.f;
                }
            }
        } else {
            if (c & 1){
                __syncthreads();       // order atomicAdds before read/reset
                if (t < 128){
                    dif[(long)(c>>1)*NPAIR + pair0 + t] = sqrtf(sq[t]);
                    sq[t] = 0.f;
                }
            }
        }
    }

    // final: bias' = mish(acc2 + bb)
    if (writeBias){
        #pragma unroll
        for (int ma = 0; ma < 2; ma++){
            #pragma unroll
            for (int na = 0; na < 4; na++){
                int colp = wcol*32 + na*8 + qt*2;
                float bb0 = __ldg(&bb[colp]);
                float bb1 = __ldg(&bb[colp + 1]);
                int row0 = wrow*32 + ma*16 + q;
                float2 v0 = { mish2(acc2[ma][na][0] + bb0), mish2(acc2[ma][na][1] + bb1) };
                float2 v1 = { mish2(acc2[ma][na][2] + bb0), mish2(acc2[ma][na][3] + bb1) };
                *(float2*)&bnew[(long)row0*DD + colp]     = v0;
                *(float2*)&bnew[(long)(row0+8)*DD + colp] = v1;
            }
        }
    }
}

// ---------------- K5: attention ----------------
__global__ void __launch_bounds__(512,1) k_attn(float scale, int dbuf){
    int h  = blockIdx.y;
    int n0 = blockIdx.x * 16;
    __shared__ float qS[16*HD];
    __shared__ float lg[16*NN_N];
    int t = threadIdx.x;
    const float* dif = g_diffs + (long)dbuf*HH*NPAIR;

    for (int idx = t; idx < 16*HD; idx += 512){
        int nn = idx >> 7, d = idx & 127;
        qS[idx] = g_qkv[(long)(n0+nn)*(3*HHD) + h*384 + d];
    }
    __syncthreads();
    {
        int m = t;
        float acc[16];
        #pragma unroll
        for (int nn = 0; nn < 16; nn++) acc[nn] = 0.f;
        const float* kp = g_qkv + (long)m*(3*HHD) + h*384 + 128;
        #pragma unroll 4
        for (int d = 0; d < HD; d += 4){
            float4 kv = *(const float4*)(kp + d);
            #pragma unroll
            for (int nn = 0; nn < 16; nn++){
                float4 qv = *(const float4*)&qS[nn*HD + d];
                acc[nn] += qv.x*kv.x + qv.y*kv.y + qv.z*kv.z + qv.w*kv.w;
            }
        }
        const float* dp = dif + (long)h*NPAIR + (long)n0*NN_N + m;
        #pragma unroll
        for (int nn = 0; nn < 16; nn++)
            lg[nn*NN_N + m] = acc[nn]*scale + dp[(long)nn*NN_N];
    }
    __syncthreads();
    {
        int row = t >> 5, lane = t & 31;
        float* Lr = lg + row*NN_N;
        float mx = -1e30f;
        for (int m = lane; m < NN_N; m += 32) mx = fmaxf(mx, Lr[m]);
        #pragma unroll
        for (int o = 16; o; o >>= 1) mx = fmaxf(mx, __shfl_xor_sync(0xffffffffu, mx, o));
        float sum = 0.f;
        for (int m = lane; m < NN_N; m += 32){
            float e = __expf(Lr[m] - mx); Lr[m] = e; sum += e;
        }
        #pragma unroll
        for (int o = 16; o; o >>= 1) sum += __shfl_xor_sync(0xffffffffu, sum, o);
        float inv = 1.f / sum;
        for (int m = lane; m < NN_N; m += 32) Lr[m] *= inv;
    }
    __syncthreads();
    {
        int d = t & 127, ng = t >> 7;
        float acc[4] = {0.f, 0.f, 0.f, 0.f};
        const float* vp = g_qkv + h*384 + 256 + d;
        #pragma unroll 4
        for (int m = 0; m < NN_N; m++){
            float vv = vp[(long)m*(3*HHD)];
            #pragma unroll
            for (int k = 0; k < 4; k++) acc[k] += lg[(ng*4+k)*NN_N + m] * vv;
        }
        #pragma unroll
        for (int k = 0; k < 4; k++)
            g_vals[(long)(n0 + ng*4 + k)*HHD + h*HD + d] = acc[k];
    }
}

// ---------------- K5b: oln + fused next-layer qkv / final out ----------------
__global__ void __launch_bounds__(512,1)
k_oln(const float* __restrict__ oW, const float* __restrict__ ob,
      const float* __restrict__ g2, const float* __restrict__ b2,
      const float* __restrict__ qW, const float* __restrict__ qb, int doQkv,
      const float* __restrict__ outW, const float* __restrict__ outb,
      float* __restrict__ out, int doOut){
    int n0 = blockIdx.x * 8;
    __shared__ float vs[8*HHD];
    __shared__ float s[8*DD];
    int t = threadIdx.x;
    for (int i = t; i < 8*HHD/4; i += 512)
        ((float4*)vs)[i] = ((const float4*)(g_vals + (long)n0*HHD))[i];
    __syncthreads();
    int r = t >> 6, i = t & 63;
    float acc = 0.f;
    #pragma unroll 8
    for (int j = 0; j < HHD; j++)
        acc += vs[r*HHD + j] * oW[j*DD + i];
    float xv = g_x[(n0+r)*DD + i] + acc + ob[i];
    s[r*DD + i] = xv;
    __syncthreads();
    float mu = 0.f;
    #pragma unroll
    for (int k = 0; k < DD; k++) mu += s[r*DD + k];
    mu *= (1.f/DD);
    float var = 0.f;
    #pragma unroll
    for (int k = 0; k < DD; k++){ float dd = s[r*DD + k]-mu; var += dd*dd; }
    var *= (1.f/DD);
    float xn = (xv - mu) * rsqrtf(var + EPSV) * g2[i] + b2[i];
    g_x[(n0+r)*DD + i] = xn;
    __syncthreads();
    s[r*DD + i] = xn;
    __syncthreads();
    if (doQkv){
        for (int j = t; j < 3*HHD; j += 512){
            float a2[8];
            float bv = qb[j];
            #pragma unroll
            for (int rr = 0; rr < 8; rr++) a2[rr] = bv;
            #pragma unroll 8
            for (int d = 0; d < DD; d++){
                float w = qW[d*(3*HHD) + j];
                #pragma unroll
                for (int rr = 0; rr < 8; rr++) a2[rr] += s[rr*DD + d] * w;
            }
            #pragma unroll
            for (int rr = 0; rr < 8; rr++) g_qkv[(long)(n0+rr)*(3*HHD) + j] = a2[rr];
        }
    }
    if (doOut && t < 8){
        float a = outb[0];
        #pragma unroll
        for (int d = 0; d < DD; d++) a += s[t*DD + d] * outW[d];
        out[n0 + t] = a;
    }
}

// ---------------- launcher (dual-stream pipeline) ----------------
extern "C" void kernel_launch(void* const* d_in, const int* in_sizes, int n_in,
                              void* d_out, int out_size){
    const float* nf    = (const float*)d_in[0];
    const float* amds  = (const float*)d_in[1];
    const float* embW  = (const float*)d_in[2];
    const float* embb  = (const float*)d_in[3];
    const float* bembW = (const float*)d_in[4];
    const float* bembb = (const float*)d_in[5];
    const float* ln1g  = (const float*)d_in[6];
    const float* ln1b  = (const float*)d_in[7];
    const float* ln2g  = (const float*)d_in[8];
    const float* ln2b  = (const float*)d_in[9];
    const float* qkvW  = (const float*)d_in[10];
    const float* qkvb  = (const float*)d_in[11];
    const float* diffW = (const float*)d_in[12];
    const float* diffb = (const float*)d_in[13];
    const float* oW    = (const float*)d_in[14];
    const float* ob    = (const float*)d_in[15];
    const float* boutW = (const float*)d_in[16];
    const float* boutb = (const float*)d_in[17];
    const float* outW  = (const float*)d_in[18];
    const float* outb  = (const float*)d_in[19];

    static int inited = 0;
    static cudaStream_t s1;
    static cudaEvent_t evBE[LAYERS], evAT[LAYERS], evJoin;
    if (!inited){
        cudaStreamCreateWithFlags(&s1, cudaStreamNonBlocking);
        for (int i = 0; i < LAYERS; i++){
            cudaEventCreateWithFlags(&evBE[i], cudaEventDisableTiming);
            cudaEventCreateWithFlags(&evAT[i], cudaEventDisableTiming);
        }
        cudaEventCreateWithFlags(&evJoin, cudaEventDisableTiming);
        cudaFuncSetAttribute(k_be, cudaFuncAttributeMaxDynamicSharedMemorySize, BE_SMEM);
        inited = 1;
    }

    k_wsplit<<<512, 256>>>(diffW, boutW);
    k_embed<<<NN_N, DD>>>(nf, amds, embW, embb, bembW, bembb, ln1g, ln1b);
    k_pq<<<NN_N/8, 512>>>(diffW);
    k_qkv<<<NN_N/8, 512>>>(qkvW, qkvb);

    float scale = 1.f / sqrtf((float)HD);
    for (int l = 0; l < LAYERS; l++){
        if (l >= 2) cudaStreamWaitEvent(0, evAT[l-2], 0);   // diffs buffer reuse guard
        k_be<<<NBLK, 256, BE_SMEM>>>(l, diffb + (long)l*HHD, boutb + (long)l*DD,
                                     l & 1, (l < LAYERS-1) ? 1 : 0,
                                     (l == 0) ? 1 : 0, l & 1);
        cudaEventRecord(evBE[l], 0);
        cudaStreamWaitEvent(s1, evBE[l], 0);
        k_attn<<<dim3(NN_N/16, HH), 512, 0, s1>>>(scale, l & 1);
        cudaEventRecord(evAT[l], s1);
        int last = (l == LAYERS-1);
        k_oln<<<NN_N/8, 512, 0, s1>>>(oW + (long)l*HHD*DD, ob + l*DD, ln2g, ln2b,
                                      qkvW + (long)(l+1)*DD*3*HHD,
                                      qkvb + (long)(l+1)*3*HHD, last ? 0 : 1,
                                      outW, outb, (float*)d_out, last);
    }
    cudaEventRecord(evJoin, s1);
    cudaStreamWaitEvent(0, evJoin, 0);
}

// round 15
// speedup vs baseline: 3.3406x; 1.0796x over previous
#include <cuda_runtime.h>
#include <cuda_fp16.h>
#include <math.h>
#include <stdint.h>

#define NN_N   512
#define FB     256
#define DD     64
#define HH     4
#define HD     128
#define HHD    512
#define LAYERS 4
#define KDIM   100
#define NPAIR  (NN_N*NN_N)
#define EPSV   1e-5f
#define ROWS   128
#define NBLK   (NPAIR/ROWS)      /* 2048 */
#define PADK   72                /* halves per smem row (conflict-free) */
#define QPAD   68                /* floats per QT smem row */

// ---------------- device scratch ----------------
__device__ float g_bias0[NPAIR*DD];
__device__ float g_bias1[NPAIR*DD];
__device__ float g_diffs[2*HH*NPAIR];   // double-buffered by layer parity
__device__ float g_x[NN_N*DD];
__device__ float g_b0[NN_N*DD];
__device__ float g_Q[NN_N*HHD];
__device__ float g_qkv[NN_N*3*HHD];
__device__ float g_vals[NN_N*HHD];
__device__ __align__(16) __half g_wimg[LAYERS*8*4*64*PADK];

// ---------------- helpers ----------------
__device__ __forceinline__ uint32_t smem_u32(const void* p){
    uint32_t a; asm("{ .reg .u64 t; cvta.to.shared.u64 t, %1; cvt.u32.u64 %0, t; }" : "=r"(a) : "l"(p));
    return a;
}
__device__ __forceinline__ float mish2(float x){
    float u = __expf(x);
    float t = fmaf(u, u, 2.f*u);
    return x * (1.f - __fdividef(2.f, t + 2.f));
}
__device__ __forceinline__ void mma16816(float (&d)[4], const uint32_t* a, const uint32_t* b){
    asm volatile("mma.sync.aligned.m16n8k16.row.col.f32.f16.f16.f32 "
        "{%0,%1,%2,%3}, {%4,%5,%6,%7}, {%8,%9}, {%0,%1,%2,%3};"
        : "+f"(d[0]), "+f"(d[1]), "+f"(d[2]), "+f"(d[3])
        : "r"(a[0]), "r"(a[1]), "r"(a[2]), "r"(a[3]), "r"(b[0]), "r"(b[1]));
}
#define LDSM4(R, addr) \
    asm volatile("ldmatrix.sync.aligned.m8n8.x4.shared.b16 {%0,%1,%2,%3}, [%4];" \
        : "=r"((R)[0]), "=r"((R)[1]), "=r"((R)[2]), "=r"((R)[3]) : "r"(addr))
__device__ __forceinline__ void cp16(uint32_t dst, const void* src){
    asm volatile("cp.async.ca.shared.global [%0], [%1], 16;" :: "r"(dst), "l"(src));
}
#define CP_COMMIT() asm volatile("cp.async.commit_group;" ::: "memory")
#define CP_WAIT1()  asm volatile("cp.async.wait_group 1;" ::: "memory")
#define CP_WAIT0()  asm volatile("cp.async.wait_group 0;" ::: "memory")

// fp16 2-product GEMM: A single plane (hi), B hi/lo split.
// residual = A_lo·B ~ 2^-11 random data perturbation — diluted downstream.
__device__ __forceinline__ void mma_gemm_ld2(uint32_t sAh,
                                             uint32_t sBh, uint32_t sBl,
                                             float (&d)[2][4][4],
                                             int lane, int wrow, int wcol){
    int lrow = lane & 7, seg = lane >> 3;
    int rsel = (seg & 1) << 3;
    int csel = (seg & 2) << 2;
    #pragma unroll
    for (int k0 = 0; k0 < 64; k0 += 16){
        uint32_t ah[2][4], bh[2][4], bl[2][4];
        #pragma unroll
        for (int ma = 0; ma < 2; ma++){
            int r = wrow*32 + ma*16 + lrow + rsel;
            uint32_t off = (uint32_t)((r*PADK + k0 + csel) * 2);
            LDSM4(ah[ma], sAh + off);
        }
        #pragma unroll
        for (int nb = 0; nb < 2; nb++){
            int n = wcol*32 + nb*16 + lrow + rsel;
            uint32_t off = (uint32_t)((n*PADK + k0 + csel) * 2);
            LDSM4(bh[nb], sBh + off);
            LDSM4(bl[nb], sBl + off);
        }
        #pragma unroll
        for (int ma = 0; ma < 2; ma++)
            #pragma unroll
            for (int nb = 0; nb < 2; nb++)
                #pragma unroll
                for (int j = 0; j < 2; j++){
                    int na = nb*2 + j;
                    uint32_t Bh[2] = { bh[nb][j], bh[nb][2+j] };
                    uint32_t Bl[2] = { bl[nb][j], bl[nb][2+j] };
                    mma16816(d[ma][na], ah[ma], Bh);
                    mma16816(d[ma][na], ah[ma], Bl);
                }
    }
}

// ---------------- K0: weight split into combined images ----------------
__global__ void k_wsplit(const float* __restrict__ dW, const float* __restrict__ bW){
    int idx = blockIdx.x*256 + threadIdx.x;     // 131072
    int k = idx & 63;
    int n = (idx>>6) & 63;
    int c = (idx>>12) & 7;
    int l = idx>>15;
    long base = ((long)(l*8 + c)*4)*64*PADK;
    long e = (long)n*PADK + k;
    float v1 = dW[(long)l*DD*HHD + (long)k*HHD + c*64 + n];   // W1^T[n][k]
    __half h1 = __float2half_rn(v1);
    g_wimg[base + e] = h1;
    g_wimg[base + 64*PADK + e] = __float2half_rn(v1 - __half2float(h1));
    float v2 = bW[(long)l*HHD*DD + (long)(c*64 + k)*DD + n];  // W2^T[n][j]
    __half h2 = __float2half_rn(v2);
    g_wimg[base + 2*64*PADK + e] = h2;
    g_wimg[base + 3*64*PADK + e] = __float2half_rn(v2 - __half2float(h2));
}

// ---------------- K1: embeddings + LN1 ----------------
__global__ void k_embed(const float* __restrict__ nf, const float* __restrict__ am,
                        const float* __restrict__ eW, const float* __restrict__ eb,
                        const float* __restrict__ bW, const float* __restrict__ bbv,
                        const float* __restrict__ g1, const float* __restrict__ b1){
    int n = blockIdx.x, d = threadIdx.x;
    float acc = eb[d];
    for (int f = 0; f < FB; f++) acc += nf[n*FB + f] * eW[f*DD + d];
    float b0 = bbv[d];
    for (int k = 0; k < KDIM; k++) b0 += am[n*KDIM + k] * bW[k*DD + d];
    g_b0[n*DD + d] = b0;
    __shared__ float s[DD];
    s[d] = acc; __syncthreads();
    float mu = 0.f;
    #pragma unroll
    for (int k = 0; k < DD; k++) mu += s[k];
    mu *= (1.f/DD);
    float var = 0.f;
    #pragma unroll
    for (int k = 0; k < DD; k++){ float dd = s[k]-mu; var += dd*dd; }
    var *= (1.f/DD);
    g_x[n*DD + d] = (acc - mu) * rsqrtf(var + EPSV) * g1[d] + b1[d];
}

// ---------------- K2: Q = b0 @ diffW_layer0 ----------------
__global__ void __launch_bounds__(512,1)
k_pq(const float* __restrict__ W){
    int n0 = blockIdx.x * 8;
    __shared__ float xs[8*DD];
    int t = threadIdx.x;
    xs[t] = g_b0[n0*DD + t];
    __syncthreads();
    int j = t;
    float acc[8];
    #pragma unroll
    for (int r = 0; r < 8; r++) acc[r] = 0.f;
    #pragma unroll 8
    for (int d = 0; d < DD; d++){
        float w = W[d*HHD + j];
        #pragma unroll
        for (int r = 0; r < 8; r++) acc[r] += xs[r*DD + d] * w;
    }
    #pragma unroll
    for (int r = 0; r < 8; r++) g_Q[(long)(n0+r)*HHD + j] = acc[r];
}

// ---------------- K3: qkv (layer 0 only) ----------------
__global__ void __launch_bounds__(512,1)
k_qkv(const float* __restrict__ W, const float* __restrict__ b){
    int n0 = blockIdx.x * 8;
    __shared__ float xs[8*DD];
    int t = threadIdx.x;
    xs[t] = g_x[n0*DD + t];
    __syncthreads();
    for (int j = t; j < 3*HHD; j += 512){
        float acc[8];
        float bv = b[j];
        #pragma unroll
        for (int r = 0; r < 8; r++) acc[r] = bv;
        #pragma unroll 8
        for (int d = 0; d < DD; d++){
            float w = W[d*(3*HHD) + j];
            #pragma unroll
            for (int r = 0; r < 8; r++) acc[r] += xs[r*DD + d] * w;
        }
        #pragma unroll
        for (int r = 0; r < 8; r++) g_qkv[(long)(n0+r)*(3*HHD) + j] = acc[r];
    }
}

// ---------------- K4: HMMA fused be kernel, 2 CTAs/SM ----------------
// smem bytes: A_hi 18432, W1 18432, W2 18432, E_hi 18432, sq 512
// (layer0 QT 34816 bytes overlays A_hi+W1 — both unused on L0)
#define SA_H    0
#define SW1     18432          /* w1h @ +0, w1l @ +9216 */
#define SW2     36864          /* w2h @ +0, w2l @ +9216 */
#define SE_H    55296
#define WPLANE  9216
#define WCHUNK  36864
#define SQ_OFF  73728
#define BE_SMEM (73728 + 512)

__global__ void __launch_bounds__(256,2)
k_be(int l, const float* __restrict__ db, const float* __restrict__ bb,
     int flip, int writeBias, int isL0, int dbuf){
    extern __shared__ __half smh[];
    float* sq = (float*)((char*)smh + SQ_OFF);
    float* QT = (float*)smh;
    uint32_t sbase = smem_u32(smh);
    int t = threadIdx.x, w = t>>5, lane = t&31;
    int wrow = w>>1, wcol = w&1;
    int q = lane>>2, qt = lane&3;
    long blk = blockIdx.x;
    long pair0 = blk * ROWS;
    int nrow   = (int)(blk >> 2);
    int m_base = (int)(blk & 3) * ROWS;
    float* dif = g_diffs + (long)dbuf*HH*NPAIR;

    const float* bin  = (flip ? g_bias1 : g_bias0) + pair0*DD;
    float*       bnew = (flip ? g_bias0 : g_bias1) + pair0*DD;
    const char*  wsrc = (const char*)g_wimg + (long)(l*8)*WCHUNK;

    // prologue
    if (isL0){
        for (int i = t; i < 2048; i += 256){
            int r = i >> 4, f4 = i & 15;
            cp16(sbase + (uint32_t)((r*QPAD + f4*4)*4),
                 g_Q + (long)(m_base + r)*HHD + f4*4);
        }
        CP_COMMIT();
        for (int i = t; i < 1152; i += 256) cp16(sbase + SW2 + i*16, wsrc + 2*WPLANE + i*16);
        CP_COMMIT();
    } else {
        for (int i = t; i < 1152; i += 256) cp16(sbase + SW1 + i*16, wsrc + i*16);
        CP_COMMIT();
        if (writeBias){
            for (int i = t; i < 1152; i += 256) cp16(sbase + SW2 + i*16, wsrc + 2*WPLANE + i*16);
            CP_COMMIT();
        }
        for (int i = t; i < 2048; i += 256){   // bias tile -> A_hi plane only
            int r = i >> 4, c4 = (i & 15)*4;
            float4 v = ((const float4*)bin)[i];
            __half2 h0 = __floats2half2_rn(v.x, v.y);
            __half2 h1 = __floats2half2_rn(v.z, v.w);
            __half2* dh = (__half2*)((char*)smh + SA_H + (r*PADK + c4)*2);
            dh[0] = h0; dh[1] = h1;
        }
    }
    if (t < 128) sq[t] = 0.f;

    float acc2[2][4][4];
    #pragma unroll
    for (int ma = 0; ma < 2; ma++)
        #pragma unroll
        for (int na = 0; na < 4; na++)
            #pragma unroll
            for (int i = 0; i < 4; i++) acc2[ma][na][i] = 0.f;

    for (int c = 0; c < 8; c++){
        if (writeBias) CP_WAIT1(); else CP_WAIT0();
        __syncthreads();

        float d1[2][4][4];
        if (isL0){
            float qnv[8];
            #pragma unroll
            for (int na = 0; na < 4; na++){
                int colp = wcol*32 + na*8 + qt*2;
                qnv[2*na]   = __ldg(&g_Q[(long)nrow*HHD + c*64 + colp]);
                qnv[2*na+1] = __ldg(&g_Q[(long)nrow*HHD + c*64 + colp + 1]);
            }
            #pragma unroll
            for (int ma = 0; ma < 2; ma++){
                int r0 = wrow*32 + ma*16 + q;
                #pragma unroll
                for (int na = 0; na < 4; na++){
                    int colp = wcol*32 + na*8 + qt*2;
                    d1[ma][na][0] = QT[r0*QPAD + colp]     - qnv[2*na];
                    d1[ma][na][1] = QT[r0*QPAD + colp + 1] - qnv[2*na+1];
                    d1[ma][na][2] = QT[(r0+8)*QPAD + colp]     - qnv[2*na];
                    d1[ma][na][3] = QT[(r0+8)*QPAD + colp + 1] - qnv[2*na+1];
                }
            }
            __syncthreads();
            if (c < 7)
                for (int i = t; i < 2048; i += 256){
                    int r = i >> 4, f4 = i & 15;
                    cp16(sbase + (uint32_t)((r*QPAD + f4*4)*4),
                         g_Q + (long)(m_base + r)*HHD + (c+1)*64 + f4*4);
                }
            CP_COMMIT();
        } else {
            #pragma unroll
            for (int ma = 0; ma < 2; ma++)
                #pragma unroll
                for (int na = 0; na < 4; na++)
                    #pragma unroll
                    for (int i = 0; i < 4; i++) d1[ma][na][i] = 0.f;
            mma_gemm_ld2(sbase + SA_H, sbase + SW1, sbase + SW1 + WPLANE,
                         d1, lane, wrow, wcol);
            __syncthreads();
            if (c < 7)
                for (int i = t; i < 1152; i += 256)
                    cp16(sbase + SW1 + i*16, wsrc + (long)(c+1)*WCHUNK + i*16);
            CP_COMMIT();
        }

        // epilogue: +db, mish, sq partials (+ E_hi plane store only if GEMM2 follows)
        float dbv[8];
        #pragma unroll
        for (int na = 0; na < 4; na++){
            int colp = wcol*32 + na*8 + qt*2;
            dbv[2*na]   = __ldg(&db[c*64 + colp]);
            dbv[2*na+1] = __ldg(&db[c*64 + colp + 1]);
        }
        float rs[2][2] = {{0.f,0.f},{0.f,0.f}};
        #pragma unroll
        for (int ma = 0; ma < 2; ma++){
            int row0 = wrow*32 + ma*16 + q;
            #pragma unroll
            for (int na = 0; na < 4; na++){
                int colp = wcol*32 + na*8 + qt*2;
                float m0 = mish2(d1[ma][na][0] + dbv[2*na]);
                float m1 = mish2(d1[ma][na][1] + dbv[2*na+1]);
                float m2 = mish2(d1[ma][na][2] + dbv[2*na]);
                float m3 = mish2(d1[ma][na][3] + dbv[2*na+1]);
                rs[ma][0] = fmaf(m0,m0, fmaf(m1,m1, rs[ma][0]));
                rs[ma][1] = fmaf(m2,m2, fmaf(m3,m3, rs[ma][1]));
                if (writeBias){
                    __half2 h01 = __floats2half2_rn(m0, m1);
                    __half2 h23 = __floats2half2_rn(m2, m3);
                    *(__half2*)((char*)smh + SE_H + (row0*PADK + colp)*2)     = h01;
                    *(__half2*)((char*)smh + SE_H + ((row0+8)*PADK + colp)*2) = h23;
                }
            }
        }
        #pragma unroll
        for (int ma = 0; ma < 2; ma++)
            #pragma unroll
            for (int hh = 0; hh < 2; hh++){
                float s = rs[ma][hh];
                s += __shfl_xor_sync(0xffffffffu, s, 1);
                s += __shfl_xor_sync(0xffffffffu, s, 2);
                if (qt == 0) atomicAdd(&sq[wrow*32 + ma*16 + q + hh*8], s);
            }

        if (writeBias){
            CP_WAIT1();
            __syncthreads();           // E_hi + sq visible, w2 ready
            mma_gemm_ld2(sbase + SE_H, sbase + SW2, sbase + SW2 + WPLANE,
                         acc2, lane, wrow, wcol);
            __syncthreads();
            if (c < 7)
                for (int i = t; i < 1152; i += 256)
                    cp16(sbase + SW2 + i*16, wsrc + (long)(c+1)*WCHUNK + 2*WPLANE + i*16);
            CP_COMMIT();
            if (c & 1){
                if (t < 128){
                    dif[(long)(c>>1)*NPAIR + pair0 + t] = sqrtf(sq[t]);
                    sq[t] = 0.f;
                }
            }
        } else {
            if (c & 1){
                __syncthreads();       // order atomicAdds before read/reset
                if (t < 128){
                    dif[(long)(c>>1)*NPAIR + pair0 + t] = sqrtf(sq[t]);
                    sq[t] = 0.f;
                }
            }
        }
    }

    // final: bias' = mish(acc2 + bb)
    if (writeBias){
        #pragma unroll
        for (int ma = 0; ma < 2; ma++){
            #pragma unroll
            for (int na = 0; na < 4; na++){
                int colp = wcol*32 + na*8 + qt*2;
                float bb0 = __ldg(&bb[colp]);
                float bb1 = __ldg(&bb[colp + 1]);
                int row0 = wrow*32 + ma*16 + q;
                float2 v0 = { mish2(acc2[ma][na][0] + bb0), mish2(acc2[ma][na][1] + bb1) };
                float2 v1 = { mish2(acc2[ma][na][2] + bb0), mish2(acc2[ma][na][3] + bb1) };
                *(float2*)&bnew[(long)row0*DD + colp]     = v0;
                *(float2*)&bnew[(long)(row0+8)*DD + colp] = v1;
            }
        }
    }
}

// ---------------- K5: attention ----------------
__global__ void __launch_bounds__(512,1) k_attn(float scale, int dbuf){
    int h  = blockIdx.y;
    int n0 = blockIdx.x * 16;
    __shared__ float qS[16*HD];
    __shared__ float lg[16*NN_N];
    int t = threadIdx.x;
    const float* dif = g_diffs + (long)dbuf*HH*NPAIR;

    for (int idx = t; idx < 16*HD; idx += 512){
        int nn = idx >> 7, d = idx & 127;
        qS[idx] = g_qkv[(long)(n0+nn)*(3*HHD) + h*384 + d];
    }
    __syncthreads();
    {
        int m = t;
        float acc[16];
        #pragma unroll
        for (int nn = 0; nn < 16; nn++) acc[nn] = 0.f;
        const float* kp = g_qkv + (long)m*(3*HHD) + h*384 + 128;
        #pragma unroll 4
        for (int d = 0; d < HD; d += 4){
            float4 kv = *(const float4*)(kp + d);
            #pragma unroll
            for (int nn = 0; nn < 16; nn++){
                float4 qv = *(const float4*)&qS[nn*HD + d];
                acc[nn] += qv.x*kv.x + qv.y*kv.y + qv.z*kv.z + qv.w*kv.w;
            }
        }
        const float* dp = dif + (long)h*NPAIR + (long)n0*NN_N + m;
        #pragma unroll
        for (int nn = 0; nn < 16; nn++)
            lg[nn*NN_N + m] = acc[nn]*scale + dp[(long)nn*NN_N];
    }
    __syncthreads();
    {
        int row = t >> 5, lane = t & 31;
        float* Lr = lg + row*NN_N;
        float mx = -1e30f;
        for (int m = lane; m < NN_N; m += 32) mx = fmaxf(mx, Lr[m]);
        #pragma unroll
        for (int o = 16; o; o >>= 1) mx = fmaxf(mx, __shfl_xor_sync(0xffffffffu, mx, o));
        float sum = 0.f;
        for (int m = lane; m < NN_N; m += 32){
            float e = __expf(Lr[m] - mx); Lr[m] = e; sum += e;
        }
        #pragma unroll
        for (int o = 16; o; o >>= 1) sum += __shfl_xor_sync(0xffffffffu, sum, o);
        float inv = 1.f / sum;
        for (int m = lane; m < NN_N; m += 32) Lr[m] *= inv;
    }
    __syncthreads();
    {
        int d = t & 127, ng = t >> 7;
        float acc[4] = {0.f, 0.f, 0.f, 0.f};
        const float* vp = g_qkv + h*384 + 256 + d;
        #pragma unroll 4
        for (int m = 0; m < NN_N; m++){
            float vv = vp[(long)m*(3*HHD)];
            #pragma unroll
            for (int k = 0; k < 4; k++) acc[k] += lg[(ng*4+k)*NN_N + m] * vv;
        }
        #pragma unroll
        for (int k = 0; k < 4; k++)
            g_vals[(long)(n0 + ng*4 + k)*HHD + h*HD + d] = acc[k];
    }
}

// ---------------- K5b: oln + fused next-layer qkv / final out ----------------
__global__ void __launch_bounds__(512,1)
k_oln(const float* __restrict__ oW, const float* __restrict__ ob,
      const float* __restrict__ g2, const float* __restrict__ b2,
      const float* __restrict__ qW, const float* __restrict__ qb, int doQkv,
      const float* __restrict__ outW, const float* __restrict__ outb,
      float* __restrict__ out, int doOut){
    int n0 = blockIdx.x * 8;
    __shared__ float vs[8*HHD];
    __shared__ float s[8*DD];
    int t = threadIdx.x;
    for (int i = t; i < 8*HHD/4; i += 512)
        ((float4*)vs)[i] = ((const float4*)(g_vals + (long)n0*HHD))[i];
    __syncthreads();
    int r = t >> 6, i = t & 63;
    float acc = 0.f;
    #pragma unroll 8
    for (int j = 0; j < HHD; j++)
        acc += vs[r*HHD + j] * oW[j*DD + i];
    float xv = g_x[(n0+r)*DD + i] + acc + ob[i];
    s[r*DD + i] = xv;
    __syncthreads();
    float mu = 0.f;
    #pragma unroll
    for (int k = 0; k < DD; k++) mu += s[r*DD + k];
    mu *= (1.f/DD);
    float var = 0.f;
    #pragma unroll
    for (int k = 0; k < DD; k++){ float dd = s[r*DD + k]-mu; var += dd*dd; }
    var *= (1.f/DD);
    float xn = (xv - mu) * rsqrtf(var + EPSV) * g2[i] + b2[i];
    g_x[(n0+r)*DD + i] = xn;
    __syncthreads();
    s[r*DD + i] = xn;
    __syncthreads();
    if (doQkv){
        for (int j = t; j < 3*HHD; j += 512){
            float a2[8];
            float bv = qb[j];
            #pragma unroll
            for (int rr = 0; rr < 8; rr++) a2[rr] = bv;
            #pragma unroll 8
            for (int d = 0; d < DD; d++){
                float w = qW[d*(3*HHD) + j];
                #pragma unroll
                for (int rr = 0; rr < 8; rr++) a2[rr] += s[rr*DD + d] * w;
            }
            #pragma unroll
            for (int rr = 0; rr < 8; rr++) g_qkv[(long)(n0+rr)*(3*HHD) + j] = a2[rr];
        }
    }
    if (doOut && t < 8){
        float a = outb[0];
        #pragma unroll
        for (int d = 0; d < DD; d++) a += s[t*DD + d] * outW[d];
        out[n0 + t] = a;
    }
}

// ---------------- launcher (dual-stream pipeline) ----------------
extern "C" void kernel_launch(void* const* d_in, const int* in_sizes, int n_in,
                              void* d_out, int out_size){
    const float* nf    = (const float*)d_in[0];
    const float* amds  = (const float*)d_in[1];
    const float* embW  = (const float*)d_in[2];
    const float* embb  = (const float*)d_in[3];
    const float* bembW = (const float*)d_in[4];
    const float* bembb = (const float*)d_in[5];
    const float* ln1g  = (const float*)d_in[6];
    const float* ln1b  = (const float*)d_in[7];
    const float* ln2g  = (const float*)d_in[8];
    const float* ln2b  = (const float*)d_in[9];
    const float* qkvW  = (const float*)d_in[10];
    const float* qkvb  = (const float*)d_in[11];
    const float* diffW = (const float*)d_in[12];
    const float* diffb = (const float*)d_in[13];
    const float* oW    = (const float*)d_in[14];
    const float* ob    = (const float*)d_in[15];
    const float* boutW = (const float*)d_in[16];
    const float* boutb = (const float*)d_in[17];
    const float* outW  = (const float*)d_in[18];
    const float* outb  = (const float*)d_in[19];

    static int inited = 0;
    static cudaStream_t s1;
    static cudaEvent_t evBE[LAYERS], evAT[LAYERS], evJoin;
    if (!inited){
        cudaStreamCreateWithFlags(&s1, cudaStreamNonBlocking);
        for (int i = 0; i < LAYERS; i++){
            cudaEventCreateWithFlags(&evBE[i], cudaEventDisableTiming);
            cudaEventCreateWithFlags(&evAT[i], cudaEventDisableTiming);
        }
        cudaEventCreateWithFlags(&evJoin, cudaEventDisableTiming);
        cudaFuncSetAttribute(k_be, cudaFuncAttributeMaxDynamicSharedMemorySize, BE_SMEM);
        inited = 1;
    }

    k_wsplit<<<512, 256>>>(diffW, boutW);
    k_embed<<<NN_N, DD>>>(nf, amds, embW, embb, bembW, bembb, ln1g, ln1b);
    k_pq<<<NN_N/8, 512>>>(diffW);
    k_qkv<<<NN_N/8, 512>>>(qkvW, qkvb);

    float scale = 1.f / sqrtf((float)HD);
    for (int l = 0; l < LAYERS; l++){
        if (l >= 2) cudaStreamWaitEvent(0, evAT[l-2], 0);   // diffs buffer reuse guard
        k_be<<<NBLK, 256, BE_SMEM>>>(l, diffb + (long)l*HHD, boutb + (long)l*DD,
                                     l & 1, (l < LAYERS-1) ? 1 : 0,
                                     (l == 0) ? 1 : 0, l & 1);
        cudaEventRecord(evBE[l], 0);
        cudaStreamWaitEvent(s1, evBE[l], 0);
        k_attn<<<dim3(NN_N/16, HH), 512, 0, s1>>>(scale, l & 1);
        cudaEventRecord(evAT[l], s1);
        int last = (l == LAYERS-1);
        k_oln<<<NN_N/8, 512, 0, s1>>>(oW + (long)l*HHD*DD, ob + l*DD, ln2g, ln2b,
                                      qkvW + (long)(l+1)*DD*3*HHD,
                                      qkvb + (long)(l+1)*3*HHD, last ? 0 : 1,
                                      outW, outb, (float*)d_out, last);
    }
    cudaEventRecord(evJoin, s1);
    cudaStreamWaitEvent(0, evJoin, 0);
}

// round 16
// speedup vs baseline: 4.1876x; 1.2535x over previous
#include <cuda_runtime.h>
#include <cuda_fp16.h>
#include <math.h>
#include <stdint.h>

#define NN_N   512
#define FB     256
#define DD     64
#define HH     4
#define HD     128
#define HHD    512
#define LAYERS 4
#define KDIM   100
#define NPAIR  (NN_N*NN_N)
#define EPSV   1e-5f
#define ROWS   128
#define NBLK   (NPAIR/ROWS)      /* 2048 */
#define PADK   72                /* halves per smem/image row (conflict-free) */
#define QPAD   68                /* floats per QT smem row */

// ---------------- device scratch ----------------
// bias ping-pong stored as fp16 images in ldmatrix layout: [blk][128 rows][PADK]
__device__ __align__(16) __half g_biasH0[NBLK*ROWS*PADK];
__device__ __align__(16) __half g_biasH1[NBLK*ROWS*PADK];
__device__ float g_diffs[2*HH*NPAIR];   // double-buffered by layer parity
__device__ float g_x[NN_N*DD];
__device__ float g_b0[NN_N*DD];
__device__ float g_Q[NN_N*HHD];
__device__ float g_qkv[NN_N*3*HHD];
__device__ float g_vals[NN_N*HHD];
// weight images (hi planes only): [l][chunk][plane(2: w1h,w2h)][64 n][72 k] halves
__device__ __align__(16) __half g_wimg[LAYERS*8*2*64*PADK];

// ---------------- helpers ----------------
__device__ __forceinline__ uint32_t smem_u32(const void* p){
    uint32_t a; asm("{ .reg .u64 t; cvta.to.shared.u64 t, %1; cvt.u32.u64 %0, t; }" : "=r"(a) : "l"(p));
    return a;
}
__device__ __forceinline__ float mish2(float x){
    float u = __expf(x);
    float t = fmaf(u, u, 2.f*u);
    return x * (1.f - __fdividef(2.f, t + 2.f));
}
__device__ __forceinline__ void mma16816(float (&d)[4], const uint32_t* a, const uint32_t* b){
    asm volatile("mma.sync.aligned.m16n8k16.row.col.f32.f16.f16.f32 "
        "{%0,%1,%2,%3}, {%4,%5,%6,%7}, {%8,%9}, {%0,%1,%2,%3};"
        : "+f"(d[0]), "+f"(d[1]), "+f"(d[2]), "+f"(d[3])
        : "r"(a[0]), "r"(a[1]), "r"(a[2]), "r"(a[3]), "r"(b[0]), "r"(b[1]));
}
#define LDSM4(R, addr) \
    asm volatile("ldmatrix.sync.aligned.m8n8.x4.shared.b16 {%0,%1,%2,%3}, [%4];" \
        : "=r"((R)[0]), "=r"((R)[1]), "=r"((R)[2]), "=r"((R)[3]) : "r"(addr))
__device__ __forceinline__ void cp16(uint32_t dst, const void* src){
    asm volatile("cp.async.ca.shared.global [%0], [%1], 16;" :: "r"(dst), "l"(src));
}
#define CP_COMMIT() asm volatile("cp.async.commit_group;" ::: "memory")
#define CP_WAIT1()  asm volatile("cp.async.wait_group 1;" ::: "memory")
#define CP_WAIT0()  asm volatile("cp.async.wait_group 0;" ::: "memory")

// single-product fp16 GEMM: D += A_hi @ B_h^T
__device__ __forceinline__ void mma_gemm_ld1(uint32_t sAh, uint32_t sBh,
                                             float (&d)[2][4][4],
                                             int lane, int wrow, int wcol){
    int lrow = lane & 7, seg = lane >> 3;
    int rsel = (seg & 1) << 3;
    int csel = (seg & 2) << 2;
    #pragma unroll
    for (int k0 = 0; k0 < 64; k0 += 16){
        uint32_t ah[2][4], bh[2][4];
        #pragma unroll
        for (int ma = 0; ma < 2; ma++){
            int r = wrow*32 + ma*16 + lrow + rsel;
            LDSM4(ah[ma], sAh + (uint32_t)((r*PADK + k0 + csel) * 2));
        }
        #pragma unroll
        for (int nb = 0; nb < 2; nb++){
            int n = wcol*32 + nb*16 + lrow + rsel;
            LDSM4(bh[nb], sBh + (uint32_t)((n*PADK + k0 + csel) * 2));
        }
        #pragma unroll
        for (int ma = 0; ma < 2; ma++)
            #pragma unroll
            for (int nb = 0; nb < 2; nb++)
                #pragma unroll
                for (int j = 0; j < 2; j++){
                    uint32_t Bh[2] = { bh[nb][j], bh[nb][2+j] };
                    mma16816(d[ma][nb*2+j], ah[ma], Bh);
                }
    }
}

// ---------------- K0: weight hi-plane images ----------------
__global__ void k_wsplit(const float* __restrict__ dW, const float* __restrict__ bW){
    int idx = blockIdx.x*256 + threadIdx.x;     // 131072
    int k = idx & 63;
    int n = (idx>>6) & 63;
    int c = (idx>>12) & 7;
    int l = idx>>15;
    long base = ((long)(l*8 + c)*2)*64*PADK;
    long e = (long)n*PADK + k;
    float v1 = dW[(long)l*DD*HHD + (long)k*HHD + c*64 + n];   // W1^T[n][k]
    g_wimg[base + e] = __float2half_rn(v1);
    float v2 = bW[(long)l*HHD*DD + (long)(c*64 + k)*DD + n];  // W2^T[n][j]
    g_wimg[base + 64*PADK + e] = __float2half_rn(v2);
}

// ---------------- K1: embeddings + LN1 ----------------
__global__ void k_embed(const float* __restrict__ nf, const float* __restrict__ am,
                        const float* __restrict__ eW, const float* __restrict__ eb,
                        const float* __restrict__ bW, const float* __restrict__ bbv,
                        const float* __restrict__ g1, const float* __restrict__ b1){
    int n = blockIdx.x, d = threadIdx.x;
    float acc = eb[d];
    for (int f = 0; f < FB; f++) acc += nf[n*FB + f] * eW[f*DD + d];
    float b0 = bbv[d];
    for (int k = 0; k < KDIM; k++) b0 += am[n*KDIM + k] * bW[k*DD + d];
    g_b0[n*DD + d] = b0;
    __shared__ float s[DD];
    s[d] = acc; __syncthreads();
    float mu = 0.f;
    #pragma unroll
    for (int k = 0; k < DD; k++) mu += s[k];
    mu *= (1.f/DD);
    float var = 0.f;
    #pragma unroll
    for (int k = 0; k < DD; k++){ float dd = s[k]-mu; var += dd*dd; }
    var *= (1.f/DD);
    g_x[n*DD + d] = (acc - mu) * rsqrtf(var + EPSV) * g1[d] + b1[d];
}

// ---------------- K2: Q = b0 @ diffW_layer0 ----------------
__global__ void __launch_bounds__(512,1)
k_pq(const float* __restrict__ W){
    int n0 = blockIdx.x * 8;
    __shared__ float xs[8*DD];
    int t = threadIdx.x;
    xs[t] = g_b0[n0*DD + t];
    __syncthreads();
    int j = t;
    float acc[8];
    #pragma unroll
    for (int r = 0; r < 8; r++) acc[r] = 0.f;
    #pragma unroll 8
    for (int d = 0; d < DD; d++){
        float w = W[d*HHD + j];
        #pragma unroll
        for (int r = 0; r < 8; r++) acc[r] += xs[r*DD + d] * w;
    }
    #pragma unroll
    for (int r = 0; r < 8; r++) g_Q[(long)(n0+r)*HHD + j] = acc[r];
}

// ---------------- K3: qkv (layer 0 only) ----------------
__global__ void __launch_bounds__(512,1)
k_qkv(const float* __restrict__ W, const float* __restrict__ b){
    int n0 = blockIdx.x * 8;
    __shared__ float xs[8*DD];
    int t = threadIdx.x;
    xs[t] = g_x[n0*DD + t];
    __syncthreads();
    for (int j = t; j < 3*HHD; j += 512){
        float acc[8];
        float bv = b[j];
        #pragma unroll
        for (int r = 0; r < 8; r++) acc[r] = bv;
        #pragma unroll 8
        for (int d = 0; d < DD; d++){
            float w = W[d*(3*HHD) + j];
            #pragma unroll
            for (int r = 0; r < 8; r++) acc[r] += xs[r*DD + d] * w;
        }
        #pragma unroll
        for (int r = 0; r < 8; r++) g_qkv[(long)(n0+r)*(3*HHD) + j] = acc[r];
    }
}

// ---------------- K4: single-product HMMA fused be kernel, 2 CTAs/SM ----------------
// smem bytes: A_hi 18432 @0, W1h 9216 @18432, [pad 9216], W2h 9216 @36864,
// E_hi 18432 @46080, sq @64512.  Layer0 QT (34816 B) overlays 0..34816 (A+W1+pad).
#define SA_H    0
#define SW1     18432
#define SW2     36864
#define SE_H    46080
#define WPLANE  9216
#define WCHUNK  18432          /* bytes per (l,chunk) 2-plane image */
#define SQ_OFF  64512
#define BE_SMEM (64512 + 512)

__global__ void __launch_bounds__(256,2)
k_be(int l, const float* __restrict__ db, const float* __restrict__ bb,
     int flip, int writeBias, int isL0, int dbuf){
    extern __shared__ __half smh[];
    float* sq = (float*)((char*)smh + SQ_OFF);
    float* QT = (float*)smh;
    uint32_t sbase = smem_u32(smh);
    int t = threadIdx.x, w = t>>5, lane = t&31;
    int wrow = w>>1, wcol = w&1;
    int q = lane>>2, qt = lane&3;
    long blk = blockIdx.x;
    long pair0 = blk * ROWS;
    int nrow   = (int)(blk >> 2);
    int m_base = (int)(blk & 3) * ROWS;
    float* dif = g_diffs + (long)dbuf*HH*NPAIR;

    const __half* binH  = (flip ? g_biasH1 : g_biasH0) + blk*(ROWS*PADK);
    __half*       bnewH = (flip ? g_biasH0 : g_biasH1) + blk*(ROWS*PADK);
    const char*   wsrc  = (const char*)g_wimg + (long)(l*8)*WCHUNK;

    // prologue: group1 = [A image + W1(0)] (or QT(0) on L0); group2 = W2(0)
    if (isL0){
        for (int i = t; i < 2048; i += 256){
            int r = i >> 4, f4 = i & 15;
            cp16(sbase + (uint32_t)((r*QPAD + f4*4)*4),
                 g_Q + (long)(m_base + r)*HHD + f4*4);
        }
        CP_COMMIT();
        for (int i = t; i < 576; i += 256) cp16(sbase + SW2 + i*16, wsrc + WPLANE + i*16);
        CP_COMMIT();
    } else {
        for (int i = t; i < 1152; i += 256) cp16(sbase + SA_H + i*16, (const char*)binH + i*16);
        for (int i = t; i < 576; i += 256)  cp16(sbase + SW1 + i*16, wsrc + i*16);
        CP_COMMIT();
        if (writeBias){
            for (int i = t; i < 576; i += 256) cp16(sbase + SW2 + i*16, wsrc + WPLANE + i*16);
            CP_COMMIT();
        }
    }
    if (t < 128) sq[t] = 0.f;

    float acc2[2][4][4];
    #pragma unroll
    for (int ma = 0; ma < 2; ma++)
        #pragma unroll
        for (int na = 0; na < 4; na++)
            #pragma unroll
            for (int i = 0; i < 4; i++) acc2[ma][na][i] = 0.f;

    for (int c = 0; c < 8; c++){
        if (writeBias) CP_WAIT1(); else CP_WAIT0();
        __syncthreads();

        float d1[2][4][4];
        if (isL0){
            float qnv[8];
            #pragma unroll
            for (int na = 0; na < 4; na++){
                int colp = wcol*32 + na*8 + qt*2;
                qnv[2*na]   = __ldg(&g_Q[(long)nrow*HHD + c*64 + colp]);
                qnv[2*na+1] = __ldg(&g_Q[(long)nrow*HHD + c*64 + colp + 1]);
            }
            #pragma unroll
            for (int ma = 0; ma < 2; ma++){
                int r0 = wrow*32 + ma*16 + q;
                #pragma unroll
                for (int na = 0; na < 4; na++){
                    int colp = wcol*32 + na*8 + qt*2;
                    d1[ma][na][0] = QT[r0*QPAD + colp]     - qnv[2*na];
                    d1[ma][na][1] = QT[r0*QPAD + colp + 1] - qnv[2*na+1];
                    d1[ma][na][2] = QT[(r0+8)*QPAD + colp]     - qnv[2*na];
                    d1[ma][na][3] = QT[(r0+8)*QPAD + colp + 1] - qnv[2*na+1];
                }
            }
            __syncthreads();
            if (c < 7)
                for (int i = t; i < 2048; i += 256){
                    int r = i >> 4, f4 = i & 15;
                    cp16(sbase + (uint32_t)((r*QPAD + f4*4)*4),
                         g_Q + (long)(m_base + r)*HHD + (c+1)*64 + f4*4);
                }
            CP_COMMIT();
        } else {
            #pragma unroll
            for (int ma = 0; ma < 2; ma++)
                #pragma unroll
                for (int na = 0; na < 4; na++)
                    #pragma unroll
                    for (int i = 0; i < 4; i++) d1[ma][na][i] = 0.f;
            mma_gemm_ld1(sbase + SA_H, sbase + SW1, d1, lane, wrow, wcol);
            __syncthreads();
            if (c < 7)
                for (int i = t; i < 576; i += 256)
                    cp16(sbase + SW1 + i*16, wsrc + (long)(c+1)*WCHUNK + i*16);
            CP_COMMIT();
        }

        // epilogue: +db, mish, sq partials (+ E_hi store only if GEMM2 follows)
        float dbv[8];
        #pragma unroll
        for (int na = 0; na < 4; na++){
            int colp = wcol*32 + na*8 + qt*2;
            dbv[2*na]   = __ldg(&db[c*64 + colp]);
            dbv[2*na+1] = __ldg(&db[c*64 + colp + 1]);
        }
        float rs[2][2] = {{0.f,0.f},{0.f,0.f}};
        #pragma unroll
        for (int ma = 0; ma < 2; ma++){
            int row0 = wrow*32 + ma*16 + q;
            #pragma unroll
            for (int na = 0; na < 4; na++){
                int colp = wcol*32 + na*8 + qt*2;
                float m0 = mish2(d1[ma][na][0] + dbv[2*na]);
                float m1 = mish2(d1[ma][na][1] + dbv[2*na+1]);
                float m2 = mish2(d1[ma][na][2] + dbv[2*na]);
                float m3 = mish2(d1[ma][na][3] + dbv[2*na+1]);
                rs[ma][0] = fmaf(m0,m0, fmaf(m1,m1, rs[ma][0]));
                rs[ma][1] = fmaf(m2,m2, fmaf(m3,m3, rs[ma][1]));
                if (writeBias){
                    __half2 h01 = __floats2half2_rn(m0, m1);
                    __half2 h23 = __floats2half2_rn(m2, m3);
                    *(__half2*)((char*)smh + SE_H + (row0*PADK + colp)*2)     = h01;
                    *(__half2*)((char*)smh + SE_H + ((row0+8)*PADK + colp)*2) = h23;
                }
            }
        }
        #pragma unroll
        for (int ma = 0; ma < 2; ma++)
            #pragma unroll
            for (int hh = 0; hh < 2; hh++){
                float s = rs[ma][hh];
                s += __shfl_xor_sync(0xffffffffu, s, 1);
                s += __shfl_xor_sync(0xffffffffu, s, 2);
                if (qt == 0) atomicAdd(&sq[wrow*32 + ma*16 + q + hh*8], s);
            }

        if (writeBias){
            CP_WAIT1();
            __syncthreads();           // E_hi + sq visible, w2 ready
            mma_gemm_ld1(sbase + SE_H, sbase + SW2, acc2, lane, wrow, wcol);
            __syncthreads();
            if (c < 7)
                for (int i = t; i < 576; i += 256)
                    cp16(sbase + SW2 + i*16, wsrc + (long)(c+1)*WCHUNK + WPLANE + i*16);
            CP_COMMIT();
            if (c & 1){
                if (t < 128){
                    dif[(long)(c>>1)*NPAIR + pair0 + t] = sqrtf(sq[t]);
                    sq[t] = 0.f;
                }
            }
        } else {
            if (c & 1){
                __syncthreads();       // order atomicAdds before read/reset
                if (t < 128){
                    dif[(long)(c>>1)*NPAIR + pair0 + t] = sqrtf(sq[t]);
                    sq[t] = 0.f;
                }
            }
        }
    }

    // final: bias' = fp16(mish(acc2 + bb)) -> padded fp16 image (next layer's A plane)
    if (writeBias){
        #pragma unroll
        for (int ma = 0; ma < 2; ma++){
            #pragma unroll
            for (int na = 0; na < 4; na++){
                int colp = wcol*32 + na*8 + qt*2;
                float bb0 = __ldg(&bb[colp]);
                float bb1 = __ldg(&bb[colp + 1]);
                int row0 = wrow*32 + ma*16 + q;
                __half2 v0 = __floats2half2_rn(mish2(acc2[ma][na][0] + bb0),
                                               mish2(acc2[ma][na][1] + bb1));
                __half2 v1 = __floats2half2_rn(mish2(acc2[ma][na][2] + bb0),
                                               mish2(acc2[ma][na][3] + bb1));
                *(__half2*)&bnewH[(long)row0*PADK + colp]     = v0;
                *(__half2*)&bnewH[(long)(row0+8)*PADK + colp] = v1;
            }
        }
    }
}

// ---------------- K5: attention ----------------
__global__ void __launch_bounds__(512,1) k_attn(float scale, int dbuf){
    int h  = blockIdx.y;
    int n0 = blockIdx.x * 16;
    __shared__ float qS[16*HD];
    __shared__ float lg[16*NN_N];
    int t = threadIdx.x;
    const float* dif = g_diffs + (long)dbuf*HH*NPAIR;

    for (int idx = t; idx < 16*HD; idx += 512){
        int nn = idx >> 7, d = idx & 127;
        qS[idx] = g_qkv[(long)(n0+nn)*(3*HHD) + h*384 + d];
    }
    __syncthreads();
    {
        int m = t;
        float acc[16];
        #pragma unroll
        for (int nn = 0; nn < 16; nn++) acc[nn] = 0.f;
        const float* kp = g_qkv + (long)m*(3*HHD) + h*384 + 128;
        #pragma unroll 4
        for (int d = 0; d < HD; d += 4){
            float4 kv = *(const float4*)(kp + d);
            #pragma unroll
            for (int nn = 0; nn < 16; nn++){
                float4 qv = *(const float4*)&qS[nn*HD + d];
                acc[nn] += qv.x*kv.x + qv.y*kv.y + qv.z*kv.z + qv.w*kv.w;
            }
        }
        const float* dp = dif + (long)h*NPAIR + (long)n0*NN_N + m;
        #pragma unroll
        for (int nn = 0; nn < 16; nn++)
            lg[nn*NN_N + m] = acc[nn]*scale + dp[(long)nn*NN_N];
    }
    __syncthreads();
    {
        int row = t >> 5, lane = t & 31;
        float* Lr = lg + row*NN_N;
        float mx = -1e30f;
        for (int m = lane; m < NN_N; m += 32) mx = fmaxf(mx, Lr[m]);
        #pragma unroll
        for (int o = 16; o; o >>= 1) mx = fmaxf(mx, __shfl_xor_sync(0xffffffffu, mx, o));
        float sum = 0.f;
        for (int m = lane; m < NN_N; m += 32){
            float e = __expf(Lr[m] - mx); Lr[m] = e; sum += e;
        }
        #pragma unroll
        for (int o = 16; o; o >>= 1) sum += __shfl_xor_sync(0xffffffffu, sum, o);
        float inv = 1.f / sum;
        for (int m = lane; m < NN_N; m += 32) Lr[m] *= inv;
    }
    __syncthreads();
    {
        int d = t & 127, ng = t >> 7;
        float acc[4] = {0.f, 0.f, 0.f, 0.f};
        const float* vp = g_qkv + h*384 + 256 + d;
        #pragma unroll 4
        for (int m = 0; m < NN_N; m++){
            float vv = vp[(long)m*(3*HHD)];
            #pragma unroll
            for (int k = 0; k < 4; k++) acc[k] += lg[(ng*4+k)*NN_N + m] * vv;
        }
        #pragma unroll
        for (int k = 0; k < 4; k++)
            g_vals[(long)(n0 + ng*4 + k)*HHD + h*HD + d] = acc[k];
    }
}

// ---------------- K5b: oln + fused next-layer qkv / final out ----------------
__global__ void __launch_bounds__(512,1)
k_oln(const float* __restrict__ oW, const float* __restrict__ ob,
      const float* __restrict__ g2, const float* __restrict__ b2,
      const float* __restrict__ qW, const float* __restrict__ qb, int doQkv,
      const float* __restrict__ outW, const float* __restrict__ outb,
      float* __restrict__ out, int doOut){
    int n0 = blockIdx.x * 8;
    __shared__ float vs[8*HHD];
    __shared__ float s[8*DD];
    int t = threadIdx.x;
    for (int i = t; i < 8*HHD/4; i += 512)
        ((float4*)vs)[i] = ((const float4*)(g_vals + (long)n0*HHD))[i];
    __syncthreads();
    int r = t >> 6, i = t & 63;
    float acc = 0.f;
    #pragma unroll 8
    for (int j = 0; j < HHD; j++)
        acc += vs[r*HHD + j] * oW[j*DD + i];
    float xv = g_x[(n0+r)*DD + i] + acc + ob[i];
    s[r*DD + i] = xv;
    __syncthreads();
    float mu = 0.f;
    #pragma unroll
    for (int k = 0; k < DD; k++) mu += s[r*DD + k];
    mu *= (1.f/DD);
    float var = 0.f;
    #pragma unroll
    for (int k = 0; k < DD; k++){ float dd = s[r*DD + k]-mu; var += dd*dd; }
    var *= (1.f/DD);
    float xn = (xv - mu) * rsqrtf(var + EPSV) * g2[i] + b2[i];
    g_x[(n0+r)*DD + i] = xn;
    __syncthreads();
    s[r*DD + i] = xn;
    __syncthreads();
    if (doQkv){
        for (int j = t; j < 3*HHD; j += 512){
            float a2[8];
            float bv = qb[j];
            #pragma unroll
            for (int rr = 0; rr < 8; rr++) a2[rr] = bv;
            #pragma unroll 8
            for (int d = 0; d < DD; d++){
                float w = qW[d*(3*HHD) + j];
                #pragma unroll
                for (int rr = 0; rr < 8; rr++) a2[rr] += s[rr*DD + d] * w;
            }
            #pragma unroll
            for (int rr = 0; rr < 8; rr++) g_qkv[(long)(n0+rr)*(3*HHD) + j] = a2[rr];
        }
    }
    if (doOut && t < 8){
        float a = outb[0];
        #pragma unroll
        for (int d = 0; d < DD; d++) a += s[t*DD + d] * outW[d];
        out[n0 + t] = a;
    }
}

// ---------------- launcher (dual-stream pipeline) ----------------
extern "C" void kernel_launch(void* const* d_in, const int* in_sizes, int n_in,
                              void* d_out, int out_size){
    const float* nf    = (const float*)d_in[0];
    const float* amds  = (const float*)d_in[1];
    const float* embW  = (const float*)d_in[2];
    const float* embb  = (const float*)d_in[3];
    const float* bembW = (const float*)d_in[4];
    const float* bembb = (const float*)d_in[5];
    const float* ln1g  = (const float*)d_in[6];
    const float* ln1b  = (const float*)d_in[7];
    const float* ln2g  = (const float*)d_in[8];
    const float* ln2b  = (const float*)d_in[9];
    const float* qkvW  = (const float*)d_in[10];
    const float* qkvb  = (const float*)d_in[11];
    const float* diffW = (const float*)d_in[12];
    const float* diffb = (const float*)d_in[13];
    const float* oW    = (const float*)d_in[14];
    const float* ob    = (const float*)d_in[15];
    const float* boutW = (const float*)d_in[16];
    const float* boutb = (const float*)d_in[17];
    const float* outW  = (const float*)d_in[18];
    const float* outb  = (const float*)d_in[19];

    static int inited = 0;
    static cudaStream_t s1;
    static cudaEvent_t evBE[LAYERS], evAT[LAYERS], evJoin;
    if (!inited){
        cudaStreamCreateWithFlags(&s1, cudaStreamNonBlocking);
        for (int i = 0; i < LAYERS; i++){
            cudaEventCreateWithFlags(&evBE[i], cudaEventDisableTiming);
            cudaEventCreateWithFlags(&evAT[i], cudaEventDisableTiming);
        }
        cudaEventCreateWithFlags(&evJoin, cudaEventDisableTiming);
        cudaFuncSetAttribute(k_be, cudaFuncAttributeMaxDynamicSharedMemorySize, BE_SMEM);
        inited = 1;
    }

    k_wsplit<<<512, 256>>>(diffW, boutW);
    k_embed<<<NN_N, DD>>>(nf, amds, embW, embb, bembW, bembb, ln1g, ln1b);
    k_pq<<<NN_N/8, 512>>>(diffW);
    k_qkv<<<NN_N/8, 512>>>(qkvW, qkvb);

    float scale = 1.f / sqrtf((float)HD);
    for (int l = 0; l < LAYERS; l++){
        if (l >= 2) cudaStreamWaitEvent(0, evAT[l-2], 0);   // diffs buffer reuse guard
        k_be<<<NBLK, 256, BE_SMEM>>>(l, diffb + (long)l*HHD, boutb + (long)l*DD,
                                     l & 1, (l < LAYERS-1) ? 1 : 0,
                                     (l == 0) ? 1 : 0, l & 1);
        cudaEventRecord(evBE[l], 0);
        cudaStreamWaitEvent(s1, evBE[l], 0);
        k_attn<<<dim3(NN_N/16, HH), 512, 0, s1>>>(scale, l & 1);
        cudaEventRecord(evAT[l], s1);
        int last = (l == LAYERS-1);
        k_oln<<<NN_N/8, 512, 0, s1>>>(oW + (long)l*HHD*DD, ob + l*DD, ln2g, ln2b,
                                      qkvW + (long)(l+1)*DD*3*HHD,
                                      qkvb + (long)(l+1)*3*HHD, last ? 0 : 1,
                                      outW, outb, (float*)d_out, last);
    }
    cudaEventRecord(evJoin, s1);
    cudaStreamWaitEvent(0, evJoin, 0);
}